// round 1
// baseline (speedup 1.0000x reference)
#include <cuda_runtime.h>
#include <math.h>
#include <stdint.h>

// ---------------- problem constants ----------------
#define Bsz   4
#define Sseq  4096
#define Dmod  512
#define Hh    8
#define DHd   64
#define Mff   2048
#define BSb   64
#define NBb   64
#define NROWS (NBb - 2)
#define NTOK  (Bsz * Sseq)        // 16384

// ---------------- scratch (device globals; no allocation) ----------------
__device__ float g_xn[(size_t)NTOK * Dmod];
__device__ float g_q [(size_t)NTOK * Dmod];
__device__ float g_k [(size_t)NTOK * Dmod];
__device__ float g_v [(size_t)NTOK * Dmod];
__device__ float g_o [(size_t)NTOK * Dmod];
__device__ float g_yn[(size_t)NTOK * Dmod];
__device__ float g_hb[(size_t)NTOK * Mff];
__device__ int   g_idx[NROWS * 8];
__device__ int   g_cnt[NROWS];

// ---------------- numpy-legacy MT19937 replication ----------------
struct MT19937 {
    unsigned int k[624];
    int pos;
};

__device__ void mt_seed(MT19937& st, unsigned int seed) {
    for (int p = 0; p < 624; p++) {
        st.k[p] = seed;
        seed = 1812433253u * (seed ^ (seed >> 30)) + (unsigned)p + 1u;
    }
    st.pos = 624;
}

__device__ unsigned int mt_next(MT19937& st) {
    if (st.pos == 624) {
        // canonical in-place twist (matches numpy mt19937_gen exactly)
        for (int i = 0; i < 624; i++) {
            unsigned int y = (st.k[i] & 0x80000000u) | (st.k[(i + 1) % 624] & 0x7fffffffu);
            st.k[i] = st.k[(i + 397) % 624] ^ (y >> 1) ^ ((y & 1u) ? 0x9908b0dfu : 0u);
        }
        st.pos = 0;
    }
    unsigned int y = st.k[st.pos++];
    y ^= y >> 11;
    y ^= (y << 7)  & 0x9d2c5680u;
    y ^= (y << 15) & 0xefc60000u;
    y ^= y >> 18;
    return y;
}

// numpy random_interval: value in [0, mx], masked rejection on 32-bit outputs
__device__ unsigned int mt_interval(MT19937& st, unsigned int mx) {
    if (mx == 0u) return 0u;
    unsigned int mask = mx;
    mask |= mask >> 1; mask |= mask >> 2; mask |= mask >> 4;
    mask |= mask >> 8; mask |= mask >> 16;
    unsigned int v;
    do { v = mt_next(st) & mask; } while (v > mx);
    return v;
}

// Replicates _block_indices(): per interior row, fixed = sorted unique
// {0,NB-1,i-1,i,i+1}; rand = RandomState(0).choice(allowed, 3, replace=False)
// == allowed[permutation(len(allowed))[:3]] (Fisher-Yates descending).
__global__ void init_idx_kernel() {
    if (threadIdx.x != 0 || blockIdx.x != 0) return;
    MT19937 st;
    mt_seed(st, 0u);
    for (int i = 1; i <= NBb - 2; i++) {
        bool fx[NBb];
        for (int z = 0; z < NBb; z++) fx[z] = false;
        fx[0] = true; fx[NBb - 1] = true;
        fx[i - 1] = true; fx[i] = true; fx[i + 1] = true;
        int fixed[8], nf = 0;
        int allowed[NBb], na = 0;
        for (int bb = 0; bb < NBb; bb++) {
            if (fx[bb]) fixed[nf++] = bb;
            else        allowed[na++] = bb;
        }
        int perm[NBb];
        for (int t = 0; t < na; t++) perm[t] = t;
        for (int t = na - 1; t >= 1; t--) {
            int j = (int)mt_interval(st, (unsigned)t);
            int tmp = perm[t]; perm[t] = perm[j]; perm[j] = tmp;
        }
        int row = i - 1;
        int cnt = 0;
        for (int s = 0; s < nf; s++) g_idx[row * 8 + cnt++] = fixed[s];
        for (int r3 = 0; r3 < 3; r3++) g_idx[row * 8 + cnt++] = allowed[perm[r3]];
        g_cnt[row] = cnt;
        for (; cnt < 8; cnt++) g_idx[row * 8 + cnt] = 0;  // masked pad
    }
}

// ---------------- LayerNorm (one CTA of 128 threads per row of 512) ----------------
__global__ void ln_kernel(const float* __restrict__ x, const float* __restrict__ g,
                          const float* __restrict__ bta, float* __restrict__ y) {
    __shared__ float red[2][4];
    const int row = blockIdx.x;
    const int t = threadIdx.x;
    const float* xr = x + (size_t)row * Dmod;
    float4 xv = ((const float4*)xr)[t];
    float s  = xv.x + xv.y + xv.z + xv.w;
    float q2 = xv.x * xv.x + xv.y * xv.y + xv.z * xv.z + xv.w * xv.w;
    #pragma unroll
    for (int o = 16; o; o >>= 1) {
        s  += __shfl_xor_sync(0xffffffffu, s,  o);
        q2 += __shfl_xor_sync(0xffffffffu, q2, o);
    }
    if ((t & 31) == 0) { red[0][t >> 5] = s; red[1][t >> 5] = q2; }
    __syncthreads();
    s  = red[0][0] + red[0][1] + red[0][2] + red[0][3];
    q2 = red[1][0] + red[1][1] + red[1][2] + red[1][3];
    const float mu   = s * (1.0f / Dmod);
    const float var  = q2 * (1.0f / Dmod) - mu * mu;
    const float rstd = rsqrtf(var + 1e-6f);
    float4 gv = ((const float4*)g)[t];
    float4 bv = ((const float4*)bta)[t];
    float4 ov;
    ov.x = (xv.x - mu) * rstd * gv.x + bv.x;
    ov.y = (xv.y - mu) * rstd * gv.y + bv.y;
    ov.z = (xv.z - mu) * rstd * gv.z + bv.z;
    ov.w = (xv.w - mu) * rstd * gv.w + bv.w;
    ((float4*)(y + (size_t)row * Dmod))[t] = ov;
}

// ---------------- SGEMM 128x128x8, 256 thr, 8x8 per thread, dbl-buffer ----------------
__device__ __forceinline__ float gelu_tanh(float x) {
    // jax.nn.gelu default (approximate=True)
    const float c = 0.7978845608028654f;
    float x3 = x * x * x;
    return 0.5f * x * (1.0f + tanhf(c * (x + 0.044715f * x3)));
}

// EPI: 0 = alpha*acc ; 1 = gelu(acc+bias) ; 2 = acc+res ; 3 = acc+bias+res
template <int EPI>
__global__ void __launch_bounds__(256, 2)
sgemm_kernel(const float* __restrict__ A, const float* __restrict__ Bw,
             float* __restrict__ C, int M, int N, int Kd, float alpha,
             const float* __restrict__ bias, const float* __restrict__ res) {
    __shared__ float As[2][8][132];   // padded: conflict-free transposed stores
    __shared__ float Bs[2][8][128];

    const int tid = threadIdx.x;
    const int bm = blockIdx.y * 128;
    const int bn = blockIdx.x * 128;
    const int a_r = tid >> 1, a_c = (tid & 1) * 4;   // A: 128 rows x 8 cols
    const int b_r = tid >> 5, b_c = (tid & 31) * 4;  // B: 8 rows x 128 cols
    const int tx = tid & 15, ty = tid >> 4;

    const float* Aptr = A + (size_t)(bm + a_r) * Kd + a_c;
    const float* Bptr = Bw + (size_t)b_r * N + bn + b_c;

    float acc[8][8];
    #pragma unroll
    for (int i = 0; i < 8; i++)
        #pragma unroll
        for (int j = 0; j < 8; j++) acc[i][j] = 0.0f;

    float4 av = *(const float4*)Aptr;
    float4 bv = *(const float4*)Bptr;
    As[0][a_c + 0][a_r] = av.x;
    As[0][a_c + 1][a_r] = av.y;
    As[0][a_c + 2][a_r] = av.z;
    As[0][a_c + 3][a_r] = av.w;
    *(float4*)&Bs[0][b_r][b_c] = bv;
    __syncthreads();

    const int nk = Kd >> 3;
    for (int t = 0; t < nk; t++) {
        const int cur = t & 1;
        if (t + 1 < nk) {
            av = *(const float4*)(Aptr + (t + 1) * 8);
            bv = *(const float4*)(Bptr + (size_t)(t + 1) * 8 * N);
        }
        #pragma unroll
        for (int kk = 0; kk < 8; kk++) {
            float ar[8], br[8];
            *(float4*)&ar[0] = *(const float4*)&As[cur][kk][ty * 8];
            *(float4*)&ar[4] = *(const float4*)&As[cur][kk][ty * 8 + 4];
            *(float4*)&br[0] = *(const float4*)&Bs[cur][kk][tx * 8];
            *(float4*)&br[4] = *(const float4*)&Bs[cur][kk][tx * 8 + 4];
            #pragma unroll
            for (int i = 0; i < 8; i++)
                #pragma unroll
                for (int j = 0; j < 8; j++)
                    acc[i][j] = fmaf(ar[i], br[j], acc[i][j]);
        }
        if (t + 1 < nk) {
            const int nxt = cur ^ 1;
            As[nxt][a_c + 0][a_r] = av.x;
            As[nxt][a_c + 1][a_r] = av.y;
            As[nxt][a_c + 2][a_r] = av.z;
            As[nxt][a_c + 3][a_r] = av.w;
            *(float4*)&Bs[nxt][b_r][b_c] = bv;
            __syncthreads();
        }
    }

    #pragma unroll
    for (int i = 0; i < 8; i++) {
        const size_t roff = (size_t)(bm + ty * 8 + i) * N + bn + tx * 8;
        float out[8];
        #pragma unroll
        for (int j = 0; j < 8; j++) {
            float vaa = acc[i][j];
            if (EPI == 0) vaa *= alpha;
            if (EPI == 1) vaa = gelu_tanh(vaa + bias[bn + tx * 8 + j]);
            if (EPI == 2) vaa = vaa + res[roff + j];
            if (EPI == 3) vaa = vaa + bias[bn + tx * 8 + j] + res[roff + j];
            out[j] = vaa;
        }
        *(float4*)&C[roff]     = *(float4*)&out[0];
        *(float4*)&C[roff + 4] = *(float4*)&out[4];
    }
}

// ---------------- fused BigBird attention ----------------
// One CTA per (b, h, query-block n). n==0 / n==NB-1 -> global (all 64 key
// blocks); otherwise the g_idx row (masked slots simply skipped: identical
// to softmax with -1e9 in fp32). Flash-style streaming softmax.
#define ATT_LD    68
#define ATT_SMEM  (4 * 64 * ATT_LD * 4)

__global__ void __launch_bounds__(256)
attn_kernel(const float* __restrict__ q, const float* __restrict__ k,
            const float* __restrict__ v, float* __restrict__ o,
            const int* __restrict__ idxTab, const int* __restrict__ cntTab) {
    extern __shared__ float sm[];
    float* qs = sm;                    // [64][ATT_LD] q[row][d]
    float* kt = sm + 64 * ATT_LD;      // [64][ATT_LD] k transposed: kt[d][j]
    float* vs = sm + 2 * 64 * ATT_LD;  // [64][ATT_LD] v[j][d]
    float* ps = sm + 3 * 64 * ATT_LD;  // [64][ATT_LD] p[row][j]

    const int n = blockIdx.x, h = blockIdx.y, b = blockIdx.z;
    const int tid = threadIdx.x;
    const int r = tid >> 2;            // query row 0..63
    const int c0 = (tid & 3) * 16;     // 16-wide column slice
    const bool isg = (n == 0) || (n == NBb - 1);
    const int nkb = isg ? NBb : cntTab[n - 1];

    const float* qbase = q + ((size_t)b * Sseq + n * BSb) * Dmod + h * DHd;
    for (int t = tid; t < 64 * 16; t += 256) {
        int rr = t >> 4, cc = (t & 15) << 2;
        *(float4*)&qs[rr * ATT_LD + cc] = *(const float4*)&qbase[(size_t)rr * Dmod + cc];
    }

    float acc[16];
    #pragma unroll
    for (int i = 0; i < 16; i++) acc[i] = 0.0f;
    float mval = -1e30f, lval = 0.0f;

    for (int it = 0; it < nkb; it++) {
        const int kb = isg ? it : idxTab[(n - 1) * 8 + it];
        const float* kbase = k + ((size_t)b * Sseq + kb * BSb) * Dmod + h * DHd;
        const float* vbase = v + ((size_t)b * Sseq + kb * BSb) * Dmod + h * DHd;

        __syncthreads();  // prior PV / q-stage done before tile overwrite
        for (int t = tid; t < 64 * 16; t += 256) {
            int j = t >> 4, cc = (t & 15) << 2;
            float4 kv = *(const float4*)&kbase[(size_t)j * Dmod + cc];
            kt[(cc + 0) * ATT_LD + j] = kv.x;
            kt[(cc + 1) * ATT_LD + j] = kv.y;
            kt[(cc + 2) * ATT_LD + j] = kv.z;
            kt[(cc + 3) * ATT_LD + j] = kv.w;
            *(float4*)&vs[j * ATT_LD + cc] = *(const float4*)&vbase[(size_t)j * Dmod + cc];
        }
        __syncthreads();

        // scores: s[jj] = sum_d q[r][d] * k[c0+jj][d]
        float s[16];
        #pragma unroll
        for (int i = 0; i < 16; i++) s[i] = 0.0f;
        #pragma unroll 4
        for (int d = 0; d < 64; d++) {
            const float qv = qs[r * ATT_LD + d];
            const float4* kr = (const float4*)&kt[d * ATT_LD + c0];
            #pragma unroll
            for (int w = 0; w < 4; w++) {
                float4 k4 = kr[w];
                s[4 * w + 0] = fmaf(qv, k4.x, s[4 * w + 0]);
                s[4 * w + 1] = fmaf(qv, k4.y, s[4 * w + 1]);
                s[4 * w + 2] = fmaf(qv, k4.z, s[4 * w + 2]);
                s[4 * w + 3] = fmaf(qv, k4.w, s[4 * w + 3]);
            }
        }

        // streaming softmax update (4 threads per row share m/l via shfl)
        float smax = s[0];
        #pragma unroll
        for (int i = 1; i < 16; i++) smax = fmaxf(smax, s[i]);
        smax = fmaxf(smax, __shfl_xor_sync(0xffffffffu, smax, 1));
        smax = fmaxf(smax, __shfl_xor_sync(0xffffffffu, smax, 2));
        const float mnew = fmaxf(mval, smax);
        const float corr = __expf(mval - mnew);
        float psum = 0.0f;
        float pv16[16];
        #pragma unroll
        for (int i = 0; i < 16; i++) {
            float p = __expf(s[i] - mnew);
            pv16[i] = p;
            psum += p;
        }
        psum += __shfl_xor_sync(0xffffffffu, psum, 1);
        psum += __shfl_xor_sync(0xffffffffu, psum, 2);
        lval = lval * corr + psum;
        mval = mnew;
        #pragma unroll
        for (int i = 0; i < 16; i++) acc[i] *= corr;
        #pragma unroll
        for (int w = 0; w < 4; w++)
            *(float4*)&ps[r * ATT_LD + c0 + w * 4] =
                make_float4(pv16[4 * w], pv16[4 * w + 1], pv16[4 * w + 2], pv16[4 * w + 3]);
        __syncthreads();

        // PV: acc[dd] += sum_j p[r][j] * v[j][c0+dd]
        #pragma unroll 4
        for (int j = 0; j < 64; j++) {
            const float pj = ps[r * ATT_LD + j];
            const float4* vr = (const float4*)&vs[j * ATT_LD + c0];
            #pragma unroll
            for (int w = 0; w < 4; w++) {
                float4 v4 = vr[w];
                acc[4 * w + 0] = fmaf(pj, v4.x, acc[4 * w + 0]);
                acc[4 * w + 1] = fmaf(pj, v4.y, acc[4 * w + 1]);
                acc[4 * w + 2] = fmaf(pj, v4.z, acc[4 * w + 2]);
                acc[4 * w + 3] = fmaf(pj, v4.w, acc[4 * w + 3]);
            }
        }
    }

    const float inv = 1.0f / lval;
    float* ob = o + ((size_t)b * Sseq + n * BSb + r) * Dmod + h * DHd + c0;
    #pragma unroll
    for (int w = 0; w < 4; w++) {
        float4 ov = make_float4(acc[4 * w] * inv, acc[4 * w + 1] * inv,
                                acc[4 * w + 2] * inv, acc[4 * w + 3] * inv);
        *(float4*)&ob[w * 4] = ov;
    }
}

// ---------------- launcher ----------------
extern "C" void kernel_launch(void* const* d_in, const int* in_sizes, int n_in,
                              void* d_out, int out_size) {
    const float* inputs = (const float*)d_in[0];
    const float* ln1_s  = (const float*)d_in[1];
    const float* ln1_b  = (const float*)d_in[2];
    const float* wq     = (const float*)d_in[3];
    const float* wk     = (const float*)d_in[4];
    const float* wv     = (const float*)d_in[5];
    const float* wo     = (const float*)d_in[6];
    const float* ln2_s  = (const float*)d_in[7];
    const float* ln2_b  = (const float*)d_in[8];
    const float* w1     = (const float*)d_in[9];
    const float* b1     = (const float*)d_in[10];
    const float* w2     = (const float*)d_in[11];
    const float* b2     = (const float*)d_in[12];
    float* out = (float*)d_out;

    float *xn, *q, *k, *v, *o, *yn, *hb;
    int *idx, *cnt;
    cudaGetSymbolAddress((void**)&xn, g_xn);
    cudaGetSymbolAddress((void**)&q,  g_q);
    cudaGetSymbolAddress((void**)&k,  g_k);
    cudaGetSymbolAddress((void**)&v,  g_v);
    cudaGetSymbolAddress((void**)&o,  g_o);
    cudaGetSymbolAddress((void**)&yn, g_yn);
    cudaGetSymbolAddress((void**)&hb, g_hb);
    cudaGetSymbolAddress((void**)&idx, g_idx);
    cudaGetSymbolAddress((void**)&cnt, g_cnt);

    cudaFuncSetAttribute(attn_kernel, cudaFuncAttributeMaxDynamicSharedMemorySize, ATT_SMEM);

    // 1. BigBird block index table (numpy RandomState(0) replication)
    init_idx_kernel<<<1, 1>>>();

    // 2. LN1
    ln_kernel<<<NTOK, 128>>>(inputs, ln1_s, ln1_b, xn);

    // 3. QKV projections (q pre-scaled by 1/sqrt(DH) = 0.125)
    dim3 g512(Dmod / 128, NTOK / 128);
    sgemm_kernel<0><<<g512, 256>>>(xn, wq, q, NTOK, Dmod, Dmod, 0.125f, nullptr, nullptr);
    sgemm_kernel<0><<<g512, 256>>>(xn, wk, k, NTOK, Dmod, Dmod, 1.0f,   nullptr, nullptr);
    sgemm_kernel<0><<<g512, 256>>>(xn, wv, v, NTOK, Dmod, Dmod, 1.0f,   nullptr, nullptr);

    // 4. attention (interior sparse + global rows fused)
    attn_kernel<<<dim3(NBb, Hh, Bsz), 256, ATT_SMEM>>>(q, k, v, o, idx, cnt);

    // 5. output projection + residual:  x = o @ wo + inputs  -> d_out
    sgemm_kernel<2><<<g512, 256>>>(o, wo, out, NTOK, Dmod, Dmod, 1.0f, nullptr, inputs);

    // 6. LN2
    ln_kernel<<<NTOK, 128>>>(out, ln2_s, ln2_b, yn);

    // 7. FFN1: gelu(yn @ w1 + b1)
    dim3 g2048(Mff / 128, NTOK / 128);
    sgemm_kernel<1><<<g2048, 256>>>(yn, w1, hb, NTOK, Mff, Dmod, 1.0f, b1, nullptr);

    // 8. FFN2 + bias + residual: out = hb @ w2 + b2 + x
    sgemm_kernel<3><<<g512, 256>>>(hb, w2, out, NTOK, Dmod, Mff, 1.0f, b2, out);
}

// round 2
// speedup vs baseline: 1.5847x; 1.5847x over previous
#include <cuda_runtime.h>
#include <math.h>
#include <stdint.h>

// ---------------- problem constants ----------------
#define Bsz   4
#define Sseq  4096
#define Dmod  512
#define Hh    8
#define DHd   64
#define Mff   2048
#define BSb   64
#define NBb   64
#define NROWS (NBb - 2)
#define NTOK  (Bsz * Sseq)        // 16384

// ---------------- scratch (device globals; no allocation) ----------------
__device__ float g_xn[(size_t)NTOK * Dmod];
__device__ float g_q [(size_t)NTOK * Dmod];
__device__ float g_k [(size_t)NTOK * Dmod];
__device__ float g_v [(size_t)NTOK * Dmod];
__device__ float g_o [(size_t)NTOK * Dmod];
__device__ float g_yn[(size_t)NTOK * Dmod];
__device__ float g_hb[(size_t)NTOK * Mff];
__device__ int   g_idx[NROWS * 8];
__device__ int   g_cnt[NROWS];

// ---------------- host-side numpy-legacy MT19937 (table is input-independent) ----------------
struct HostMT {
    unsigned int k[624];
    int pos;
};
static void h_mt_seed(HostMT& st, unsigned int seed) {
    for (int p = 0; p < 624; p++) {
        st.k[p] = seed;
        seed = 1812433253u * (seed ^ (seed >> 30)) + (unsigned)p + 1u;
    }
    st.pos = 624;
}
static unsigned int h_mt_next(HostMT& st) {
    if (st.pos == 624) {
        for (int i = 0; i < 624; i++) {
            unsigned int y = (st.k[i] & 0x80000000u) | (st.k[(i + 1) % 624] & 0x7fffffffu);
            st.k[i] = st.k[(i + 397) % 624] ^ (y >> 1) ^ ((y & 1u) ? 0x9908b0dfu : 0u);
        }
        st.pos = 0;
    }
    unsigned int y = st.k[st.pos++];
    y ^= y >> 11;
    y ^= (y << 7)  & 0x9d2c5680u;
    y ^= (y << 15) & 0xefc60000u;
    y ^= y >> 18;
    return y;
}
static unsigned int h_mt_interval(HostMT& st, unsigned int mx) {
    if (mx == 0u) return 0u;
    unsigned int mask = mx;
    mask |= mask >> 1; mask |= mask >> 2; mask |= mask >> 4;
    mask |= mask >> 8; mask |= mask >> 16;
    unsigned int v;
    do { v = h_mt_next(st) & mask; } while (v > mx);
    return v;
}
// Fills h_idx/h_cnt exactly like reference _block_indices() (validated in R1).
static void h_make_table(int* h_idx, int* h_cnt) {
    HostMT st;
    h_mt_seed(st, 0u);
    for (int i = 1; i <= NBb - 2; i++) {
        bool fx[NBb];
        for (int z = 0; z < NBb; z++) fx[z] = false;
        fx[0] = true; fx[NBb - 1] = true;
        fx[i - 1] = true; fx[i] = true; fx[i + 1] = true;
        int fixed[8], nf = 0;
        int allowed[NBb], na = 0;
        for (int bb = 0; bb < NBb; bb++) {
            if (fx[bb]) fixed[nf++] = bb;
            else        allowed[na++] = bb;
        }
        int perm[NBb];
        for (int t = 0; t < na; t++) perm[t] = t;
        for (int t = na - 1; t >= 1; t--) {
            int j = (int)h_mt_interval(st, (unsigned)t);
            int tmp = perm[t]; perm[t] = perm[j]; perm[j] = tmp;
        }
        int row = i - 1;
        int cnt = 0;
        for (int s = 0; s < nf; s++) h_idx[row * 8 + cnt++] = fixed[s];
        for (int r3 = 0; r3 < 3; r3++) h_idx[row * 8 + cnt++] = allowed[perm[r3]];
        h_cnt[row] = cnt;
        for (; cnt < 8; cnt++) h_idx[row * 8 + cnt] = 0;
    }
}

// ---------------- LayerNorm (one CTA of 128 threads per row of 512) ----------------
__global__ void ln_kernel(const float* __restrict__ x, const float* __restrict__ g,
                          const float* __restrict__ bta, float* __restrict__ y) {
    __shared__ float red[2][4];
    const int row = blockIdx.x;
    const int t = threadIdx.x;
    const float* xr = x + (size_t)row * Dmod;
    float4 xv = ((const float4*)xr)[t];
    float s  = xv.x + xv.y + xv.z + xv.w;
    float q2 = xv.x * xv.x + xv.y * xv.y + xv.z * xv.z + xv.w * xv.w;
    #pragma unroll
    for (int o = 16; o; o >>= 1) {
        s  += __shfl_xor_sync(0xffffffffu, s,  o);
        q2 += __shfl_xor_sync(0xffffffffu, q2, o);
    }
    if ((t & 31) == 0) { red[0][t >> 5] = s; red[1][t >> 5] = q2; }
    __syncthreads();
    s  = red[0][0] + red[0][1] + red[0][2] + red[0][3];
    q2 = red[1][0] + red[1][1] + red[1][2] + red[1][3];
    const float mu   = s * (1.0f / Dmod);
    const float var  = q2 * (1.0f / Dmod) - mu * mu;
    const float rstd = rsqrtf(var + 1e-6f);
    float4 gv = ((const float4*)g)[t];
    float4 bv = ((const float4*)bta)[t];
    float4 ov;
    ov.x = (xv.x - mu) * rstd * gv.x + bv.x;
    ov.y = (xv.y - mu) * rstd * gv.y + bv.y;
    ov.z = (xv.z - mu) * rstd * gv.z + bv.z;
    ov.w = (xv.w - mu) * rstd * gv.w + bv.w;
    ((float4*)(y + (size_t)row * Dmod))[t] = ov;
}

// ---------------- TF32 tensor-core SGEMM ----------------
// 128x128 block tile, K-step 32, 256 threads = 8 warps (2M x 4N),
// warp tile 64x32 via 16x m16n8k8 mma. cp.async double buffered.
__device__ __forceinline__ float gelu_tanh(float x) {
    const float c = 0.7978845608028654f;
    float x3 = x * x * x;
    return 0.5f * x * (1.0f + tanhf(c * (x + 0.044715f * x3)));
}

__device__ __forceinline__ uint32_t f2tf(float x) {
    uint32_t r;
    asm("cvt.rna.tf32.f32 %0, %1;" : "=r"(r) : "f"(x));
    return r;
}

__device__ __forceinline__ void cpasync16(uint32_t saddr, const void* gaddr) {
    asm volatile("cp.async.cg.shared.global [%0], [%1], 16;" :: "r"(saddr), "l"(gaddr) : "memory");
}

#define A_LD   36
#define B_LD   136
#define A_TILE (128 * A_LD)          // floats per A buffer
#define B_TILE (32 * B_LD)           // floats per B buffer
#define GEMM_SMEM ((2 * A_TILE + 2 * B_TILE) * 4)

// EPI: 0 = alpha*acc ; 1 = gelu(acc+bias) ; 2 = acc+res ; 3 = acc+bias+res
template <int EPI>
__global__ void __launch_bounds__(256, 2)
sgemm_tc(const float* __restrict__ A, const float* __restrict__ Bw,
         float* __restrict__ C, int Mr, int N, int K, float alpha,
         const float* __restrict__ bias, const float* __restrict__ res) {
    extern __shared__ float sm[];
    float* Asm = sm;                      // [2][128][A_LD]  As[m][k]
    float* Bsm = sm + 2 * A_TILE;         // [2][32][B_LD]   Bs[k][n]

    const int tid  = threadIdx.x;
    const int bm   = blockIdx.y * 128;
    const int bn   = blockIdx.x * 128;
    const int lane = tid & 31;
    const int wid  = tid >> 5;
    const int wm   = wid & 1;             // 0..1
    const int wn   = wid >> 1;            // 0..3
    const int lr   = lane >> 2;           // 0..7
    const int lc   = lane & 3;            // 0..3

    uint32_t sbase = (uint32_t)__cvta_generic_to_shared(sm);
    uint32_t sA = sbase;
    uint32_t sB = sbase + 2 * A_TILE * 4;

    float acc[4][4][4];
    #pragma unroll
    for (int mt = 0; mt < 4; mt++)
        #pragma unroll
        for (int nt = 0; nt < 4; nt++)
            #pragma unroll
            for (int r = 0; r < 4; r++) acc[mt][nt][r] = 0.0f;

    const int nk = K >> 5;

    // precomputed per-thread load coordinates
    const int a_row = tid >> 1;                 // used as c>>3 pattern below
    (void)a_row;

    // ---- prologue: load tile 0 into buffer 0 ----
    {
        const float* Ag = A + (size_t)bm * K;
        #pragma unroll
        for (int i = 0; i < 4; i++) {
            int c = tid + 256 * i;
            int row = c >> 3, k4 = (c & 7) * 4;
            cpasync16(sA + (uint32_t)(row * A_LD + k4) * 4, Ag + (size_t)row * K + k4);
        }
        const float* Bg = Bw + (size_t)0 * N + bn;
        #pragma unroll
        for (int i = 0; i < 4; i++) {
            int c = tid + 256 * i;
            int kr = c >> 5, n4 = (c & 31) * 4;
            cpasync16(sB + (uint32_t)(kr * B_LD + n4) * 4, Bg + (size_t)kr * N + n4);
        }
        asm volatile("cp.async.commit_group;" ::: "memory");
    }

    for (int t = 0; t < nk; t++) {
        const int cur = t & 1;
        if (t + 1 < nk) {
            const int nb = (t + 1) & 1;
            const float* Ag = A + (size_t)bm * K + (t + 1) * 32;
            #pragma unroll
            for (int i = 0; i < 4; i++) {
                int c = tid + 256 * i;
                int row = c >> 3, k4 = (c & 7) * 4;
                cpasync16(sA + (uint32_t)(nb * A_TILE + row * A_LD + k4) * 4,
                          Ag + (size_t)row * K + k4);
            }
            const float* Bg = Bw + (size_t)((t + 1) * 32) * N + bn;
            #pragma unroll
            for (int i = 0; i < 4; i++) {
                int c = tid + 256 * i;
                int kr = c >> 5, n4 = (c & 31) * 4;
                cpasync16(sB + (uint32_t)(nb * B_TILE + kr * B_LD + n4) * 4,
                          Bg + (size_t)kr * N + n4);
            }
            asm volatile("cp.async.commit_group;" ::: "memory");
            asm volatile("cp.async.wait_group 1;" ::: "memory");
        } else {
            asm volatile("cp.async.wait_group 0;" ::: "memory");
        }
        __syncthreads();

        const float* Asb = Asm + cur * A_TILE;
        const float* Bsb = Bsm + cur * B_TILE;

        #pragma unroll
        for (int ks = 0; ks < 4; ks++) {
            const int k0 = ks * 8;
            uint32_t af[4][4], bf[4][2];
            #pragma unroll
            for (int mt = 0; mt < 4; mt++) {
                const float* p = Asb + (wm * 64 + mt * 16 + lr) * A_LD + k0 + lc;
                af[mt][0] = f2tf(p[0]);
                af[mt][1] = f2tf(p[8 * A_LD]);
                af[mt][2] = f2tf(p[4]);
                af[mt][3] = f2tf(p[8 * A_LD + 4]);
            }
            #pragma unroll
            for (int nt = 0; nt < 4; nt++) {
                const float* p = Bsb + (k0 + lc) * B_LD + wn * 32 + nt * 8 + lr;
                bf[nt][0] = f2tf(p[0]);
                bf[nt][1] = f2tf(p[4 * B_LD]);
            }
            #pragma unroll
            for (int mt = 0; mt < 4; mt++)
                #pragma unroll
                for (int nt = 0; nt < 4; nt++) {
                    asm volatile(
                        "mma.sync.aligned.m16n8k8.row.col.f32.tf32.tf32.f32 "
                        "{%0,%1,%2,%3}, {%4,%5,%6,%7}, {%8,%9}, {%0,%1,%2,%3};"
                        : "+f"(acc[mt][nt][0]), "+f"(acc[mt][nt][1]),
                          "+f"(acc[mt][nt][2]), "+f"(acc[mt][nt][3])
                        : "r"(af[mt][0]), "r"(af[mt][1]), "r"(af[mt][2]), "r"(af[mt][3]),
                          "r"(bf[nt][0]), "r"(bf[nt][1]));
                }
        }
        __syncthreads();
    }

    // ---- epilogue ----
    #pragma unroll
    for (int mt = 0; mt < 4; mt++) {
        const int row0 = bm + wm * 64 + mt * 16 + lr;
        #pragma unroll
        for (int half = 0; half < 2; half++) {
            const int row = row0 + half * 8;
            #pragma unroll
            for (int nt = 0; nt < 4; nt++) {
                const int col = bn + wn * 32 + nt * 8 + lc * 2;
                float v0 = acc[mt][nt][half * 2 + 0];
                float v1 = acc[mt][nt][half * 2 + 1];
                const size_t off = (size_t)row * N + col;
                if (EPI == 0) { v0 *= alpha; v1 *= alpha; }
                if (EPI == 1) {
                    v0 = gelu_tanh(v0 + bias[col]);
                    v1 = gelu_tanh(v1 + bias[col + 1]);
                }
                if (EPI == 2) {
                    v0 += res[off]; v1 += res[off + 1];
                }
                if (EPI == 3) {
                    v0 += bias[col] + res[off];
                    v1 += bias[col + 1] + res[off + 1];
                }
                *(float2*)&C[off] = make_float2(v0, v1);
            }
        }
    }
}

// ---------------- fused BigBird attention ----------------
#define ATT_LD    68
#define ATT_SMEM  (4 * 64 * ATT_LD * 4)

__global__ void __launch_bounds__(256)
attn_kernel(const float* __restrict__ q, const float* __restrict__ k,
            const float* __restrict__ v, float* __restrict__ o,
            const int* __restrict__ idxTab, const int* __restrict__ cntTab) {
    extern __shared__ float sm[];
    float* qs = sm;                    // [64][ATT_LD]
    float* kt = sm + 64 * ATT_LD;      // k transposed: kt[d][j]
    float* vs = sm + 2 * 64 * ATT_LD;  // v[j][d]
    float* ps = sm + 3 * 64 * ATT_LD;  // p[row][j]

    // global blocks (8x work) scheduled first to cut the tail
    const int bx = blockIdx.x;
    const int n = (bx < 2) ? (bx == 0 ? 0 : NBb - 1) : (bx - 1);
    const int h = blockIdx.y, b = blockIdx.z;
    const int tid = threadIdx.x;
    const int r = tid >> 2;
    const int c0 = (tid & 3) * 16;
    const bool isg = (n == 0) || (n == NBb - 1);
    const int nkb = isg ? NBb : cntTab[n - 1];

    const float* qbase = q + ((size_t)b * Sseq + n * BSb) * Dmod + h * DHd;
    for (int t = tid; t < 64 * 16; t += 256) {
        int rr = t >> 4, cc = (t & 15) << 2;
        *(float4*)&qs[rr * ATT_LD + cc] = *(const float4*)&qbase[(size_t)rr * Dmod + cc];
    }

    float acc[16];
    #pragma unroll
    for (int i = 0; i < 16; i++) acc[i] = 0.0f;
    float mval = -1e30f, lval = 0.0f;

    for (int it = 0; it < nkb; it++) {
        const int kb = isg ? it : idxTab[(n - 1) * 8 + it];
        const float* kbase = k + ((size_t)b * Sseq + kb * BSb) * Dmod + h * DHd;
        const float* vbase = v + ((size_t)b * Sseq + kb * BSb) * Dmod + h * DHd;

        __syncthreads();
        for (int t = tid; t < 64 * 16; t += 256) {
            int j = t >> 4, cc = (t & 15) << 2;
            float4 kv = *(const float4*)&kbase[(size_t)j * Dmod + cc];
            kt[(cc + 0) * ATT_LD + j] = kv.x;
            kt[(cc + 1) * ATT_LD + j] = kv.y;
            kt[(cc + 2) * ATT_LD + j] = kv.z;
            kt[(cc + 3) * ATT_LD + j] = kv.w;
            *(float4*)&vs[j * ATT_LD + cc] = *(const float4*)&vbase[(size_t)j * Dmod + cc];
        }
        __syncthreads();

        float s[16];
        #pragma unroll
        for (int i = 0; i < 16; i++) s[i] = 0.0f;
        #pragma unroll 4
        for (int d = 0; d < 64; d++) {
            const float qv = qs[r * ATT_LD + d];
            const float4* kr = (const float4*)&kt[d * ATT_LD + c0];
            #pragma unroll
            for (int w = 0; w < 4; w++) {
                float4 k4 = kr[w];
                s[4 * w + 0] = fmaf(qv, k4.x, s[4 * w + 0]);
                s[4 * w + 1] = fmaf(qv, k4.y, s[4 * w + 1]);
                s[4 * w + 2] = fmaf(qv, k4.z, s[4 * w + 2]);
                s[4 * w + 3] = fmaf(qv, k4.w, s[4 * w + 3]);
            }
        }

        float smax = s[0];
        #pragma unroll
        for (int i = 1; i < 16; i++) smax = fmaxf(smax, s[i]);
        smax = fmaxf(smax, __shfl_xor_sync(0xffffffffu, smax, 1));
        smax = fmaxf(smax, __shfl_xor_sync(0xffffffffu, smax, 2));
        const float mnew = fmaxf(mval, smax);
        const float corr = __expf(mval - mnew);
        float psum = 0.0f;
        float pv16[16];
        #pragma unroll
        for (int i = 0; i < 16; i++) {
            float p = __expf(s[i] - mnew);
            pv16[i] = p;
            psum += p;
        }
        psum += __shfl_xor_sync(0xffffffffu, psum, 1);
        psum += __shfl_xor_sync(0xffffffffu, psum, 2);
        lval = lval * corr + psum;
        mval = mnew;
        #pragma unroll
        for (int i = 0; i < 16; i++) acc[i] *= corr;
        #pragma unroll
        for (int w = 0; w < 4; w++)
            *(float4*)&ps[r * ATT_LD + c0 + w * 4] =
                make_float4(pv16[4 * w], pv16[4 * w + 1], pv16[4 * w + 2], pv16[4 * w + 3]);
        __syncthreads();

        #pragma unroll 4
        for (int j = 0; j < 64; j++) {
            const float pj = ps[r * ATT_LD + j];
            const float4* vr = (const float4*)&vs[j * ATT_LD + c0];
            #pragma unroll
            for (int w = 0; w < 4; w++) {
                float4 v4 = vr[w];
                acc[4 * w + 0] = fmaf(pj, v4.x, acc[4 * w + 0]);
                acc[4 * w + 1] = fmaf(pj, v4.y, acc[4 * w + 1]);
                acc[4 * w + 2] = fmaf(pj, v4.z, acc[4 * w + 2]);
                acc[4 * w + 3] = fmaf(pj, v4.w, acc[4 * w + 3]);
            }
        }
    }

    const float inv = 1.0f / lval;
    float* ob = o + ((size_t)b * Sseq + n * BSb + r) * Dmod + h * DHd + c0;
    #pragma unroll
    for (int w = 0; w < 4; w++) {
        float4 ov = make_float4(acc[4 * w] * inv, acc[4 * w + 1] * inv,
                                acc[4 * w + 2] * inv, acc[4 * w + 3] * inv);
        *(float4*)&ob[w * 4] = ov;
    }
}

// ---------------- launcher ----------------
extern "C" void kernel_launch(void* const* d_in, const int* in_sizes, int n_in,
                              void* d_out, int out_size) {
    const float* inputs = (const float*)d_in[0];
    const float* ln1_s  = (const float*)d_in[1];
    const float* ln1_b  = (const float*)d_in[2];
    const float* wq     = (const float*)d_in[3];
    const float* wk     = (const float*)d_in[4];
    const float* wv     = (const float*)d_in[5];
    const float* wo     = (const float*)d_in[6];
    const float* ln2_s  = (const float*)d_in[7];
    const float* ln2_b  = (const float*)d_in[8];
    const float* w1     = (const float*)d_in[9];
    const float* b1     = (const float*)d_in[10];
    const float* w2     = (const float*)d_in[11];
    const float* b2     = (const float*)d_in[12];
    float* out = (float*)d_out;

    float *xn, *q, *k, *v, *o, *yn, *hb;
    int *idx, *cnt;
    cudaGetSymbolAddress((void**)&xn, g_xn);
    cudaGetSymbolAddress((void**)&q,  g_q);
    cudaGetSymbolAddress((void**)&k,  g_k);
    cudaGetSymbolAddress((void**)&v,  g_v);
    cudaGetSymbolAddress((void**)&o,  g_o);
    cudaGetSymbolAddress((void**)&yn, g_yn);
    cudaGetSymbolAddress((void**)&hb, g_hb);
    cudaGetSymbolAddress((void**)&idx, g_idx);
    cudaGetSymbolAddress((void**)&cnt, g_cnt);

    cudaFuncSetAttribute(attn_kernel, cudaFuncAttributeMaxDynamicSharedMemorySize, ATT_SMEM);
    cudaFuncSetAttribute(sgemm_tc<0>, cudaFuncAttributeMaxDynamicSharedMemorySize, GEMM_SMEM);
    cudaFuncSetAttribute(sgemm_tc<1>, cudaFuncAttributeMaxDynamicSharedMemorySize, GEMM_SMEM);
    cudaFuncSetAttribute(sgemm_tc<2>, cudaFuncAttributeMaxDynamicSharedMemorySize, GEMM_SMEM);
    cudaFuncSetAttribute(sgemm_tc<3>, cudaFuncAttributeMaxDynamicSharedMemorySize, GEMM_SMEM);

    // 1. BigBird block index table — computed on HOST (input-independent),
    //    uploaded via an async H2D memcpy node (static storage persists).
    static int h_idx[NROWS * 8];
    static int h_cnt[NROWS];
    h_make_table(h_idx, h_cnt);
    cudaMemcpyAsync(idx, h_idx, sizeof(h_idx), cudaMemcpyHostToDevice, 0);
    cudaMemcpyAsync(cnt, h_cnt, sizeof(h_cnt), cudaMemcpyHostToDevice, 0);

    // 2. LN1
    ln_kernel<<<NTOK, 128>>>(inputs, ln1_s, ln1_b, xn);

    // 3. QKV projections (q pre-scaled by 1/sqrt(DH) = 0.125)
    dim3 g512(Dmod / 128, NTOK / 128);
    sgemm_tc<0><<<g512, 256, GEMM_SMEM>>>(xn, wq, q, NTOK, Dmod, Dmod, 0.125f, nullptr, nullptr);
    sgemm_tc<0><<<g512, 256, GEMM_SMEM>>>(xn, wk, k, NTOK, Dmod, Dmod, 1.0f,   nullptr, nullptr);
    sgemm_tc<0><<<g512, 256, GEMM_SMEM>>>(xn, wv, v, NTOK, Dmod, Dmod, 1.0f,   nullptr, nullptr);

    // 4. attention (interior sparse + global rows fused)
    attn_kernel<<<dim3(NBb, Hh, Bsz), 256, ATT_SMEM>>>(q, k, v, o, idx, cnt);

    // 5. output projection + residual:  x = o @ wo + inputs  -> d_out
    sgemm_tc<2><<<g512, 256, GEMM_SMEM>>>(o, wo, out, NTOK, Dmod, Dmod, 1.0f, nullptr, inputs);

    // 6. LN2
    ln_kernel<<<NTOK, 128>>>(out, ln2_s, ln2_b, yn);

    // 7. FFN1: gelu(yn @ w1 + b1)
    dim3 g2048(Mff / 128, NTOK / 128);
    sgemm_tc<1><<<g2048, 256, GEMM_SMEM>>>(yn, w1, hb, NTOK, Mff, Dmod, 1.0f, b1, nullptr);

    // 8. FFN2 + bias + residual: out = hb @ w2 + b2 + x
    sgemm_tc<3><<<g512, 256, GEMM_SMEM>>>(hb, w2, out, NTOK, Dmod, Mff, 1.0f, b2, out);
}

// round 3
// speedup vs baseline: 5.8452x; 3.6885x over previous
#include <cuda_runtime.h>
#include <math.h>
#include <stdint.h>

// ---------------- problem constants ----------------
#define Bsz   4
#define Sseq  4096
#define Dmod  512
#define Hh    8
#define DHd   64
#define Mff   2048
#define BSb   64
#define NBb   64
#define NROWS (NBb - 2)
#define NTOK  (Bsz * Sseq)        // 16384

// ---------------- scratch (device globals; no allocation) ----------------
__device__ float g_xn[(size_t)NTOK * Dmod];
__device__ float g_q [(size_t)NTOK * Dmod];
__device__ float g_k [(size_t)NTOK * Dmod];
__device__ float g_v [(size_t)NTOK * Dmod];
__device__ float g_o [(size_t)NTOK * Dmod];
__device__ float g_yn[(size_t)NTOK * Dmod];
__device__ float g_hb[(size_t)NTOK * Mff];
__device__ int   g_idx[NROWS * 8];
__device__ int   g_cnt[NROWS];

// ---------------- host-side numpy-legacy MT19937 (table is input-independent) ----------------
struct HostMT {
    unsigned int k[624];
    int pos;
};
static void h_mt_seed(HostMT& st, unsigned int seed) {
    for (int p = 0; p < 624; p++) {
        st.k[p] = seed;
        seed = 1812433253u * (seed ^ (seed >> 30)) + (unsigned)p + 1u;
    }
    st.pos = 624;
}
static unsigned int h_mt_next(HostMT& st) {
    if (st.pos == 624) {
        for (int i = 0; i < 624; i++) {
            unsigned int y = (st.k[i] & 0x80000000u) | (st.k[(i + 1) % 624] & 0x7fffffffu);
            st.k[i] = st.k[(i + 397) % 624] ^ (y >> 1) ^ ((y & 1u) ? 0x9908b0dfu : 0u);
        }
        st.pos = 0;
    }
    unsigned int y = st.k[st.pos++];
    y ^= y >> 11;
    y ^= (y << 7)  & 0x9d2c5680u;
    y ^= (y << 15) & 0xefc60000u;
    y ^= y >> 18;
    return y;
}
static unsigned int h_mt_interval(HostMT& st, unsigned int mx) {
    if (mx == 0u) return 0u;
    unsigned int mask = mx;
    mask |= mask >> 1; mask |= mask >> 2; mask |= mask >> 4;
    mask |= mask >> 8; mask |= mask >> 16;
    unsigned int v;
    do { v = h_mt_next(st) & mask; } while (v > mx);
    return v;
}
static void h_make_table(int* h_idx, int* h_cnt) {
    HostMT st;
    h_mt_seed(st, 0u);
    for (int i = 1; i <= NBb - 2; i++) {
        bool fx[NBb];
        for (int z = 0; z < NBb; z++) fx[z] = false;
        fx[0] = true; fx[NBb - 1] = true;
        fx[i - 1] = true; fx[i] = true; fx[i + 1] = true;
        int fixed[8], nf = 0;
        int allowed[NBb], na = 0;
        for (int bb = 0; bb < NBb; bb++) {
            if (fx[bb]) fixed[nf++] = bb;
            else        allowed[na++] = bb;
        }
        int perm[NBb];
        for (int t = 0; t < na; t++) perm[t] = t;
        for (int t = na - 1; t >= 1; t--) {
            int j = (int)h_mt_interval(st, (unsigned)t);
            int tmp = perm[t]; perm[t] = perm[j]; perm[j] = tmp;
        }
        int row = i - 1;
        int cnt = 0;
        for (int s = 0; s < nf; s++) h_idx[row * 8 + cnt++] = fixed[s];
        for (int r3 = 0; r3 < 3; r3++) h_idx[row * 8 + cnt++] = allowed[perm[r3]];
        h_cnt[row] = cnt;
        for (; cnt < 8; cnt++) h_idx[row * 8 + cnt] = 0;
    }
}

// ---------------- LayerNorm ----------------
__global__ void ln_kernel(const float* __restrict__ x, const float* __restrict__ g,
                          const float* __restrict__ bta, float* __restrict__ y) {
    __shared__ float red[2][4];
    const int row = blockIdx.x;
    const int t = threadIdx.x;
    const float* xr = x + (size_t)row * Dmod;
    float4 xv = ((const float4*)xr)[t];
    float s  = xv.x + xv.y + xv.z + xv.w;
    float q2 = xv.x * xv.x + xv.y * xv.y + xv.z * xv.z + xv.w * xv.w;
    #pragma unroll
    for (int o = 16; o; o >>= 1) {
        s  += __shfl_xor_sync(0xffffffffu, s,  o);
        q2 += __shfl_xor_sync(0xffffffffu, q2, o);
    }
    if ((t & 31) == 0) { red[0][t >> 5] = s; red[1][t >> 5] = q2; }
    __syncthreads();
    s  = red[0][0] + red[0][1] + red[0][2] + red[0][3];
    q2 = red[1][0] + red[1][1] + red[1][2] + red[1][3];
    const float mu   = s * (1.0f / Dmod);
    const float var  = q2 * (1.0f / Dmod) - mu * mu;
    const float rstd = rsqrtf(var + 1e-6f);
    float4 gv = ((const float4*)g)[t];
    float4 bv = ((const float4*)bta)[t];
    float4 ov;
    ov.x = (xv.x - mu) * rstd * gv.x + bv.x;
    ov.y = (xv.y - mu) * rstd * gv.y + bv.y;
    ov.z = (xv.z - mu) * rstd * gv.z + bv.z;
    ov.w = (xv.w - mu) * rstd * gv.w + bv.w;
    ((float4*)(y + (size_t)row * Dmod))[t] = ov;
}

// ---------------- common helpers ----------------
__device__ __forceinline__ float gelu_tanh(float x) {
    const float c = 0.7978845608028654f;
    float x3 = x * x * x;
    return 0.5f * x * (1.0f + tanhf(c * (x + 0.044715f * x3)));
}
__device__ __forceinline__ uint32_t f2tf(float x) {
    uint32_t r;
    asm("cvt.rna.tf32.f32 %0, %1;" : "=r"(r) : "f"(x));
    return r;
}
__device__ __forceinline__ void cpasync16(uint32_t saddr, const void* gaddr) {
    asm volatile("cp.async.cg.shared.global [%0], [%1], 16;" :: "r"(saddr), "l"(gaddr) : "memory");
}
__device__ __forceinline__ void mma_tf32(float* c, const uint32_t* a, uint32_t b0, uint32_t b1) {
    asm volatile(
        "mma.sync.aligned.m16n8k8.row.col.f32.tf32.tf32.f32 "
        "{%0,%1,%2,%3}, {%4,%5,%6,%7}, {%8,%9}, {%0,%1,%2,%3};"
        : "+f"(c[0]), "+f"(c[1]), "+f"(c[2]), "+f"(c[3])
        : "r"(a[0]), "r"(a[1]), "r"(a[2]), "r"(a[3]), "r"(b0), "r"(b1));
}

// ---------------- TF32 tensor-core SGEMM (unchanged from R2) ----------------
#define A_LD   36
#define B_LD   136
#define A_TILE (128 * A_LD)
#define B_TILE (32 * B_LD)
#define GEMM_SMEM ((2 * A_TILE + 2 * B_TILE) * 4)

// EPI: 0 = alpha*acc ; 1 = gelu(acc+bias) ; 2 = acc+res ; 3 = acc+bias+res
template <int EPI>
__global__ void __launch_bounds__(256, 2)
sgemm_tc(const float* __restrict__ A, const float* __restrict__ Bw,
         float* __restrict__ C, int Mr, int N, int K, float alpha,
         const float* __restrict__ bias, const float* __restrict__ res) {
    extern __shared__ float sm[];
    float* Asm = sm;
    float* Bsm = sm + 2 * A_TILE;

    const int tid  = threadIdx.x;
    const int bm   = blockIdx.y * 128;
    const int bn   = blockIdx.x * 128;
    const int lane = tid & 31;
    const int wid  = tid >> 5;
    const int wm   = wid & 1;
    const int wn   = wid >> 1;
    const int lr   = lane >> 2;
    const int lc   = lane & 3;

    uint32_t sbase = (uint32_t)__cvta_generic_to_shared(sm);
    uint32_t sA = sbase;
    uint32_t sB = sbase + 2 * A_TILE * 4;

    float acc[4][4][4];
    #pragma unroll
    for (int mt = 0; mt < 4; mt++)
        #pragma unroll
        for (int nt = 0; nt < 4; nt++)
            #pragma unroll
            for (int r = 0; r < 4; r++) acc[mt][nt][r] = 0.0f;

    const int nk = K >> 5;

    {
        const float* Ag = A + (size_t)bm * K;
        #pragma unroll
        for (int i = 0; i < 4; i++) {
            int c = tid + 256 * i;
            int row = c >> 3, k4 = (c & 7) * 4;
            cpasync16(sA + (uint32_t)(row * A_LD + k4) * 4, Ag + (size_t)row * K + k4);
        }
        const float* Bg = Bw + bn;
        #pragma unroll
        for (int i = 0; i < 4; i++) {
            int c = tid + 256 * i;
            int kr = c >> 5, n4 = (c & 31) * 4;
            cpasync16(sB + (uint32_t)(kr * B_LD + n4) * 4, Bg + (size_t)kr * N + n4);
        }
        asm volatile("cp.async.commit_group;" ::: "memory");
    }

    for (int t = 0; t < nk; t++) {
        const int cur = t & 1;
        if (t + 1 < nk) {
            const int nb = (t + 1) & 1;
            const float* Ag = A + (size_t)bm * K + (t + 1) * 32;
            #pragma unroll
            for (int i = 0; i < 4; i++) {
                int c = tid + 256 * i;
                int row = c >> 3, k4 = (c & 7) * 4;
                cpasync16(sA + (uint32_t)(nb * A_TILE + row * A_LD + k4) * 4,
                          Ag + (size_t)row * K + k4);
            }
            const float* Bg = Bw + (size_t)((t + 1) * 32) * N + bn;
            #pragma unroll
            for (int i = 0; i < 4; i++) {
                int c = tid + 256 * i;
                int kr = c >> 5, n4 = (c & 31) * 4;
                cpasync16(sB + (uint32_t)(nb * B_TILE + kr * B_LD + n4) * 4,
                          Bg + (size_t)kr * N + n4);
            }
            asm volatile("cp.async.commit_group;" ::: "memory");
            asm volatile("cp.async.wait_group 1;" ::: "memory");
        } else {
            asm volatile("cp.async.wait_group 0;" ::: "memory");
        }
        __syncthreads();

        const float* Asb = Asm + cur * A_TILE;
        const float* Bsb = Bsm + cur * B_TILE;

        #pragma unroll
        for (int ks = 0; ks < 4; ks++) {
            const int k0 = ks * 8;
            uint32_t af[4][4], bf[4][2];
            #pragma unroll
            for (int mt = 0; mt < 4; mt++) {
                const float* p = Asb + (wm * 64 + mt * 16 + lr) * A_LD + k0 + lc;
                af[mt][0] = f2tf(p[0]);
                af[mt][1] = f2tf(p[8 * A_LD]);
                af[mt][2] = f2tf(p[4]);
                af[mt][3] = f2tf(p[8 * A_LD + 4]);
            }
            #pragma unroll
            for (int nt = 0; nt < 4; nt++) {
                const float* p = Bsb + (k0 + lc) * B_LD + wn * 32 + nt * 8 + lr;
                bf[nt][0] = f2tf(p[0]);
                bf[nt][1] = f2tf(p[4 * B_LD]);
            }
            #pragma unroll
            for (int mt = 0; mt < 4; mt++)
                #pragma unroll
                for (int nt = 0; nt < 4; nt++)
                    mma_tf32(acc[mt][nt], af[mt], bf[nt][0], bf[nt][1]);
        }
        __syncthreads();
    }

    #pragma unroll
    for (int mt = 0; mt < 4; mt++) {
        const int row0 = bm + wm * 64 + mt * 16 + lr;
        #pragma unroll
        for (int half = 0; half < 2; half++) {
            const int row = row0 + half * 8;
            #pragma unroll
            for (int nt = 0; nt < 4; nt++) {
                const int col = bn + wn * 32 + nt * 8 + lc * 2;
                float v0 = acc[mt][nt][half * 2 + 0];
                float v1 = acc[mt][nt][half * 2 + 1];
                const size_t off = (size_t)row * N + col;
                if (EPI == 0) { v0 *= alpha; v1 *= alpha; }
                if (EPI == 1) {
                    v0 = gelu_tanh(v0 + bias[col]);
                    v1 = gelu_tanh(v1 + bias[col + 1]);
                }
                if (EPI == 2) {
                    v0 += res[off]; v1 += res[off + 1];
                }
                if (EPI == 3) {
                    v0 += bias[col] + res[off];
                    v1 += bias[col + 1] + res[off + 1];
                }
                *(float2*)&C[off] = make_float2(v0, v1);
            }
        }
    }
}

// ---------------- tensor-core flash BigBird attention ----------------
// 128 threads = 4 warps; warp w owns query rows [w*16, w*16+16).
// QK^T and PV on m16n8k8.tf32 mma; K/V double-buffered cp.async;
// P round-trips per-warp-private smem (syncwarp only).
#define KLD 68
#define VLD 72
#define PLD 68
#define K_OFF   0
#define V_OFF   (2 * 64 * KLD)                 // 8704
#define P_OFF   (V_OFF + 2 * 64 * VLD)         // 17920
#define ATT_SMEM ((P_OFF + 64 * PLD) * 4)      // 89088 bytes

__device__ __forceinline__ void att_load_kv(uint32_t sbase, int tid, int stage,
                                            const float* kb_g, const float* vb_g) {
    #pragma unroll
    for (int i = 0; i < 8; i++) {
        int c = tid + 128 * i;
        int rr = c >> 4, c4 = (c & 15) * 4;
        cpasync16(sbase + (uint32_t)(K_OFF + stage * 64 * KLD + rr * KLD + c4) * 4,
                  kb_g + (size_t)rr * Dmod + c4);
        cpasync16(sbase + (uint32_t)(V_OFF + stage * 64 * VLD + rr * VLD + c4) * 4,
                  vb_g + (size_t)rr * Dmod + c4);
    }
    asm volatile("cp.async.commit_group;" ::: "memory");
}

__global__ void __launch_bounds__(128)
attn_tc(const float* __restrict__ q, const float* __restrict__ k,
        const float* __restrict__ v, float* __restrict__ o,
        const int* __restrict__ idxTab, const int* __restrict__ cntTab) {
    extern __shared__ float sm[];
    float* Ks = sm + K_OFF;
    float* Vs = sm + V_OFF;
    float* Ps = sm + P_OFF;

    const int bx = blockIdx.x;
    const int n = (bx < 2) ? (bx == 0 ? 0 : NBb - 1) : (bx - 1);  // globals first
    const int h = blockIdx.y, b = blockIdx.z;
    const int tid = threadIdx.x;
    const int lane = tid & 31, w = tid >> 5;
    const int lr = lane >> 2, lc = lane & 3;
    const bool isg = (n == 0) || (n == NBb - 1);
    const int nkb = isg ? NBb : cntTab[n - 1];

    uint32_t sbase = (uint32_t)__cvta_generic_to_shared(sm);

    // ---- Q tile -> smem (Ps region) -> tf32 A-fragments, kept in registers ----
    const float* qbase = q + ((size_t)b * Sseq + n * BSb) * Dmod + h * DHd;
    for (int i = tid; i < 64 * 16; i += 128) {
        int rr = i >> 4, c4 = (i & 15) * 4;
        *(float4*)&Ps[rr * PLD + c4] = *(const float4*)&qbase[(size_t)rr * Dmod + c4];
    }
    __syncthreads();
    uint32_t aq[8][4];
    #pragma unroll
    for (int kt = 0; kt < 8; kt++) {
        const float* p = Ps + (w * 16 + lr) * PLD + kt * 8 + lc;
        aq[kt][0] = f2tf(p[0]);
        aq[kt][1] = f2tf(p[8 * PLD]);
        aq[kt][2] = f2tf(p[4]);
        aq[kt][3] = f2tf(p[8 * PLD + 4]);
    }
    __syncthreads();  // Ps free for P use

    float accO[8][4];
    #pragma unroll
    for (int nt = 0; nt < 8; nt++)
        #pragma unroll
        for (int r = 0; r < 4; r++) accO[nt][r] = 0.0f;
    float m0 = -1e30f, m1 = -1e30f, l0 = 0.0f, l1 = 0.0f;

    // prologue: kv-block 0 -> stage 0
    {
        const int kb = isg ? 0 : idxTab[(n - 1) * 8];
        const float* kb_g = k + ((size_t)b * Sseq + kb * BSb) * Dmod + h * DHd;
        const float* vb_g = v + ((size_t)b * Sseq + kb * BSb) * Dmod + h * DHd;
        att_load_kv(sbase, tid, 0, kb_g, vb_g);
    }

    for (int it = 0; it < nkb; it++) {
        const int st = it & 1;
        if (it + 1 < nkb) {
            const int kb = isg ? (it + 1) : idxTab[(n - 1) * 8 + it + 1];
            const float* kb_g = k + ((size_t)b * Sseq + kb * BSb) * Dmod + h * DHd;
            const float* vb_g = v + ((size_t)b * Sseq + kb * BSb) * Dmod + h * DHd;
            att_load_kv(sbase, tid, st ^ 1, kb_g, vb_g);
            asm volatile("cp.async.wait_group 1;" ::: "memory");
        } else {
            asm volatile("cp.async.wait_group 0;" ::: "memory");
        }
        __syncthreads();

        // ---- S = Q · K^T  (per warp: 16 x 64) ----
        float s[8][4];
        #pragma unroll
        for (int nt = 0; nt < 8; nt++)
            #pragma unroll
            for (int r = 0; r < 4; r++) s[nt][r] = 0.0f;

        const float* Kst = Ks + st * 64 * KLD;
        #pragma unroll
        for (int kt = 0; kt < 8; kt++) {
            #pragma unroll
            for (int nt = 0; nt < 8; nt++) {
                const float* pb = Kst + (nt * 8 + lr) * KLD + kt * 8 + lc;
                mma_tf32(s[nt], aq[kt], f2tf(pb[0]), f2tf(pb[4]));
            }
        }

        // ---- streaming softmax on fragments (rows lr / lr+8) ----
        float mx0 = -1e30f, mx1 = -1e30f;
        #pragma unroll
        for (int nt = 0; nt < 8; nt++) {
            mx0 = fmaxf(mx0, fmaxf(s[nt][0], s[nt][1]));
            mx1 = fmaxf(mx1, fmaxf(s[nt][2], s[nt][3]));
        }
        mx0 = fmaxf(mx0, __shfl_xor_sync(0xffffffffu, mx0, 1));
        mx0 = fmaxf(mx0, __shfl_xor_sync(0xffffffffu, mx0, 2));
        mx1 = fmaxf(mx1, __shfl_xor_sync(0xffffffffu, mx1, 1));
        mx1 = fmaxf(mx1, __shfl_xor_sync(0xffffffffu, mx1, 2));
        const float mn0 = fmaxf(m0, mx0), mn1 = fmaxf(m1, mx1);
        const float cor0 = __expf(m0 - mn0), cor1 = __expf(m1 - mn1);
        float ps0 = 0.0f, ps1 = 0.0f;
        #pragma unroll
        for (int nt = 0; nt < 8; nt++) {
            s[nt][0] = __expf(s[nt][0] - mn0);
            s[nt][1] = __expf(s[nt][1] - mn0);
            s[nt][2] = __expf(s[nt][2] - mn1);
            s[nt][3] = __expf(s[nt][3] - mn1);
            ps0 += s[nt][0] + s[nt][1];
            ps1 += s[nt][2] + s[nt][3];
        }
        ps0 += __shfl_xor_sync(0xffffffffu, ps0, 1);
        ps0 += __shfl_xor_sync(0xffffffffu, ps0, 2);
        ps1 += __shfl_xor_sync(0xffffffffu, ps1, 1);
        ps1 += __shfl_xor_sync(0xffffffffu, ps1, 2);
        l0 = l0 * cor0 + ps0;
        l1 = l1 * cor1 + ps1;
        m0 = mn0; m1 = mn1;
        #pragma unroll
        for (int nt = 0; nt < 8; nt++) {
            accO[nt][0] *= cor0; accO[nt][1] *= cor0;
            accO[nt][2] *= cor1; accO[nt][3] *= cor1;
        }

        // ---- P -> per-warp-private smem ----
        float* pw = Ps + (w * 16 + lr) * PLD;
        #pragma unroll
        for (int nt = 0; nt < 8; nt++) {
            *(float2*)&pw[nt * 8 + 2 * lc]             = make_float2(s[nt][0], s[nt][1]);
            *(float2*)&pw[8 * PLD + nt * 8 + 2 * lc]   = make_float2(s[nt][2], s[nt][3]);
        }
        __syncwarp();

        // ---- O += P · V  (per warp: 16 x 64) ----
        const float* Vst = Vs + st * 64 * VLD;
        #pragma unroll
        for (int kt = 0; kt < 8; kt++) {
            const float* pp = Ps + (w * 16 + lr) * PLD + kt * 8 + lc;
            uint32_t ap[4];
            ap[0] = f2tf(pp[0]);
            ap[1] = f2tf(pp[8 * PLD]);
            ap[2] = f2tf(pp[4]);
            ap[3] = f2tf(pp[8 * PLD + 4]);
            #pragma unroll
            for (int nt = 0; nt < 8; nt++) {
                const float* pv = Vst + (kt * 8 + lc) * VLD + nt * 8 + lr;
                mma_tf32(accO[nt], ap, f2tf(pv[0]), f2tf(pv[4 * VLD]));
            }
        }
        __syncthreads();  // stage st consumed; next prefetch may overwrite it
    }

    // ---- finalize & store ----
    const float inv0 = 1.0f / l0, inv1 = 1.0f / l1;
    float* ob = o + ((size_t)b * Sseq + n * BSb + w * 16 + lr) * Dmod + h * DHd;
    #pragma unroll
    for (int nt = 0; nt < 8; nt++) {
        *(float2*)&ob[nt * 8 + 2 * lc] =
            make_float2(accO[nt][0] * inv0, accO[nt][1] * inv0);
        *(float2*)&ob[(size_t)8 * Dmod + nt * 8 + 2 * lc] =
            make_float2(accO[nt][2] * inv1, accO[nt][3] * inv1);
    }
}

// ---------------- launcher ----------------
extern "C" void kernel_launch(void* const* d_in, const int* in_sizes, int n_in,
                              void* d_out, int out_size) {
    const float* inputs = (const float*)d_in[0];
    const float* ln1_s  = (const float*)d_in[1];
    const float* ln1_b  = (const float*)d_in[2];
    const float* wq     = (const float*)d_in[3];
    const float* wk     = (const float*)d_in[4];
    const float* wv     = (const float*)d_in[5];
    const float* wo     = (const float*)d_in[6];
    const float* ln2_s  = (const float*)d_in[7];
    const float* ln2_b  = (const float*)d_in[8];
    const float* w1     = (const float*)d_in[9];
    const float* b1     = (const float*)d_in[10];
    const float* w2     = (const float*)d_in[11];
    const float* b2     = (const float*)d_in[12];
    float* out = (float*)d_out;

    float *xn, *q, *k, *v, *o, *yn, *hb;
    int *idx, *cnt;
    cudaGetSymbolAddress((void**)&xn, g_xn);
    cudaGetSymbolAddress((void**)&q,  g_q);
    cudaGetSymbolAddress((void**)&k,  g_k);
    cudaGetSymbolAddress((void**)&v,  g_v);
    cudaGetSymbolAddress((void**)&o,  g_o);
    cudaGetSymbolAddress((void**)&yn, g_yn);
    cudaGetSymbolAddress((void**)&hb, g_hb);
    cudaGetSymbolAddress((void**)&idx, g_idx);
    cudaGetSymbolAddress((void**)&cnt, g_cnt);

    cudaFuncSetAttribute(attn_tc, cudaFuncAttributeMaxDynamicSharedMemorySize, ATT_SMEM);
    cudaFuncSetAttribute(sgemm_tc<0>, cudaFuncAttributeMaxDynamicSharedMemorySize, GEMM_SMEM);
    cudaFuncSetAttribute(sgemm_tc<1>, cudaFuncAttributeMaxDynamicSharedMemorySize, GEMM_SMEM);
    cudaFuncSetAttribute(sgemm_tc<2>, cudaFuncAttributeMaxDynamicSharedMemorySize, GEMM_SMEM);
    cudaFuncSetAttribute(sgemm_tc<3>, cudaFuncAttributeMaxDynamicSharedMemorySize, GEMM_SMEM);

    // 1. BigBird block index table (host-computed, input-independent)
    static int h_idx[NROWS * 8];
    static int h_cnt[NROWS];
    h_make_table(h_idx, h_cnt);
    cudaMemcpyAsync(idx, h_idx, sizeof(h_idx), cudaMemcpyHostToDevice, 0);
    cudaMemcpyAsync(cnt, h_cnt, sizeof(h_cnt), cudaMemcpyHostToDevice, 0);

    // 2. LN1
    ln_kernel<<<NTOK, 128>>>(inputs, ln1_s, ln1_b, xn);

    // 3. QKV projections (q pre-scaled by 1/sqrt(DH) = 0.125)
    dim3 g512(Dmod / 128, NTOK / 128);
    sgemm_tc<0><<<g512, 256, GEMM_SMEM>>>(xn, wq, q, NTOK, Dmod, Dmod, 0.125f, nullptr, nullptr);
    sgemm_tc<0><<<g512, 256, GEMM_SMEM>>>(xn, wk, k, NTOK, Dmod, Dmod, 1.0f,   nullptr, nullptr);
    sgemm_tc<0><<<g512, 256, GEMM_SMEM>>>(xn, wv, v, NTOK, Dmod, Dmod, 1.0f,   nullptr, nullptr);

    // 4. tensor-core flash attention
    attn_tc<<<dim3(NBb, Hh, Bsz), 128, ATT_SMEM>>>(q, k, v, o, idx, cnt);

    // 5. output projection + residual
    sgemm_tc<2><<<g512, 256, GEMM_SMEM>>>(o, wo, out, NTOK, Dmod, Dmod, 1.0f, nullptr, inputs);

    // 6. LN2
    ln_kernel<<<NTOK, 128>>>(out, ln2_s, ln2_b, yn);

    // 7. FFN1: gelu(yn @ w1 + b1)
    dim3 g2048(Mff / 128, NTOK / 128);
    sgemm_tc<1><<<g2048, 256, GEMM_SMEM>>>(yn, w1, hb, NTOK, Mff, Dmod, 1.0f, b1, nullptr);

    // 8. FFN2 + bias + residual
    sgemm_tc<3><<<g512, 256, GEMM_SMEM>>>(hb, w2, out, NTOK, Dmod, Mff, 1.0f, b2, out);
}

// round 4
// speedup vs baseline: 6.9447x; 1.1881x over previous
#include <cuda_runtime.h>
#include <math.h>
#include <stdint.h>

// ---------------- problem constants ----------------
#define Bsz   4
#define Sseq  4096
#define Dmod  512
#define Hh    8
#define DHd   64
#define Mff   2048
#define BSb   64
#define NBb   64
#define NROWS (NBb - 2)
#define NTOK  (Bsz * Sseq)        // 16384
#define QKV_LD 1536

// ---------------- scratch (device globals; no allocation) ----------------
__device__ float g_xn  [(size_t)NTOK * Dmod];
__device__ float g_qkv [(size_t)NTOK * QKV_LD];   // packed q|k|v, tf32-rounded
__device__ float g_o   [(size_t)NTOK * Dmod];
__device__ float g_yn  [(size_t)NTOK * Dmod];
__device__ float g_hb  [(size_t)NTOK * Mff];
__device__ float g_wqkv[(size_t)Dmod * QKV_LD];   // packed rounded weights
__device__ float g_wor [(size_t)Dmod * Dmod];
__device__ float g_w1r [(size_t)Dmod * Mff];
__device__ float g_w2r [(size_t)Mff * Dmod];
__device__ int   g_idx[NROWS * 8];
__device__ int   g_cnt[NROWS];

// ---------------- host-side numpy-legacy MT19937 (table is input-independent) ----------------
struct HostMT { unsigned int k[624]; int pos; };
static void h_mt_seed(HostMT& st, unsigned int seed) {
    for (int p = 0; p < 624; p++) {
        st.k[p] = seed;
        seed = 1812433253u * (seed ^ (seed >> 30)) + (unsigned)p + 1u;
    }
    st.pos = 624;
}
static unsigned int h_mt_next(HostMT& st) {
    if (st.pos == 624) {
        for (int i = 0; i < 624; i++) {
            unsigned int y = (st.k[i] & 0x80000000u) | (st.k[(i + 1) % 624] & 0x7fffffffu);
            st.k[i] = st.k[(i + 397) % 624] ^ (y >> 1) ^ ((y & 1u) ? 0x9908b0dfu : 0u);
        }
        st.pos = 0;
    }
    unsigned int y = st.k[st.pos++];
    y ^= y >> 11;
    y ^= (y << 7)  & 0x9d2c5680u;
    y ^= (y << 15) & 0xefc60000u;
    y ^= y >> 18;
    return y;
}
static unsigned int h_mt_interval(HostMT& st, unsigned int mx) {
    if (mx == 0u) return 0u;
    unsigned int mask = mx;
    mask |= mask >> 1; mask |= mask >> 2; mask |= mask >> 4;
    mask |= mask >> 8; mask |= mask >> 16;
    unsigned int v;
    do { v = h_mt_next(st) & mask; } while (v > mx);
    return v;
}
static void h_make_table(int* h_idx, int* h_cnt) {
    HostMT st;
    h_mt_seed(st, 0u);
    for (int i = 1; i <= NBb - 2; i++) {
        bool fx[NBb];
        for (int z = 0; z < NBb; z++) fx[z] = false;
        fx[0] = true; fx[NBb - 1] = true;
        fx[i - 1] = true; fx[i] = true; fx[i + 1] = true;
        int fixed[8], nf = 0;
        int allowed[NBb], na = 0;
        for (int bb = 0; bb < NBb; bb++) {
            if (fx[bb]) fixed[nf++] = bb;
            else        allowed[na++] = bb;
        }
        int perm[NBb];
        for (int t = 0; t < na; t++) perm[t] = t;
        for (int t = na - 1; t >= 1; t--) {
            int j = (int)h_mt_interval(st, (unsigned)t);
            int tmp = perm[t]; perm[t] = perm[j]; perm[j] = tmp;
        }
        int row = i - 1;
        int cnt = 0;
        for (int s = 0; s < nf; s++) h_idx[row * 8 + cnt++] = fixed[s];
        for (int r3 = 0; r3 < 3; r3++) h_idx[row * 8 + cnt++] = allowed[perm[r3]];
        h_cnt[row] = cnt;
        for (; cnt < 8; cnt++) h_idx[row * 8 + cnt] = 0;
    }
}

// ---------------- helpers ----------------
__device__ __forceinline__ uint32_t f2tf(float x) {
    uint32_t r;
    asm("cvt.rna.tf32.f32 %0, %1;" : "=r"(r) : "f"(x));
    return r;
}
__device__ __forceinline__ float rf(float x) { return __uint_as_float(f2tf(x)); }
__device__ __forceinline__ float4 r4(float4 a) {
    a.x = rf(a.x); a.y = rf(a.y); a.z = rf(a.z); a.w = rf(a.w);
    return a;
}
__device__ __forceinline__ float gelu_tanh(float x) {
    const float c = 0.7978845608028654f;
    float x3 = x * x * x;
    return 0.5f * x * (1.0f + tanhf(c * (x + 0.044715f * x3)));
}
__device__ __forceinline__ void cpasync16(uint32_t saddr, const void* gaddr) {
    asm volatile("cp.async.cg.shared.global [%0], [%1], 16;" :: "r"(saddr), "l"(gaddr) : "memory");
}
__device__ __forceinline__ void mma_tf32(float* c, const uint32_t* a, uint32_t b0, uint32_t b1) {
    asm volatile(
        "mma.sync.aligned.m16n8k8.row.col.f32.tf32.tf32.f32 "
        "{%0,%1,%2,%3}, {%4,%5,%6,%7}, {%8,%9}, {%0,%1,%2,%3};"
        : "+f"(c[0]), "+f"(c[1]), "+f"(c[2]), "+f"(c[3])
        : "r"(a[0]), "r"(a[1]), "r"(a[2]), "r"(a[3]), "r"(b0), "r"(b1));
}

// ---------------- weight rounding + packing (runs once per launch, ~6us) ----------------
// 786432 float4 total: [0,196608) pack wq|wk|wv -> g_wqkv, then wo, w1, w2.
__global__ void round_pack(const float* __restrict__ wq, const float* __restrict__ wk,
                           const float* __restrict__ wv, const float* __restrict__ wo,
                           const float* __restrict__ w1, const float* __restrict__ w2,
                           float* __restrict__ dqkv, float* __restrict__ dwo,
                           float* __restrict__ dw1, float* __restrict__ dw2) {
    int i = blockIdx.x * 256 + threadIdx.x;
    if (i < 196608) {
        int d = i / 384, c4 = (i % 384) * 4;
        const float* src = (c4 < 512) ? wq : (c4 < 1024 ? wk : wv);
        float4 vsrc = *(const float4*)&src[(size_t)d * 512 + (c4 & 511)];
        *(float4*)&dqkv[(size_t)d * QKV_LD + c4] = r4(vsrc);
    } else if (i < 262144) {
        int j = i - 196608;
        ((float4*)dwo)[j] = r4(((const float4*)wo)[j]);
    } else if (i < 524288) {
        int j = i - 262144;
        ((float4*)dw1)[j] = r4(((const float4*)w1)[j]);
    } else if (i < 786432) {
        int j = i - 524288;
        ((float4*)dw2)[j] = r4(((const float4*)w2)[j]);
    }
}

// ---------------- LayerNorm (RND: emit tf32-rounded output) ----------------
template <bool RND>
__global__ void ln_kernel(const float* __restrict__ x, const float* __restrict__ g,
                          const float* __restrict__ bta, float* __restrict__ y) {
    __shared__ float red[2][4];
    const int row = blockIdx.x;
    const int t = threadIdx.x;
    const float* xr = x + (size_t)row * Dmod;
    float4 xv = ((const float4*)xr)[t];
    float s  = xv.x + xv.y + xv.z + xv.w;
    float q2 = xv.x * xv.x + xv.y * xv.y + xv.z * xv.z + xv.w * xv.w;
    #pragma unroll
    for (int o = 16; o; o >>= 1) {
        s  += __shfl_xor_sync(0xffffffffu, s,  o);
        q2 += __shfl_xor_sync(0xffffffffu, q2, o);
    }
    if ((t & 31) == 0) { red[0][t >> 5] = s; red[1][t >> 5] = q2; }
    __syncthreads();
    s  = red[0][0] + red[0][1] + red[0][2] + red[0][3];
    q2 = red[1][0] + red[1][1] + red[1][2] + red[1][3];
    const float mu   = s * (1.0f / Dmod);
    const float var  = q2 * (1.0f / Dmod) - mu * mu;
    const float rstd = rsqrtf(var + 1e-6f);
    float4 gv = ((const float4*)g)[t];
    float4 bv = ((const float4*)bta)[t];
    float4 ov;
    ov.x = (xv.x - mu) * rstd * gv.x + bv.x;
    ov.y = (xv.y - mu) * rstd * gv.y + bv.y;
    ov.z = (xv.z - mu) * rstd * gv.z + bv.z;
    ov.w = (xv.w - mu) * rstd * gv.w + bv.w;
    if (RND) ov = r4(ov);
    ((float4*)(y + (size_t)row * Dmod))[t] = ov;
}

// ---------------- TF32 tensor-core SGEMM (inputs pre-rounded; no cvt in loop) ----------------
#define A_LD   36
#define B_LD   136
#define A_TILE (128 * A_LD)
#define B_TILE (32 * B_LD)
#define GEMM_SMEM ((2 * A_TILE + 2 * B_TILE) * 4)

// EPI: 0 = qkv (alpha on cols<512, round) ; 1 = gelu(acc+bias) ; 2 = acc+res ; 3 = acc+bias+res
template <int EPI, bool RND>
__global__ void __launch_bounds__(256, 2)
sgemm_tc(const float* __restrict__ A, const float* __restrict__ Bw,
         float* __restrict__ C, int N, int K, float alpha,
         const float* __restrict__ bias, const float* __restrict__ res) {
    extern __shared__ float sm[];
    float* Asm = sm;
    float* Bsm = sm + 2 * A_TILE;

    const int tid  = threadIdx.x;
    const int bm   = blockIdx.y * 128;
    const int bn   = blockIdx.x * 128;
    const int lane = tid & 31;
    const int wid  = tid >> 5;
    const int wm   = wid & 1;
    const int wn   = wid >> 1;
    const int lr   = lane >> 2;
    const int lc   = lane & 3;

    uint32_t sbase = (uint32_t)__cvta_generic_to_shared(sm);
    uint32_t sA = sbase;
    uint32_t sB = sbase + 2 * A_TILE * 4;

    float acc[4][4][4];
    #pragma unroll
    for (int mt = 0; mt < 4; mt++)
        #pragma unroll
        for (int nt = 0; nt < 4; nt++)
            #pragma unroll
            for (int r = 0; r < 4; r++) acc[mt][nt][r] = 0.0f;

    const int nk = K >> 5;

    {
        const float* Ag = A + (size_t)bm * K;
        #pragma unroll
        for (int i = 0; i < 4; i++) {
            int c = tid + 256 * i;
            int row = c >> 3, k4 = (c & 7) * 4;
            cpasync16(sA + (uint32_t)(row * A_LD + k4) * 4, Ag + (size_t)row * K + k4);
        }
        const float* Bg = Bw + bn;
        #pragma unroll
        for (int i = 0; i < 4; i++) {
            int c = tid + 256 * i;
            int kr = c >> 5, n4 = (c & 31) * 4;
            cpasync16(sB + (uint32_t)(kr * B_LD + n4) * 4, Bg + (size_t)kr * N + n4);
        }
        asm volatile("cp.async.commit_group;" ::: "memory");
    }

    for (int t = 0; t < nk; t++) {
        const int cur = t & 1;
        if (t + 1 < nk) {
            const int nb = (t + 1) & 1;
            const float* Ag = A + (size_t)bm * K + (t + 1) * 32;
            #pragma unroll
            for (int i = 0; i < 4; i++) {
                int c = tid + 256 * i;
                int row = c >> 3, k4 = (c & 7) * 4;
                cpasync16(sA + (uint32_t)(nb * A_TILE + row * A_LD + k4) * 4,
                          Ag + (size_t)row * K + k4);
            }
            const float* Bg = Bw + (size_t)((t + 1) * 32) * N + bn;
            #pragma unroll
            for (int i = 0; i < 4; i++) {
                int c = tid + 256 * i;
                int kr = c >> 5, n4 = (c & 31) * 4;
                cpasync16(sB + (uint32_t)(nb * B_TILE + kr * B_LD + n4) * 4,
                          Bg + (size_t)kr * N + n4);
            }
            asm volatile("cp.async.commit_group;" ::: "memory");
            asm volatile("cp.async.wait_group 1;" ::: "memory");
        } else {
            asm volatile("cp.async.wait_group 0;" ::: "memory");
        }
        __syncthreads();

        const uint32_t* Asb = (const uint32_t*)(Asm + cur * A_TILE);
        const uint32_t* Bsb = (const uint32_t*)(Bsm + cur * B_TILE);

        #pragma unroll
        for (int ks = 0; ks < 4; ks++) {
            const int k0 = ks * 8;
            uint32_t af[4][4], bf[4][2];
            #pragma unroll
            for (int mt = 0; mt < 4; mt++) {
                const uint32_t* p = Asb + (wm * 64 + mt * 16 + lr) * A_LD + k0 + lc;
                af[mt][0] = p[0];
                af[mt][1] = p[8 * A_LD];
                af[mt][2] = p[4];
                af[mt][3] = p[8 * A_LD + 4];
            }
            #pragma unroll
            for (int nt = 0; nt < 4; nt++) {
                const uint32_t* p = Bsb + (k0 + lc) * B_LD + wn * 32 + nt * 8 + lr;
                bf[nt][0] = p[0];
                bf[nt][1] = p[4 * B_LD];
            }
            #pragma unroll
            for (int mt = 0; mt < 4; mt++)
                #pragma unroll
                for (int nt = 0; nt < 4; nt++)
                    mma_tf32(acc[mt][nt], af[mt], bf[nt][0], bf[nt][1]);
        }
        __syncthreads();
    }

    const float a_eff = (EPI == 0) ? ((bn < 512) ? alpha : 1.0f) : alpha;

    #pragma unroll
    for (int mt = 0; mt < 4; mt++) {
        const int row0 = bm + wm * 64 + mt * 16 + lr;
        #pragma unroll
        for (int half = 0; half < 2; half++) {
            const int row = row0 + half * 8;
            #pragma unroll
            for (int nt = 0; nt < 4; nt++) {
                const int col = bn + wn * 32 + nt * 8 + lc * 2;
                float v0 = acc[mt][nt][half * 2 + 0];
                float v1 = acc[mt][nt][half * 2 + 1];
                const size_t off = (size_t)row * N + col;
                if (EPI == 0) { v0 *= a_eff; v1 *= a_eff; }
                if (EPI == 1) {
                    v0 = gelu_tanh(v0 + bias[col]);
                    v1 = gelu_tanh(v1 + bias[col + 1]);
                }
                if (EPI == 2) { v0 += res[off]; v1 += res[off + 1]; }
                if (EPI == 3) {
                    v0 += bias[col] + res[off];
                    v1 += bias[col + 1] + res[off + 1];
                }
                if (RND) { v0 = rf(v0); v1 = rf(v1); }
                *(float2*)&C[off] = make_float2(v0, v1);
            }
        }
    }
}

// ---------------- tensor-core flash BigBird attention ----------------
// q/k/v pre-rounded tf32 in packed g_qkv [tok][1536]. No cvt in hot loop.
#define KLD 68
#define VLD 72
#define PLD 68
#define K_OFF   0
#define V_OFF   (2 * 64 * KLD)
#define P_OFF   (V_OFF + 2 * 64 * VLD)
#define ATT_SMEM ((P_OFF + 64 * PLD) * 4)

__device__ __forceinline__ void att_load_kv(uint32_t sbase, int tid, int stage,
                                            const float* kb_g, const float* vb_g) {
    #pragma unroll
    for (int i = 0; i < 8; i++) {
        int c = tid + 128 * i;
        int rr = c >> 4, c4 = (c & 15) * 4;
        cpasync16(sbase + (uint32_t)(K_OFF + stage * 64 * KLD + rr * KLD + c4) * 4,
                  kb_g + (size_t)rr * QKV_LD + c4);
        cpasync16(sbase + (uint32_t)(V_OFF + stage * 64 * VLD + rr * VLD + c4) * 4,
                  vb_g + (size_t)rr * QKV_LD + c4);
    }
    asm volatile("cp.async.commit_group;" ::: "memory");
}

__global__ void __launch_bounds__(128)
attn_tc(const float* __restrict__ qkv, float* __restrict__ o,
        const int* __restrict__ idxTab, const int* __restrict__ cntTab) {
    extern __shared__ float sm[];
    float* Ks = sm + K_OFF;
    float* Vs = sm + V_OFF;
    float* Ps = sm + P_OFF;

    const int bx = blockIdx.x;
    const int n = (bx < 2) ? (bx == 0 ? 0 : NBb - 1) : (bx - 1);  // globals first
    const int h = blockIdx.y, b = blockIdx.z;
    const int tid = threadIdx.x;
    const int lane = tid & 31, w = tid >> 5;
    const int lr = lane >> 2, lc = lane & 3;
    const bool isg = (n == 0) || (n == NBb - 1);
    const int nkb = isg ? NBb : cntTab[n - 1];

    uint32_t sbase = (uint32_t)__cvta_generic_to_shared(sm);

    // ---- Q tile -> smem -> fragments (raw bits; already tf32-rounded) ----
    const float* qbase = qkv + ((size_t)b * Sseq + n * BSb) * QKV_LD + h * DHd;
    for (int i = tid; i < 64 * 16; i += 128) {
        int rr = i >> 4, c4 = (i & 15) * 4;
        *(float4*)&Ps[rr * PLD + c4] = *(const float4*)&qbase[(size_t)rr * QKV_LD + c4];
    }
    __syncthreads();
    uint32_t aq[8][4];
    #pragma unroll
    for (int kt = 0; kt < 8; kt++) {
        const uint32_t* p = (const uint32_t*)Ps + (w * 16 + lr) * PLD + kt * 8 + lc;
        aq[kt][0] = p[0];
        aq[kt][1] = p[8 * PLD];
        aq[kt][2] = p[4];
        aq[kt][3] = p[8 * PLD + 4];
    }
    __syncthreads();

    float accO[8][4];
    #pragma unroll
    for (int nt = 0; nt < 8; nt++)
        #pragma unroll
        for (int r = 0; r < 4; r++) accO[nt][r] = 0.0f;
    float m0 = -1e30f, m1 = -1e30f, l0 = 0.0f, l1 = 0.0f;

    {
        const int kb = isg ? 0 : idxTab[(n - 1) * 8];
        const float* base = qkv + ((size_t)b * Sseq + kb * BSb) * QKV_LD + h * DHd;
        att_load_kv(sbase, tid, 0, base + 512, base + 1024);
    }

    for (int it = 0; it < nkb; it++) {
        const int st = it & 1;
        if (it + 1 < nkb) {
            const int kb = isg ? (it + 1) : idxTab[(n - 1) * 8 + it + 1];
            const float* base = qkv + ((size_t)b * Sseq + kb * BSb) * QKV_LD + h * DHd;
            att_load_kv(sbase, tid, st ^ 1, base + 512, base + 1024);
            asm volatile("cp.async.wait_group 1;" ::: "memory");
        } else {
            asm volatile("cp.async.wait_group 0;" ::: "memory");
        }
        __syncthreads();

        // ---- S = Q · K^T ----
        float s[8][4];
        #pragma unroll
        for (int nt = 0; nt < 8; nt++)
            #pragma unroll
            for (int r = 0; r < 4; r++) s[nt][r] = 0.0f;

        const uint32_t* Kst = (const uint32_t*)(Ks + st * 64 * KLD);
        #pragma unroll
        for (int kt = 0; kt < 8; kt++) {
            #pragma unroll
            for (int nt = 0; nt < 8; nt++) {
                const uint32_t* pb = Kst + (nt * 8 + lr) * KLD + kt * 8 + lc;
                mma_tf32(s[nt], aq[kt], pb[0], pb[4]);
            }
        }

        // ---- streaming softmax ----
        float mx0 = -1e30f, mx1 = -1e30f;
        #pragma unroll
        for (int nt = 0; nt < 8; nt++) {
            mx0 = fmaxf(mx0, fmaxf(s[nt][0], s[nt][1]));
            mx1 = fmaxf(mx1, fmaxf(s[nt][2], s[nt][3]));
        }
        mx0 = fmaxf(mx0, __shfl_xor_sync(0xffffffffu, mx0, 1));
        mx0 = fmaxf(mx0, __shfl_xor_sync(0xffffffffu, mx0, 2));
        mx1 = fmaxf(mx1, __shfl_xor_sync(0xffffffffu, mx1, 1));
        mx1 = fmaxf(mx1, __shfl_xor_sync(0xffffffffu, mx1, 2));
        const float mn0 = fmaxf(m0, mx0), mn1 = fmaxf(m1, mx1);
        const float cor0 = __expf(m0 - mn0), cor1 = __expf(m1 - mn1);
        float ps0 = 0.0f, ps1 = 0.0f;
        #pragma unroll
        for (int nt = 0; nt < 8; nt++) {
            s[nt][0] = __expf(s[nt][0] - mn0);
            s[nt][1] = __expf(s[nt][1] - mn0);
            s[nt][2] = __expf(s[nt][2] - mn1);
            s[nt][3] = __expf(s[nt][3] - mn1);
            ps0 += s[nt][0] + s[nt][1];
            ps1 += s[nt][2] + s[nt][3];
        }
        ps0 += __shfl_xor_sync(0xffffffffu, ps0, 1);
        ps0 += __shfl_xor_sync(0xffffffffu, ps0, 2);
        ps1 += __shfl_xor_sync(0xffffffffu, ps1, 1);
        ps1 += __shfl_xor_sync(0xffffffffu, ps1, 2);
        l0 = l0 * cor0 + ps0;
        l1 = l1 * cor1 + ps1;
        m0 = mn0; m1 = mn1;
        #pragma unroll
        for (int nt = 0; nt < 8; nt++) {
            accO[nt][0] *= cor0; accO[nt][1] *= cor0;
            accO[nt][2] *= cor1; accO[nt][3] *= cor1;
        }

        // ---- P -> per-warp smem (rounded once at write) ----
        float* pw = Ps + (w * 16 + lr) * PLD;
        #pragma unroll
        for (int nt = 0; nt < 8; nt++) {
            *(float2*)&pw[nt * 8 + 2 * lc]           = make_float2(rf(s[nt][0]), rf(s[nt][1]));
            *(float2*)&pw[8 * PLD + nt * 8 + 2 * lc] = make_float2(rf(s[nt][2]), rf(s[nt][3]));
        }
        __syncwarp();

        // ---- O += P · V ----
        const uint32_t* Vst = (const uint32_t*)(Vs + st * 64 * VLD);
        #pragma unroll
        for (int kt = 0; kt < 8; kt++) {
            const uint32_t* pp = (const uint32_t*)Ps + (w * 16 + lr) * PLD + kt * 8 + lc;
            uint32_t ap[4];
            ap[0] = pp[0];
            ap[1] = pp[8 * PLD];
            ap[2] = pp[4];
            ap[3] = pp[8 * PLD + 4];
            #pragma unroll
            for (int nt = 0; nt < 8; nt++) {
                const uint32_t* pv = Vst + (kt * 8 + lc) * VLD + nt * 8 + lr;
                mma_tf32(accO[nt], ap, pv[0], pv[4 * VLD]);
            }
        }
        __syncthreads();
    }

    // ---- finalize & store (rounded: o feeds WO GEMM) ----
    const float inv0 = 1.0f / l0, inv1 = 1.0f / l1;
    float* ob = o + ((size_t)b * Sseq + n * BSb + w * 16 + lr) * Dmod + h * DHd;
    #pragma unroll
    for (int nt = 0; nt < 8; nt++) {
        *(float2*)&ob[nt * 8 + 2 * lc] =
            make_float2(rf(accO[nt][0] * inv0), rf(accO[nt][1] * inv0));
        *(float2*)&ob[(size_t)8 * Dmod + nt * 8 + 2 * lc] =
            make_float2(rf(accO[nt][2] * inv1), rf(accO[nt][3] * inv1));
    }
}

// ---------------- launcher ----------------
extern "C" void kernel_launch(void* const* d_in, const int* in_sizes, int n_in,
                              void* d_out, int out_size) {
    const float* inputs = (const float*)d_in[0];
    const float* ln1_s  = (const float*)d_in[1];
    const float* ln1_b  = (const float*)d_in[2];
    const float* wq     = (const float*)d_in[3];
    const float* wk     = (const float*)d_in[4];
    const float* wv     = (const float*)d_in[5];
    const float* wo     = (const float*)d_in[6];
    const float* ln2_s  = (const float*)d_in[7];
    const float* ln2_b  = (const float*)d_in[8];
    const float* w1     = (const float*)d_in[9];
    const float* b1     = (const float*)d_in[10];
    const float* w2     = (const float*)d_in[11];
    const float* b2     = (const float*)d_in[12];
    float* out = (float*)d_out;

    float *xn, *qkv, *o, *yn, *hb, *wqkv, *wor, *w1r, *w2r;
    int *idx, *cnt;
    cudaGetSymbolAddress((void**)&xn,   g_xn);
    cudaGetSymbolAddress((void**)&qkv,  g_qkv);
    cudaGetSymbolAddress((void**)&o,    g_o);
    cudaGetSymbolAddress((void**)&yn,   g_yn);
    cudaGetSymbolAddress((void**)&hb,   g_hb);
    cudaGetSymbolAddress((void**)&wqkv, g_wqkv);
    cudaGetSymbolAddress((void**)&wor,  g_wor);
    cudaGetSymbolAddress((void**)&w1r,  g_w1r);
    cudaGetSymbolAddress((void**)&w2r,  g_w2r);
    cudaGetSymbolAddress((void**)&idx,  g_idx);
    cudaGetSymbolAddress((void**)&cnt,  g_cnt);

    cudaFuncSetAttribute(attn_tc, cudaFuncAttributeMaxDynamicSharedMemorySize, ATT_SMEM);
    cudaFuncSetAttribute(sgemm_tc<0, true>,  cudaFuncAttributeMaxDynamicSharedMemorySize, GEMM_SMEM);
    cudaFuncSetAttribute(sgemm_tc<1, true>,  cudaFuncAttributeMaxDynamicSharedMemorySize, GEMM_SMEM);
    cudaFuncSetAttribute(sgemm_tc<2, false>, cudaFuncAttributeMaxDynamicSharedMemorySize, GEMM_SMEM);
    cudaFuncSetAttribute(sgemm_tc<3, false>, cudaFuncAttributeMaxDynamicSharedMemorySize, GEMM_SMEM);

    // 0. BigBird block index table (host-computed, input-independent)
    static int h_idx[NROWS * 8];
    static int h_cnt[NROWS];
    h_make_table(h_idx, h_cnt);
    cudaMemcpyAsync(idx, h_idx, sizeof(h_idx), cudaMemcpyHostToDevice, 0);
    cudaMemcpyAsync(cnt, h_cnt, sizeof(h_cnt), cudaMemcpyHostToDevice, 0);

    // 1. round + pack weights to tf32 (identity w.r.t. prior numerics)
    round_pack<<<3072, 256>>>(wq, wk, wv, wo, w1, w2, wqkv, wor, w1r, w2r);

    // 2. LN1 (rounded output: feeds GEMM A)
    ln_kernel<true><<<NTOK, 128>>>(inputs, ln1_s, ln1_b, xn);

    // 3. QKV: single GEMM, N=1536 packed; alpha=0.125 on q columns only
    dim3 gqkv(QKV_LD / 128, NTOK / 128);
    sgemm_tc<0, true><<<gqkv, 256, GEMM_SMEM>>>(xn, wqkv, qkv, QKV_LD, Dmod, 0.125f, nullptr, nullptr);

    // 4. tensor-core flash attention (reads packed qkv)
    attn_tc<<<dim3(NBb, Hh, Bsz), 128, ATT_SMEM>>>(qkv, o, idx, cnt);

    // 5. output projection + residual (exact fp32 out)
    dim3 g512(Dmod / 128, NTOK / 128);
    sgemm_tc<2, false><<<g512, 256, GEMM_SMEM>>>(o, wor, out, Dmod, Dmod, 1.0f, nullptr, inputs);

    // 6. LN2 (rounded output)
    ln_kernel<true><<<NTOK, 128>>>(out, ln2_s, ln2_b, yn);

    // 7. FFN1: gelu(yn @ w1 + b1), rounded (feeds FFN2 A)
    dim3 g2048(Mff / 128, NTOK / 128);
    sgemm_tc<1, true><<<g2048, 256, GEMM_SMEM>>>(yn, w1r, hb, Mff, Dmod, 1.0f, b1, nullptr);

    // 8. FFN2 + bias + residual (exact fp32 out)
    sgemm_tc<3, false><<<g512, 256, GEMM_SMEM>>>(hb, w2r, out, Dmod, Mff, 1.0f, b2, out);
}

// round 5
// speedup vs baseline: 8.1004x; 1.1664x over previous
#include <cuda_runtime.h>
#include <math.h>
#include <stdint.h>

// ---------------- problem constants ----------------
#define Bsz   4
#define Sseq  4096
#define Dmod  512
#define Hh    8
#define DHd   64
#define Mff   2048
#define BSb   64
#define NBb   64
#define NROWS (NBb - 2)
#define NTOK  (Bsz * Sseq)        // 16384
#define QKV_LD 1536

// ---------------- scratch (device globals; no allocation) ----------------
__device__ float g_xn  [(size_t)NTOK * Dmod];
__device__ float g_qkv [(size_t)NTOK * QKV_LD];
__device__ float g_o   [(size_t)NTOK * Dmod];
__device__ float g_yn  [(size_t)NTOK * Dmod];
__device__ float g_hb  [(size_t)NTOK * Mff];
__device__ float g_wqkv[(size_t)QKV_LD * Dmod];   // transposed [n][k], rounded
__device__ float g_wor [(size_t)Dmod * Dmod];     // transposed
__device__ float g_w1r [(size_t)Mff * Dmod];      // transposed
__device__ float g_w2r [(size_t)Dmod * Mff];      // transposed
__device__ float g_po  [(size_t)512 * 64 * 64];   // global-split partial acc
__device__ float g_pm  [512 * 64];
__device__ float g_pl  [512 * 64];
__device__ int   g_idx[NROWS * 8];
__device__ int   g_cnt[NROWS];

// ---------------- host-side numpy-legacy MT19937 ----------------
struct HostMT { unsigned int k[624]; int pos; };
static void h_mt_seed(HostMT& st, unsigned int seed) {
    for (int p = 0; p < 624; p++) {
        st.k[p] = seed;
        seed = 1812433253u * (seed ^ (seed >> 30)) + (unsigned)p + 1u;
    }
    st.pos = 624;
}
static unsigned int h_mt_next(HostMT& st) {
    if (st.pos == 624) {
        for (int i = 0; i < 624; i++) {
            unsigned int y = (st.k[i] & 0x80000000u) | (st.k[(i + 1) % 624] & 0x7fffffffu);
            st.k[i] = st.k[(i + 397) % 624] ^ (y >> 1) ^ ((y & 1u) ? 0x9908b0dfu : 0u);
        }
        st.pos = 0;
    }
    unsigned int y = st.k[st.pos++];
    y ^= y >> 11;
    y ^= (y << 7)  & 0x9d2c5680u;
    y ^= (y << 15) & 0xefc60000u;
    y ^= y >> 18;
    return y;
}
static unsigned int h_mt_interval(HostMT& st, unsigned int mx) {
    if (mx == 0u) return 0u;
    unsigned int mask = mx;
    mask |= mask >> 1; mask |= mask >> 2; mask |= mask >> 4;
    mask |= mask >> 8; mask |= mask >> 16;
    unsigned int v;
    do { v = h_mt_next(st) & mask; } while (v > mx);
    return v;
}
static void h_make_table(int* h_idx, int* h_cnt) {
    HostMT st;
    h_mt_seed(st, 0u);
    for (int i = 1; i <= NBb - 2; i++) {
        bool fx[NBb];
        for (int z = 0; z < NBb; z++) fx[z] = false;
        fx[0] = true; fx[NBb - 1] = true;
        fx[i - 1] = true; fx[i] = true; fx[i + 1] = true;
        int fixed[8], nf = 0;
        int allowed[NBb], na = 0;
        for (int bb = 0; bb < NBb; bb++) {
            if (fx[bb]) fixed[nf++] = bb;
            else        allowed[na++] = bb;
        }
        int perm[NBb];
        for (int t = 0; t < na; t++) perm[t] = t;
        for (int t = na - 1; t >= 1; t--) {
            int j = (int)h_mt_interval(st, (unsigned)t);
            int tmp = perm[t]; perm[t] = perm[j]; perm[j] = tmp;
        }
        int row = i - 1;
        int cnt = 0;
        for (int s = 0; s < nf; s++) h_idx[row * 8 + cnt++] = fixed[s];
        for (int r3 = 0; r3 < 3; r3++) h_idx[row * 8 + cnt++] = allowed[perm[r3]];
        h_cnt[row] = cnt;
        for (; cnt < 8; cnt++) h_idx[row * 8 + cnt] = 0;
    }
}

// ---------------- helpers ----------------
__device__ __forceinline__ uint32_t f2tf(float x) {
    uint32_t r;
    asm("cvt.rna.tf32.f32 %0, %1;" : "=r"(r) : "f"(x));
    return r;
}
__device__ __forceinline__ float rf(float x) { return __uint_as_float(f2tf(x)); }
__device__ __forceinline__ float gelu_tanh(float x) {
    const float c = 0.7978845608028654f;
    float x3 = x * x * x;
    return 0.5f * x * (1.0f + tanhf(c * (x + 0.044715f * x3)));
}
__device__ __forceinline__ void cpasync16(uint32_t saddr, const void* gaddr) {
    asm volatile("cp.async.cg.shared.global [%0], [%1], 16;" :: "r"(saddr), "l"(gaddr) : "memory");
}
__device__ __forceinline__ void mma_tf32(float* c, const uint32_t* a, uint32_t b0, uint32_t b1) {
    asm volatile(
        "mma.sync.aligned.m16n8k8.row.col.f32.tf32.tf32.f32 "
        "{%0,%1,%2,%3}, {%4,%5,%6,%7}, {%8,%9}, {%0,%1,%2,%3};"
        : "+f"(c[0]), "+f"(c[1]), "+f"(c[2]), "+f"(c[3])
        : "r"(a[0]), "r"(a[1]), "r"(a[2]), "r"(a[3]), "r"(b0), "r"(b1));
}
// ldmatrix x4 on 32-bit data: tile = 8 rows x 4 tf32; thread t -> (row t/4, col t%4)
__device__ __forceinline__ void ldsm4(uint32_t* r, uint32_t saddr) {
    asm volatile("ldmatrix.sync.aligned.m8n8.x4.shared.b16 {%0,%1,%2,%3}, [%4];"
                 : "=r"(r[0]), "=r"(r[1]), "=r"(r[2]), "=r"(r[3]) : "r"(saddr));
}

// ---------------- transpose + tf32-round weights: src[R][C] -> dst[C][R] ----------------
__global__ void __launch_bounds__(256)
transpose_round(const float* __restrict__ src, float* __restrict__ dst, int R, int C) {
    __shared__ float t[32][33];
    const int c0 = blockIdx.x * 32, r0 = blockIdx.y * 32;
    const int tx = threadIdx.x & 31, ty = threadIdx.x >> 5;
    #pragma unroll
    for (int j = 0; j < 4; j++)
        t[ty + j * 8][tx] = rf(src[(size_t)(r0 + ty + j * 8) * C + c0 + tx]);
    __syncthreads();
    #pragma unroll
    for (int j = 0; j < 4; j++)
        dst[(size_t)(c0 + ty + j * 8) * R + r0 + tx] = t[tx][ty + j * 8];
}

// ---------------- LayerNorm ----------------
template <bool RND>
__global__ void ln_kernel(const float* __restrict__ x, const float* __restrict__ g,
                          const float* __restrict__ bta, float* __restrict__ y) {
    __shared__ float red[2][4];
    const int row = blockIdx.x;
    const int t = threadIdx.x;
    const float* xr = x + (size_t)row * Dmod;
    float4 xv = ((const float4*)xr)[t];
    float s  = xv.x + xv.y + xv.z + xv.w;
    float q2 = xv.x * xv.x + xv.y * xv.y + xv.z * xv.z + xv.w * xv.w;
    #pragma unroll
    for (int o = 16; o; o >>= 1) {
        s  += __shfl_xor_sync(0xffffffffu, s,  o);
        q2 += __shfl_xor_sync(0xffffffffu, q2, o);
    }
    if ((t & 31) == 0) { red[0][t >> 5] = s; red[1][t >> 5] = q2; }
    __syncthreads();
    s  = red[0][0] + red[0][1] + red[0][2] + red[0][3];
    q2 = red[1][0] + red[1][1] + red[1][2] + red[1][3];
    const float mu   = s * (1.0f / Dmod);
    const float var  = q2 * (1.0f / Dmod) - mu * mu;
    const float rstd = rsqrtf(var + 1e-6f);
    float4 gv = ((const float4*)g)[t];
    float4 bv = ((const float4*)bta)[t];
    float4 ov;
    ov.x = (xv.x - mu) * rstd * gv.x + bv.x;
    ov.y = (xv.y - mu) * rstd * gv.y + bv.y;
    ov.z = (xv.z - mu) * rstd * gv.z + bv.z;
    ov.w = (xv.w - mu) * rstd * gv.w + bv.w;
    if (RND) { ov.x = rf(ov.x); ov.y = rf(ov.y); ov.z = rf(ov.z); ov.w = rf(ov.w); }
    ((float4*)(y + (size_t)row * Dmod))[t] = ov;
}

// ---------------- TF32 TC SGEMM: A[m][k], Bt[n][k] (pre-transposed), LDSM frags ----------------
#define G_LD   36
#define G_TILE (128 * G_LD)                 // 4608 floats per buffer
#define GEMM_SMEM (4 * G_TILE * 4)          // A dbuf + B dbuf = 73728 B

// EPI: 0 = qkv (alpha on cols<512, round) ; 1 = gelu(acc+bias) ; 2 = acc+res ; 3 = acc+bias+res
template <int EPI, bool RND>
__global__ void __launch_bounds__(256, 2)
sgemm_tc(const float* __restrict__ A, const float* __restrict__ Bt,
         float* __restrict__ C, int N, int K, float alpha,
         const float* __restrict__ bias, const float* __restrict__ res) {
    extern __shared__ float sm[];
    const int tid  = threadIdx.x;
    const int bm   = blockIdx.y * 128;
    const int bn   = blockIdx.x * 128;
    const int lane = tid & 31;
    const int wid  = tid >> 5;
    const int wm   = wid & 1;
    const int wn   = wid >> 1;
    const int lr   = lane >> 2;
    const int lc   = lane & 3;
    const int tile = lane >> 3;     // ldmatrix tile id
    const int t7   = lane & 7;

    uint32_t sbase = (uint32_t)__cvta_generic_to_shared(sm);
    uint32_t sA = sbase;                        // [2][128][G_LD]
    uint32_t sB = sbase + 2 * G_TILE * 4;       // [2][128][G_LD]

    float acc[4][4][4];
    #pragma unroll
    for (int mt = 0; mt < 4; mt++)
        #pragma unroll
        for (int nt = 0; nt < 4; nt++)
            #pragma unroll
            for (int r = 0; r < 4; r++) acc[mt][nt][r] = 0.0f;

    const int nk = K >> 5;

    // identical load shape for A and Bt: 128 rows x 32 floats, row stride K
    const int ldrow = tid >> 3, ldk4 = (tid & 7) * 4;
    {
        const float* Ag = A  + (size_t)(bm + ldrow) * K + ldk4;
        const float* Bg = Bt + (size_t)(bn + ldrow) * K + ldk4;
        #pragma unroll
        for (int i = 0; i < 4; i++) {
            cpasync16(sA + (uint32_t)(((ldrow + 32 * i) * G_LD + ldk4) * 4), Ag + (size_t)(32 * i) * K);
            cpasync16(sB + (uint32_t)(((ldrow + 32 * i) * G_LD + ldk4) * 4), Bg + (size_t)(32 * i) * K);
        }
        asm volatile("cp.async.commit_group;" ::: "memory");
    }

    for (int t = 0; t < nk; t++) {
        const int cur = t & 1;
        if (t + 1 < nk) {
            const int nb = (t + 1) & 1;
            const float* Ag = A  + (size_t)(bm + ldrow) * K + (t + 1) * 32 + ldk4;
            const float* Bg = Bt + (size_t)(bn + ldrow) * K + (t + 1) * 32 + ldk4;
            #pragma unroll
            for (int i = 0; i < 4; i++) {
                cpasync16(sA + (uint32_t)((nb * G_TILE + (ldrow + 32 * i) * G_LD + ldk4) * 4),
                          Ag + (size_t)(32 * i) * K);
                cpasync16(sB + (uint32_t)((nb * G_TILE + (ldrow + 32 * i) * G_LD + ldk4) * 4),
                          Bg + (size_t)(32 * i) * K);
            }
            asm volatile("cp.async.commit_group;" ::: "memory");
            asm volatile("cp.async.wait_group 1;" ::: "memory");
        } else {
            asm volatile("cp.async.wait_group 0;" ::: "memory");
        }
        __syncthreads();

        const uint32_t sAc = sA + (uint32_t)(cur * G_TILE * 4);
        const uint32_t sBc = sB + (uint32_t)(cur * G_TILE * 4);

        #pragma unroll
        for (int ks = 0; ks < 4; ks++) {
            const int k0 = ks * 8;
            uint32_t af[4][4], bf[2][4];
            // A frags: r0=a0 r1=a1 r2=a2 r3=a3
            const int aRow = wm * 64 + (tile & 1) * 8 + t7;
            const int aCol = k0 + (tile >> 1) * 4;
            #pragma unroll
            for (int mt = 0; mt < 4; mt++)
                ldsm4(af[mt], sAc + (uint32_t)(((aRow + mt * 16) * G_LD + aCol) * 4));
            // B frags: r0=b0(even nt) r1=b1(even) r2=b0(odd) r3=b1(odd)
            const int bRow = wn * 32 + (tile >> 1) * 8 + t7;
            const int bCol = k0 + (tile & 1) * 4;
            #pragma unroll
            for (int ntp = 0; ntp < 2; ntp++)
                ldsm4(bf[ntp], sBc + (uint32_t)(((bRow + ntp * 16) * G_LD + bCol) * 4));
            #pragma unroll
            for (int mt = 0; mt < 4; mt++) {
                mma_tf32(acc[mt][0], af[mt], bf[0][0], bf[0][1]);
                mma_tf32(acc[mt][1], af[mt], bf[0][2], bf[0][3]);
                mma_tf32(acc[mt][2], af[mt], bf[1][0], bf[1][1]);
                mma_tf32(acc[mt][3], af[mt], bf[1][2], bf[1][3]);
            }
        }
        __syncthreads();
    }

    const float a_eff = (EPI == 0) ? ((bn < 512) ? alpha : 1.0f) : alpha;

    #pragma unroll
    for (int mt = 0; mt < 4; mt++) {
        const int row0 = bm + wm * 64 + mt * 16 + lr;
        #pragma unroll
        for (int half = 0; half < 2; half++) {
            const int row = row0 + half * 8;
            #pragma unroll
            for (int nt = 0; nt < 4; nt++) {
                const int col = bn + wn * 32 + nt * 8 + lc * 2;
                float v0 = acc[mt][nt][half * 2 + 0];
                float v1 = acc[mt][nt][half * 2 + 1];
                const size_t off = (size_t)row * N + col;
                if (EPI == 0) { v0 *= a_eff; v1 *= a_eff; }
                if (EPI == 1) {
                    v0 = gelu_tanh(v0 + bias[col]);
                    v1 = gelu_tanh(v1 + bias[col + 1]);
                }
                if (EPI == 2) { v0 += res[off]; v1 += res[off + 1]; }
                if (EPI == 3) {
                    v0 += bias[col] + res[off];
                    v1 += bias[col + 1] + res[off + 1];
                }
                if (RND) { v0 = rf(v0); v1 = rf(v1); }
                *(float2*)&C[off] = make_float2(v0, v1);
            }
        }
    }
}

// ---------------- flash BigBird attention: 32-row kv subtiles, split-KV globals ----------------
#define AKLD 68
#define AVLD 72
#define APLD 36
#define A_KOFF 0
#define A_VOFF (2 * 32 * AKLD)              // 4352
#define A_POFF (A_VOFF + 2 * 32 * AVLD)     // 8960
#define ATT_SMEM ((A_POFF + 64 * APLD) * 4) // 45056 B -> 5 CTAs/SM

__device__ __forceinline__ void att_load_sub(uint32_t sbase, int tid, int stage,
                                             const float* kb_g, const float* vb_g) {
    const int row = tid >> 4, c4 = (tid & 15) * 4;
    #pragma unroll
    for (int i = 0; i < 4; i++) {
        cpasync16(sbase + (uint32_t)((A_KOFF + stage * 32 * AKLD + (row + 8 * i) * AKLD + c4) * 4),
                  kb_g + (size_t)(row + 8 * i) * QKV_LD + c4);
        cpasync16(sbase + (uint32_t)((A_VOFF + stage * 32 * AVLD + (row + 8 * i) * AVLD + c4) * 4),
                  vb_g + (size_t)(row + 8 * i) * QKV_LD + c4);
    }
    asm volatile("cp.async.commit_group;" ::: "memory");
}

__global__ void __launch_bounds__(128)
attn_tc(const float* __restrict__ qkv, float* __restrict__ o,
        float* __restrict__ po, float* __restrict__ pm, float* __restrict__ pl,
        const int* __restrict__ idxTab, const int* __restrict__ cntTab) {
    extern __shared__ float sm[];
    const int bx = blockIdx.x, h = blockIdx.y, b = blockIdx.z;
    const int tid = threadIdx.x;
    const int lane = tid & 31, w = tid >> 5;
    const int lr = lane >> 2, lc = lane & 3;
    const int tile = lane >> 3, t7 = lane & 7;

    const bool isg = (bx < 16);
    int n, split = 0, nsub;
    if (isg) { split = bx & 7; n = (bx >> 3) ? (NBb - 1) : 0; nsub = 16; }
    else     { n = bx - 15; nsub = 2 * cntTab[n - 1]; }

    uint32_t sbase = (uint32_t)__cvta_generic_to_shared(sm);

    // ---- Q: stage through K region, fragment via LDSM, keep in regs ----
    const float* qbase = qkv + (size_t)(b * Sseq + n * BSb) * QKV_LD + h * DHd;
    for (int i = tid; i < 1024; i += 128) {
        int rr = i >> 4, c4 = (i & 15) << 2;
        *(float4*)&sm[rr * AKLD + c4] = *(const float4*)&qbase[(size_t)rr * QKV_LD + c4];
    }
    __syncthreads();
    uint32_t aq[8][4];
    {
        const int qRow = w * 16 + (tile & 1) * 8 + t7;
        #pragma unroll
        for (int kt = 0; kt < 8; kt++)
            ldsm4(aq[kt], sbase + (uint32_t)((qRow * AKLD + kt * 8 + (tile >> 1) * 4) * 4));
    }
    __syncthreads();

    float accO[8][4];
    #pragma unroll
    for (int nt = 0; nt < 8; nt++)
        #pragma unroll
        for (int r = 0; r < 4; r++) accO[nt][r] = 0.0f;
    float m0 = -1e30f, m1 = -1e30f, l0 = 0.0f, l1 = 0.0f;

    // prologue
    {
        const int blk = isg ? split * 8 : idxTab[(n - 1) * 8];
        const float* base = qkv + (size_t)(b * Sseq + blk * BSb) * QKV_LD + h * DHd;
        att_load_sub(sbase, tid, 0, base + 512, base + 1024);
    }

    for (int it = 0; it < nsub; it++) {
        const int st = it & 1;
        if (it + 1 < nsub) {
            const int i2 = it + 1;
            const int blk = isg ? (split * 8 + (i2 >> 1)) : idxTab[(n - 1) * 8 + (i2 >> 1)];
            const float* base = qkv + (size_t)(b * Sseq + blk * BSb + (i2 & 1) * 32) * QKV_LD + h * DHd;
            att_load_sub(sbase, tid, st ^ 1, base + 512, base + 1024);
            asm volatile("cp.async.wait_group 1;" ::: "memory");
        } else {
            asm volatile("cp.async.wait_group 0;" ::: "memory");
        }
        __syncthreads();

        // ---- S = Q K^T (16 x 32 per warp) ----
        float s[4][4];
        #pragma unroll
        for (int nt = 0; nt < 4; nt++)
            #pragma unroll
            for (int r = 0; r < 4; r++) s[nt][r] = 0.0f;

        const uint32_t kB = sbase + (uint32_t)((A_KOFF + st * 32 * AKLD) * 4);
        const int kRow = (tile >> 1) * 8 + t7;
        const int kCol = (tile & 1) * 4;
        #pragma unroll
        for (int kt = 0; kt < 8; kt++) {
            uint32_t bf[2][4];
            #pragma unroll
            for (int ntp = 0; ntp < 2; ntp++)
                ldsm4(bf[ntp], kB + (uint32_t)(((ntp * 16 + kRow) * AKLD + kt * 8 + kCol) * 4));
            mma_tf32(s[0], aq[kt], bf[0][0], bf[0][1]);
            mma_tf32(s[1], aq[kt], bf[0][2], bf[0][3]);
            mma_tf32(s[2], aq[kt], bf[1][0], bf[1][1]);
            mma_tf32(s[3], aq[kt], bf[1][2], bf[1][3]);
        }

        // ---- streaming softmax (rows lr / lr+8) ----
        float mx0 = fmaxf(fmaxf(s[0][0], s[0][1]), fmaxf(s[1][0], s[1][1]));
        float mx1 = fmaxf(fmaxf(s[0][2], s[0][3]), fmaxf(s[1][2], s[1][3]));
        mx0 = fmaxf(mx0, fmaxf(fmaxf(s[2][0], s[2][1]), fmaxf(s[3][0], s[3][1])));
        mx1 = fmaxf(mx1, fmaxf(fmaxf(s[2][2], s[2][3]), fmaxf(s[3][2], s[3][3])));
        mx0 = fmaxf(mx0, __shfl_xor_sync(0xffffffffu, mx0, 1));
        mx0 = fmaxf(mx0, __shfl_xor_sync(0xffffffffu, mx0, 2));
        mx1 = fmaxf(mx1, __shfl_xor_sync(0xffffffffu, mx1, 1));
        mx1 = fmaxf(mx1, __shfl_xor_sync(0xffffffffu, mx1, 2));
        const float mn0 = fmaxf(m0, mx0), mn1 = fmaxf(m1, mx1);
        const float cor0 = __expf(m0 - mn0), cor1 = __expf(m1 - mn1);
        float ps0 = 0.0f, ps1 = 0.0f;
        #pragma unroll
        for (int nt = 0; nt < 4; nt++) {
            s[nt][0] = __expf(s[nt][0] - mn0);
            s[nt][1] = __expf(s[nt][1] - mn0);
            s[nt][2] = __expf(s[nt][2] - mn1);
            s[nt][3] = __expf(s[nt][3] - mn1);
            ps0 += s[nt][0] + s[nt][1];
            ps1 += s[nt][2] + s[nt][3];
        }
        ps0 += __shfl_xor_sync(0xffffffffu, ps0, 1);
        ps0 += __shfl_xor_sync(0xffffffffu, ps0, 2);
        ps1 += __shfl_xor_sync(0xffffffffu, ps1, 1);
        ps1 += __shfl_xor_sync(0xffffffffu, ps1, 2);
        l0 = l0 * cor0 + ps0;
        l1 = l1 * cor1 + ps1;
        m0 = mn0; m1 = mn1;
        #pragma unroll
        for (int nt = 0; nt < 8; nt++) {
            accO[nt][0] *= cor0; accO[nt][1] *= cor0;
            accO[nt][2] *= cor1; accO[nt][3] *= cor1;
        }

        // ---- P -> per-warp smem (rounded) ----
        float* pw = sm + A_POFF + (w * 16 + lr) * APLD;
        #pragma unroll
        for (int nt = 0; nt < 4; nt++) {
            *(float2*)&pw[nt * 8 + 2 * lc]            = make_float2(rf(s[nt][0]), rf(s[nt][1]));
            *(float2*)&pw[8 * APLD + nt * 8 + 2 * lc] = make_float2(rf(s[nt][2]), rf(s[nt][3]));
        }
        __syncwarp();

        // ---- O += P V (16 x 64 per warp) ----
        const uint32_t pB = sbase + (uint32_t)(A_POFF * 4);
        const int pRow = w * 16 + (tile & 1) * 8 + t7;
        const int pCol = (tile >> 1) * 4;
        const uint32_t* Vst = (const uint32_t*)(sm + A_VOFF + st * 32 * AVLD);
        #pragma unroll
        for (int kt = 0; kt < 4; kt++) {
            uint32_t ap[4];
            ldsm4(ap, pB + (uint32_t)((pRow * APLD + kt * 8 + pCol) * 4));
            #pragma unroll
            for (int nt = 0; nt < 8; nt++) {
                const uint32_t* pv = Vst + (kt * 8 + lc) * AVLD + nt * 8 + lr;
                mma_tf32(accO[nt], ap, pv[0], pv[4 * AVLD]);
            }
        }
        __syncthreads();
    }

    if (!isg) {
        const float inv0 = 1.0f / l0, inv1 = 1.0f / l1;
        float* ob = o + (size_t)(b * Sseq + n * BSb + w * 16 + lr) * Dmod + h * DHd;
        #pragma unroll
        for (int nt = 0; nt < 8; nt++) {
            *(float2*)&ob[nt * 8 + 2 * lc] =
                make_float2(rf(accO[nt][0] * inv0), rf(accO[nt][1] * inv0));
            *(float2*)&ob[(size_t)8 * Dmod + nt * 8 + 2 * lc] =
                make_float2(rf(accO[nt][2] * inv1), rf(accO[nt][3] * inv1));
        }
    } else {
        const int g = n ? 1 : 0;
        const int pslot = ((b * 2 + g) * Hh + h) * 8 + split;
        if (lc == 0) {
            pm[pslot * 64 + w * 16 + lr]     = m0;
            pl[pslot * 64 + w * 16 + lr]     = l0;
            pm[pslot * 64 + w * 16 + 8 + lr] = m1;
            pl[pslot * 64 + w * 16 + 8 + lr] = l1;
        }
        float* pb = po + ((size_t)pslot * 64 + w * 16 + lr) * 64;
        #pragma unroll
        for (int nt = 0; nt < 8; nt++) {
            *(float2*)&pb[nt * 8 + 2 * lc]          = make_float2(accO[nt][0], accO[nt][1]);
            *(float2*)&pb[8 * 64 + nt * 8 + 2 * lc] = make_float2(accO[nt][2], accO[nt][3]);
        }
    }
}

// ---------------- combine global-split partials ----------------
__global__ void __launch_bounds__(256)
combine_kernel(const float* __restrict__ po, const float* __restrict__ pm,
               const float* __restrict__ pl, float* __restrict__ o) {
    const int group = blockIdx.x;             // (b*2+g)*8 + h, 0..63
    const int b = group >> 4, g = (group >> 3) & 1, h = group & 7;
    const int row = threadIdx.x >> 2;
    const int cseg = (threadIdx.x & 3) * 16;

    float mv[8], lv[8];
    float M = -1e30f;
    #pragma unroll
    for (int s = 0; s < 8; s++) {
        mv[s] = pm[(group * 8 + s) * 64 + row];
        lv[s] = pl[(group * 8 + s) * 64 + row];
        M = fmaxf(M, mv[s]);
    }
    float L = 0.0f, wgt[8];
    #pragma unroll
    for (int s = 0; s < 8; s++) {
        wgt[s] = __expf(mv[s] - M);
        L += lv[s] * wgt[s];
    }
    float acc[16];
    #pragma unroll
    for (int c = 0; c < 16; c++) acc[c] = 0.0f;
    #pragma unroll
    for (int s = 0; s < 8; s++) {
        const float* pr = po + ((size_t)(group * 8 + s) * 64 + row) * 64 + cseg;
        #pragma unroll
        for (int c4 = 0; c4 < 4; c4++) {
            float4 vv = *(const float4*)&pr[c4 * 4];
            acc[c4 * 4 + 0] += wgt[s] * vv.x;
            acc[c4 * 4 + 1] += wgt[s] * vv.y;
            acc[c4 * 4 + 2] += wgt[s] * vv.z;
            acc[c4 * 4 + 3] += wgt[s] * vv.w;
        }
    }
    const float inv = 1.0f / L;
    const int nblk = g ? (NBb - 1) : 0;
    float* ob = o + (size_t)(b * Sseq + nblk * BSb + row) * Dmod + h * DHd + cseg;
    #pragma unroll
    for (int c4 = 0; c4 < 4; c4++) {
        float4 ov;
        ov.x = rf(acc[c4 * 4 + 0] * inv);
        ov.y = rf(acc[c4 * 4 + 1] * inv);
        ov.z = rf(acc[c4 * 4 + 2] * inv);
        ov.w = rf(acc[c4 * 4 + 3] * inv);
        *(float4*)&ob[c4 * 4] = ov;
    }
}

// ---------------- launcher ----------------
extern "C" void kernel_launch(void* const* d_in, const int* in_sizes, int n_in,
                              void* d_out, int out_size) {
    const float* inputs = (const float*)d_in[0];
    const float* ln1_s  = (const float*)d_in[1];
    const float* ln1_b  = (const float*)d_in[2];
    const float* wq     = (const float*)d_in[3];
    const float* wk     = (const float*)d_in[4];
    const float* wv     = (const float*)d_in[5];
    const float* wo     = (const float*)d_in[6];
    const float* ln2_s  = (const float*)d_in[7];
    const float* ln2_b  = (const float*)d_in[8];
    const float* w1     = (const float*)d_in[9];
    const float* b1     = (const float*)d_in[10];
    const float* w2     = (const float*)d_in[11];
    const float* b2     = (const float*)d_in[12];
    float* out = (float*)d_out;

    float *xn, *qkv, *o, *yn, *hb, *wqkv, *wor, *w1r, *w2r, *po, *pmv, *plv;
    int *idx, *cnt;
    cudaGetSymbolAddress((void**)&xn,   g_xn);
    cudaGetSymbolAddress((void**)&qkv,  g_qkv);
    cudaGetSymbolAddress((void**)&o,    g_o);
    cudaGetSymbolAddress((void**)&yn,   g_yn);
    cudaGetSymbolAddress((void**)&hb,   g_hb);
    cudaGetSymbolAddress((void**)&wqkv, g_wqkv);
    cudaGetSymbolAddress((void**)&wor,  g_wor);
    cudaGetSymbolAddress((void**)&w1r,  g_w1r);
    cudaGetSymbolAddress((void**)&w2r,  g_w2r);
    cudaGetSymbolAddress((void**)&po,   g_po);
    cudaGetSymbolAddress((void**)&pmv,  g_pm);
    cudaGetSymbolAddress((void**)&plv,  g_pl);
    cudaGetSymbolAddress((void**)&idx,  g_idx);
    cudaGetSymbolAddress((void**)&cnt,  g_cnt);

    cudaFuncSetAttribute(sgemm_tc<0, true>,  cudaFuncAttributeMaxDynamicSharedMemorySize, GEMM_SMEM);
    cudaFuncSetAttribute(sgemm_tc<1, true>,  cudaFuncAttributeMaxDynamicSharedMemorySize, GEMM_SMEM);
    cudaFuncSetAttribute(sgemm_tc<2, false>, cudaFuncAttributeMaxDynamicSharedMemorySize, GEMM_SMEM);
    cudaFuncSetAttribute(sgemm_tc<3, false>, cudaFuncAttributeMaxDynamicSharedMemorySize, GEMM_SMEM);

    // 0. BigBird index table (host, input-independent)
    static int h_idx[NROWS * 8];
    static int h_cnt[NROWS];
    h_make_table(h_idx, h_cnt);
    cudaMemcpyAsync(idx, h_idx, sizeof(h_idx), cudaMemcpyHostToDevice, 0);
    cudaMemcpyAsync(cnt, h_cnt, sizeof(h_cnt), cudaMemcpyHostToDevice, 0);

    // 1. transpose + round weights: dst[n][k]
    transpose_round<<<dim3(16, 16), 256>>>(wq, wqkv,              Dmod, Dmod);
    transpose_round<<<dim3(16, 16), 256>>>(wk, wqkv + 512 * 512,  Dmod, Dmod);
    transpose_round<<<dim3(16, 16), 256>>>(wv, wqkv + 1024 * 512, Dmod, Dmod);
    transpose_round<<<dim3(16, 16), 256>>>(wo, wor,               Dmod, Dmod);
    transpose_round<<<dim3(64, 16), 256>>>(w1, w1r,               Dmod, Mff);
    transpose_round<<<dim3(16, 64), 256>>>(w2, w2r,               Mff, Dmod);

    // 2. LN1 (rounded)
    ln_kernel<true><<<NTOK, 128>>>(inputs, ln1_s, ln1_b, xn);

    // 3. QKV: single GEMM, N=1536 packed; alpha=0.125 on q columns
    dim3 gqkv(QKV_LD / 128, NTOK / 128);
    sgemm_tc<0, true><<<gqkv, 256, GEMM_SMEM>>>(xn, wqkv, qkv, QKV_LD, Dmod, 0.125f, nullptr, nullptr);

    // 4. attention: interiors + split-KV globals, then combine
    attn_tc<<<dim3(78, Hh, Bsz), 128, ATT_SMEM>>>(qkv, o, po, pmv, plv, idx, cnt);
    combine_kernel<<<64, 256>>>(po, pmv, plv, o);

    // 5. WO + residual (exact fp32)
    dim3 g512(Dmod / 128, NTOK / 128);
    sgemm_tc<2, false><<<g512, 256, GEMM_SMEM>>>(o, wor, out, Dmod, Dmod, 1.0f, nullptr, inputs);

    // 6. LN2 (rounded)
    ln_kernel<true><<<NTOK, 128>>>(out, ln2_s, ln2_b, yn);

    // 7. FFN1: gelu(yn @ w1 + b1), rounded
    dim3 g2048(Mff / 128, NTOK / 128);
    sgemm_tc<1, true><<<g2048, 256, GEMM_SMEM>>>(yn, w1r, hb, Mff, Dmod, 1.0f, b1, nullptr);

    // 8. FFN2 + bias + residual (exact fp32)
    sgemm_tc<3, false><<<g512, 256, GEMM_SMEM>>>(hb, w2r, out, Dmod, Mff, 1.0f, b2, out);
}

// round 6
// speedup vs baseline: 8.2522x; 1.0187x over previous
#include <cuda_runtime.h>
#include <math.h>
#include <stdint.h>

// ---------------- problem constants ----------------
#define Bsz   4
#define Sseq  4096
#define Dmod  512
#define Hh    8
#define DHd   64
#define Mff   2048
#define BSb   64
#define NBb   64
#define NROWS (NBb - 2)
#define NTOK  (Bsz * Sseq)        // 16384
#define QKV_LD 1536

// ---------------- scratch (device globals; no allocation) ----------------
__device__ float g_xn  [(size_t)NTOK * Dmod];
__device__ float g_qkv [(size_t)NTOK * QKV_LD];
__device__ float g_o   [(size_t)NTOK * Dmod];
__device__ float g_yn  [(size_t)NTOK * Dmod];
__device__ float g_hb  [(size_t)NTOK * Mff];
__device__ float g_wqkv[(size_t)QKV_LD * Dmod];   // transposed [n][k], rounded
__device__ float g_wor [(size_t)Dmod * Dmod];     // transposed
__device__ float g_w1r [(size_t)Mff * Dmod];      // transposed
__device__ float g_w2r [(size_t)Dmod * Mff];      // transposed
__device__ float g_po  [(size_t)512 * 64 * 64];   // global-split partial acc
__device__ float g_pm  [512 * 64];
__device__ float g_pl  [512 * 64];
__device__ int   g_idx[NROWS * 8];
__device__ int   g_cnt[NROWS];

// ---------------- host-side numpy-legacy MT19937 ----------------
struct HostMT { unsigned int k[624]; int pos; };
static void h_mt_seed(HostMT& st, unsigned int seed) {
    for (int p = 0; p < 624; p++) {
        st.k[p] = seed;
        seed = 1812433253u * (seed ^ (seed >> 30)) + (unsigned)p + 1u;
    }
    st.pos = 624;
}
static unsigned int h_mt_next(HostMT& st) {
    if (st.pos == 624) {
        for (int i = 0; i < 624; i++) {
            unsigned int y = (st.k[i] & 0x80000000u) | (st.k[(i + 1) % 624] & 0x7fffffffu);
            st.k[i] = st.k[(i + 397) % 624] ^ (y >> 1) ^ ((y & 1u) ? 0x9908b0dfu : 0u);
        }
        st.pos = 0;
    }
    unsigned int y = st.k[st.pos++];
    y ^= y >> 11;
    y ^= (y << 7)  & 0x9d2c5680u;
    y ^= (y << 15) & 0xefc60000u;
    y ^= y >> 18;
    return y;
}
static unsigned int h_mt_interval(HostMT& st, unsigned int mx) {
    if (mx == 0u) return 0u;
    unsigned int mask = mx;
    mask |= mask >> 1; mask |= mask >> 2; mask |= mask >> 4;
    mask |= mask >> 8; mask |= mask >> 16;
    unsigned int v;
    do { v = h_mt_next(st) & mask; } while (v > mx);
    return v;
}
static void h_make_table(int* h_idx, int* h_cnt) {
    HostMT st;
    h_mt_seed(st, 0u);
    for (int i = 1; i <= NBb - 2; i++) {
        bool fx[NBb];
        for (int z = 0; z < NBb; z++) fx[z] = false;
        fx[0] = true; fx[NBb - 1] = true;
        fx[i - 1] = true; fx[i] = true; fx[i + 1] = true;
        int fixed[8], nf = 0;
        int allowed[NBb], na = 0;
        for (int bb = 0; bb < NBb; bb++) {
            if (fx[bb]) fixed[nf++] = bb;
            else        allowed[na++] = bb;
        }
        int perm[NBb];
        for (int t = 0; t < na; t++) perm[t] = t;
        for (int t = na - 1; t >= 1; t--) {
            int j = (int)h_mt_interval(st, (unsigned)t);
            int tmp = perm[t]; perm[t] = perm[j]; perm[j] = tmp;
        }
        int row = i - 1;
        int cnt = 0;
        for (int s = 0; s < nf; s++) h_idx[row * 8 + cnt++] = fixed[s];
        for (int r3 = 0; r3 < 3; r3++) h_idx[row * 8 + cnt++] = allowed[perm[r3]];
        h_cnt[row] = cnt;
        for (; cnt < 8; cnt++) h_idx[row * 8 + cnt] = 0;
    }
}

// ---------------- helpers ----------------
__device__ __forceinline__ uint32_t f2tf(float x) {
    uint32_t r;
    asm("cvt.rna.tf32.f32 %0, %1;" : "=r"(r) : "f"(x));
    return r;
}
__device__ __forceinline__ float rf(float x) { return __uint_as_float(f2tf(x)); }
__device__ __forceinline__ float gelu_tanh(float x) {
    const float c = 0.7978845608028654f;
    float x3 = x * x * x;
    return 0.5f * x * (1.0f + tanhf(c * (x + 0.044715f * x3)));
}
__device__ __forceinline__ void cpasync16(uint32_t saddr, const void* gaddr) {
    asm volatile("cp.async.cg.shared.global [%0], [%1], 16;" :: "r"(saddr), "l"(gaddr) : "memory");
}
__device__ __forceinline__ void mma_tf32(float* c, const uint32_t* a, uint32_t b0, uint32_t b1) {
    asm volatile(
        "mma.sync.aligned.m16n8k8.row.col.f32.tf32.tf32.f32 "
        "{%0,%1,%2,%3}, {%4,%5,%6,%7}, {%8,%9}, {%0,%1,%2,%3};"
        : "+f"(c[0]), "+f"(c[1]), "+f"(c[2]), "+f"(c[3])
        : "r"(a[0]), "r"(a[1]), "r"(a[2]), "r"(a[3]), "r"(b0), "r"(b1));
}
__device__ __forceinline__ void ldsm4(uint32_t* r, uint32_t saddr) {
    asm volatile("ldmatrix.sync.aligned.m8n8.x4.shared.b16 {%0,%1,%2,%3}, [%4];"
                 : "=r"(r[0]), "=r"(r[1]), "=r"(r[2]), "=r"(r[3]) : "r"(saddr));
}

// ---------------- merged transpose + tf32-round of all 6 weight matrices ----------------
// One launch. Flat tile index over: wq(256) wk(256) wv(256) wo(256) w1(1024) w2(1024) = 3072.
__global__ void __launch_bounds__(256)
transpose_round_all(const float* __restrict__ wq, const float* __restrict__ wk,
                    const float* __restrict__ wv, const float* __restrict__ wo,
                    const float* __restrict__ w1, const float* __restrict__ w2,
                    float* __restrict__ dqkv, float* __restrict__ dwo,
                    float* __restrict__ dw1, float* __restrict__ dw2) {
    __shared__ float t[32][33];
    const int bid = blockIdx.x;
    const float* src;
    float* dst;
    int R, C, ti;
    if (bid < 1024) {                     // wq/wk/wv/wo: 512x512, 256 tiles each
        const int m = bid >> 8;
        ti = bid & 255;
        R = 512; C = 512;
        if (m == 0)      { src = wq; dst = dqkv; }
        else if (m == 1) { src = wk; dst = dqkv + 512 * 512; }
        else if (m == 2) { src = wv; dst = dqkv + 1024 * 512; }
        else             { src = wo; dst = dwo; }
    } else if (bid < 2048) {              // w1: 512x2048
        ti = bid - 1024; R = 512; C = 2048; src = w1; dst = dw1;
    } else {                              // w2: 2048x512
        ti = bid - 2048; R = 2048; C = 512; src = w2; dst = dw2;
    }
    const int Ct = C >> 5;
    const int r0 = (ti / Ct) * 32, c0 = (ti % Ct) * 32;
    const int tx = threadIdx.x & 31, ty = threadIdx.x >> 5;
    #pragma unroll
    for (int j = 0; j < 4; j++)
        t[ty + j * 8][tx] = rf(src[(size_t)(r0 + ty + j * 8) * C + c0 + tx]);
    __syncthreads();
    #pragma unroll
    for (int j = 0; j < 4; j++)
        dst[(size_t)(c0 + ty + j * 8) * R + r0 + tx] = t[tx][ty + j * 8];
}

// ---------------- LayerNorm ----------------
template <bool RND>
__global__ void ln_kernel(const float* __restrict__ x, const float* __restrict__ g,
                          const float* __restrict__ bta, float* __restrict__ y) {
    __shared__ float red[2][4];
    const int row = blockIdx.x;
    const int t = threadIdx.x;
    const float* xr = x + (size_t)row * Dmod;
    float4 xv = ((const float4*)xr)[t];
    float s  = xv.x + xv.y + xv.z + xv.w;
    float q2 = xv.x * xv.x + xv.y * xv.y + xv.z * xv.z + xv.w * xv.w;
    #pragma unroll
    for (int o = 16; o; o >>= 1) {
        s  += __shfl_xor_sync(0xffffffffu, s,  o);
        q2 += __shfl_xor_sync(0xffffffffu, q2, o);
    }
    if ((t & 31) == 0) { red[0][t >> 5] = s; red[1][t >> 5] = q2; }
    __syncthreads();
    s  = red[0][0] + red[0][1] + red[0][2] + red[0][3];
    q2 = red[1][0] + red[1][1] + red[1][2] + red[1][3];
    const float mu   = s * (1.0f / Dmod);
    const float var  = q2 * (1.0f / Dmod) - mu * mu;
    const float rstd = rsqrtf(var + 1e-6f);
    float4 gv = ((const float4*)g)[t];
    float4 bv = ((const float4*)bta)[t];
    float4 ov;
    ov.x = (xv.x - mu) * rstd * gv.x + bv.x;
    ov.y = (xv.y - mu) * rstd * gv.y + bv.y;
    ov.z = (xv.z - mu) * rstd * gv.z + bv.z;
    ov.w = (xv.w - mu) * rstd * gv.w + bv.w;
    if (RND) { ov.x = rf(ov.x); ov.y = rf(ov.y); ov.z = rf(ov.z); ov.w = rf(ov.w); }
    ((float4*)(y + (size_t)row * Dmod))[t] = ov;
}

// ---------------- TF32 TC SGEMM: 3-stage cp.async pipeline, single sync/iter ----------------
#define G_LD   36
#define G_TILE (128 * G_LD)                 // 4608 floats per (A or B) stage
#define GEMM_SMEM (6 * G_TILE * 4)          // 3 stages x (A+B) = 110592 B

__device__ __forceinline__ void gemm_prefetch(uint32_t sA, uint32_t sB,
                                              const float* __restrict__ A,
                                              const float* __restrict__ Bt,
                                              int bm, int bn, int K,
                                              int ldrow, int ldk4, int t, int stage) {
    const float* Ag = A  + (size_t)(bm + ldrow) * K + t * 32 + ldk4;
    const float* Bg = Bt + (size_t)(bn + ldrow) * K + t * 32 + ldk4;
    const uint32_t so = (uint32_t)((stage * G_TILE + ldrow * G_LD + ldk4) * 4);
    #pragma unroll
    for (int i = 0; i < 4; i++) {
        cpasync16(sA + so + (uint32_t)(32 * i * G_LD * 4), Ag + (size_t)(32 * i) * K);
        cpasync16(sB + so + (uint32_t)(32 * i * G_LD * 4), Bg + (size_t)(32 * i) * K);
    }
    asm volatile("cp.async.commit_group;" ::: "memory");
}

// EPI: 0 = qkv (alpha on cols<512, round) ; 1 = gelu(acc+bias) ; 2 = acc+res ; 3 = acc+bias+res
template <int EPI, bool RND>
__global__ void __launch_bounds__(256, 2)
sgemm_tc(const float* __restrict__ A, const float* __restrict__ Bt,
         float* __restrict__ C, int N, int K, float alpha,
         const float* __restrict__ bias, const float* __restrict__ res) {
    extern __shared__ float sm[];
    const int tid  = threadIdx.x;
    const int bm   = blockIdx.y * 128;
    const int bn   = blockIdx.x * 128;
    const int lane = tid & 31;
    const int wid  = tid >> 5;
    const int wm   = wid & 1;
    const int wn   = wid >> 1;
    const int lr   = lane >> 2;
    const int lc   = lane & 3;
    const int tile = lane >> 3;
    const int t7   = lane & 7;

    uint32_t sbase = (uint32_t)__cvta_generic_to_shared(sm);
    uint32_t sA = sbase;                        // [3][128][G_LD]
    uint32_t sB = sbase + 3 * G_TILE * 4;       // [3][128][G_LD]

    float acc[4][4][4];
    #pragma unroll
    for (int mt = 0; mt < 4; mt++)
        #pragma unroll
        for (int nt = 0; nt < 4; nt++)
            #pragma unroll
            for (int r = 0; r < 4; r++) acc[mt][nt][r] = 0.0f;

    const int nk = K >> 5;
    const int ldrow = tid >> 3, ldk4 = (tid & 7) * 4;

    // prologue: tiles 0 and 1 (nk >= 16 always here)
    gemm_prefetch(sA, sB, A, Bt, bm, bn, K, ldrow, ldk4, 0, 0);
    gemm_prefetch(sA, sB, A, Bt, bm, bn, K, ldrow, ldk4, 1, 1);

    int cs = 0;       // stage of tile t
    int ps = 2;       // stage for tile t+2
    for (int t = 0; t < nk; t++) {
        if (t + 1 < nk) {
            asm volatile("cp.async.wait_group 1;" ::: "memory");
        } else {
            asm volatile("cp.async.wait_group 0;" ::: "memory");
        }
        __syncthreads();   // tile t visible to all; everyone done reading stage ps

        if (t + 2 < nk)
            gemm_prefetch(sA, sB, A, Bt, bm, bn, K, ldrow, ldk4, t + 2, ps);

        const uint32_t sAc = sA + (uint32_t)(cs * G_TILE * 4);
        const uint32_t sBc = sB + (uint32_t)(cs * G_TILE * 4);

        #pragma unroll
        for (int ks = 0; ks < 4; ks++) {
            const int k0 = ks * 8;
            uint32_t af[4][4], bf[2][4];
            const int aRow = wm * 64 + (tile & 1) * 8 + t7;
            const int aCol = k0 + (tile >> 1) * 4;
            #pragma unroll
            for (int mt = 0; mt < 4; mt++)
                ldsm4(af[mt], sAc + (uint32_t)(((aRow + mt * 16) * G_LD + aCol) * 4));
            const int bRow = wn * 32 + (tile >> 1) * 8 + t7;
            const int bCol = k0 + (tile & 1) * 4;
            #pragma unroll
            for (int ntp = 0; ntp < 2; ntp++)
                ldsm4(bf[ntp], sBc + (uint32_t)(((bRow + ntp * 16) * G_LD + bCol) * 4));
            #pragma unroll
            for (int mt = 0; mt < 4; mt++) {
                mma_tf32(acc[mt][0], af[mt], bf[0][0], bf[0][1]);
                mma_tf32(acc[mt][1], af[mt], bf[0][2], bf[0][3]);
                mma_tf32(acc[mt][2], af[mt], bf[1][0], bf[1][1]);
                mma_tf32(acc[mt][3], af[mt], bf[1][2], bf[1][3]);
            }
        }

        cs = (cs == 2) ? 0 : cs + 1;
        ps = (ps == 2) ? 0 : ps + 1;
    }

    const float a_eff = (EPI == 0) ? ((bn < 512) ? alpha : 1.0f) : alpha;

    #pragma unroll
    for (int mt = 0; mt < 4; mt++) {
        const int row0 = bm + wm * 64 + mt * 16 + lr;
        #pragma unroll
        for (int half = 0; half < 2; half++) {
            const int row = row0 + half * 8;
            #pragma unroll
            for (int nt = 0; nt < 4; nt++) {
                const int col = bn + wn * 32 + nt * 8 + lc * 2;
                float v0 = acc[mt][nt][half * 2 + 0];
                float v1 = acc[mt][nt][half * 2 + 1];
                const size_t off = (size_t)row * N + col;
                if (EPI == 0) { v0 *= a_eff; v1 *= a_eff; }
                if (EPI == 1) {
                    v0 = gelu_tanh(v0 + bias[col]);
                    v1 = gelu_tanh(v1 + bias[col + 1]);
                }
                if (EPI == 2) { v0 += res[off]; v1 += res[off + 1]; }
                if (EPI == 3) {
                    v0 += bias[col] + res[off];
                    v1 += bias[col + 1] + res[off + 1];
                }
                if (RND) { v0 = rf(v0); v1 = rf(v1); }
                *(float2*)&C[off] = make_float2(v0, v1);
            }
        }
    }
}

// ---------------- flash BigBird attention: 32-row kv subtiles, split-KV globals ----------------
#define AKLD 68
#define AVLD 72
#define APLD 36
#define A_KOFF 0
#define A_VOFF (2 * 32 * AKLD)
#define A_POFF (A_VOFF + 2 * 32 * AVLD)
#define ATT_SMEM ((A_POFF + 64 * APLD) * 4)

__device__ __forceinline__ void att_load_sub(uint32_t sbase, int tid, int stage,
                                             const float* kb_g, const float* vb_g) {
    const int row = tid >> 4, c4 = (tid & 15) * 4;
    #pragma unroll
    for (int i = 0; i < 4; i++) {
        cpasync16(sbase + (uint32_t)((A_KOFF + stage * 32 * AKLD + (row + 8 * i) * AKLD + c4) * 4),
                  kb_g + (size_t)(row + 8 * i) * QKV_LD + c4);
        cpasync16(sbase + (uint32_t)((A_VOFF + stage * 32 * AVLD + (row + 8 * i) * AVLD + c4) * 4),
                  vb_g + (size_t)(row + 8 * i) * QKV_LD + c4);
    }
    asm volatile("cp.async.commit_group;" ::: "memory");
}

__global__ void __launch_bounds__(128)
attn_tc(const float* __restrict__ qkv, float* __restrict__ o,
        float* __restrict__ po, float* __restrict__ pm, float* __restrict__ pl,
        const int* __restrict__ idxTab, const int* __restrict__ cntTab) {
    extern __shared__ float sm[];
    const int bx = blockIdx.x, h = blockIdx.y, b = blockIdx.z;
    const int tid = threadIdx.x;
    const int lane = tid & 31, w = tid >> 5;
    const int lr = lane >> 2, lc = lane & 3;
    const int tile = lane >> 3, t7 = lane & 7;

    const bool isg = (bx < 16);
    int n, split = 0, nsub;
    if (isg) { split = bx & 7; n = (bx >> 3) ? (NBb - 1) : 0; nsub = 16; }
    else     { n = bx - 15; nsub = 2 * cntTab[n - 1]; }

    uint32_t sbase = (uint32_t)__cvta_generic_to_shared(sm);

    const float* qbase = qkv + (size_t)(b * Sseq + n * BSb) * QKV_LD + h * DHd;
    for (int i = tid; i < 1024; i += 128) {
        int rr = i >> 4, c4 = (i & 15) << 2;
        *(float4*)&sm[rr * AKLD + c4] = *(const float4*)&qbase[(size_t)rr * QKV_LD + c4];
    }
    __syncthreads();
    uint32_t aq[8][4];
    {
        const int qRow = w * 16 + (tile & 1) * 8 + t7;
        #pragma unroll
        for (int kt = 0; kt < 8; kt++)
            ldsm4(aq[kt], sbase + (uint32_t)((qRow * AKLD + kt * 8 + (tile >> 1) * 4) * 4));
    }
    __syncthreads();

    float accO[8][4];
    #pragma unroll
    for (int nt = 0; nt < 8; nt++)
        #pragma unroll
        for (int r = 0; r < 4; r++) accO[nt][r] = 0.0f;
    float m0 = -1e30f, m1 = -1e30f, l0 = 0.0f, l1 = 0.0f;

    {
        const int blk = isg ? split * 8 : idxTab[(n - 1) * 8];
        const float* base = qkv + (size_t)(b * Sseq + blk * BSb) * QKV_LD + h * DHd;
        att_load_sub(sbase, tid, 0, base + 512, base + 1024);
    }

    for (int it = 0; it < nsub; it++) {
        const int st = it & 1;
        if (it + 1 < nsub) {
            const int i2 = it + 1;
            const int blk = isg ? (split * 8 + (i2 >> 1)) : idxTab[(n - 1) * 8 + (i2 >> 1)];
            const float* base = qkv + (size_t)(b * Sseq + blk * BSb + (i2 & 1) * 32) * QKV_LD + h * DHd;
            att_load_sub(sbase, tid, st ^ 1, base + 512, base + 1024);
            asm volatile("cp.async.wait_group 1;" ::: "memory");
        } else {
            asm volatile("cp.async.wait_group 0;" ::: "memory");
        }
        __syncthreads();

        float s[4][4];
        #pragma unroll
        for (int nt = 0; nt < 4; nt++)
            #pragma unroll
            for (int r = 0; r < 4; r++) s[nt][r] = 0.0f;

        const uint32_t kB = sbase + (uint32_t)((A_KOFF + st * 32 * AKLD) * 4);
        const int kRow = (tile >> 1) * 8 + t7;
        const int kCol = (tile & 1) * 4;
        #pragma unroll
        for (int kt = 0; kt < 8; kt++) {
            uint32_t bf[2][4];
            #pragma unroll
            for (int ntp = 0; ntp < 2; ntp++)
                ldsm4(bf[ntp], kB + (uint32_t)(((ntp * 16 + kRow) * AKLD + kt * 8 + kCol) * 4));
            mma_tf32(s[0], aq[kt], bf[0][0], bf[0][1]);
            mma_tf32(s[1], aq[kt], bf[0][2], bf[0][3]);
            mma_tf32(s[2], aq[kt], bf[1][0], bf[1][1]);
            mma_tf32(s[3], aq[kt], bf[1][2], bf[1][3]);
        }

        float mx0 = fmaxf(fmaxf(s[0][0], s[0][1]), fmaxf(s[1][0], s[1][1]));
        float mx1 = fmaxf(fmaxf(s[0][2], s[0][3]), fmaxf(s[1][2], s[1][3]));
        mx0 = fmaxf(mx0, fmaxf(fmaxf(s[2][0], s[2][1]), fmaxf(s[3][0], s[3][1])));
        mx1 = fmaxf(mx1, fmaxf(fmaxf(s[2][2], s[2][3]), fmaxf(s[3][2], s[3][3])));
        mx0 = fmaxf(mx0, __shfl_xor_sync(0xffffffffu, mx0, 1));
        mx0 = fmaxf(mx0, __shfl_xor_sync(0xffffffffu, mx0, 2));
        mx1 = fmaxf(mx1, __shfl_xor_sync(0xffffffffu, mx1, 1));
        mx1 = fmaxf(mx1, __shfl_xor_sync(0xffffffffu, mx1, 2));
        const float mn0 = fmaxf(m0, mx0), mn1 = fmaxf(m1, mx1);
        const float cor0 = __expf(m0 - mn0), cor1 = __expf(m1 - mn1);
        float ps0 = 0.0f, ps1 = 0.0f;
        #pragma unroll
        for (int nt = 0; nt < 4; nt++) {
            s[nt][0] = __expf(s[nt][0] - mn0);
            s[nt][1] = __expf(s[nt][1] - mn0);
            s[nt][2] = __expf(s[nt][2] - mn1);
            s[nt][3] = __expf(s[nt][3] - mn1);
            ps0 += s[nt][0] + s[nt][1];
            ps1 += s[nt][2] + s[nt][3];
        }
        ps0 += __shfl_xor_sync(0xffffffffu, ps0, 1);
        ps0 += __shfl_xor_sync(0xffffffffu, ps0, 2);
        ps1 += __shfl_xor_sync(0xffffffffu, ps1, 1);
        ps1 += __shfl_xor_sync(0xffffffffu, ps1, 2);
        l0 = l0 * cor0 + ps0;
        l1 = l1 * cor1 + ps1;
        m0 = mn0; m1 = mn1;
        #pragma unroll
        for (int nt = 0; nt < 8; nt++) {
            accO[nt][0] *= cor0; accO[nt][1] *= cor0;
            accO[nt][2] *= cor1; accO[nt][3] *= cor1;
        }

        float* pw = sm + A_POFF + (w * 16 + lr) * APLD;
        #pragma unroll
        for (int nt = 0; nt < 4; nt++) {
            *(float2*)&pw[nt * 8 + 2 * lc]            = make_float2(rf(s[nt][0]), rf(s[nt][1]));
            *(float2*)&pw[8 * APLD + nt * 8 + 2 * lc] = make_float2(rf(s[nt][2]), rf(s[nt][3]));
        }
        __syncwarp();

        const uint32_t pB = sbase + (uint32_t)(A_POFF * 4);
        const int pRow = w * 16 + (tile & 1) * 8 + t7;
        const int pCol = (tile >> 1) * 4;
        const uint32_t* Vst = (const uint32_t*)(sm + A_VOFF + st * 32 * AVLD);
        #pragma unroll
        for (int kt = 0; kt < 4; kt++) {
            uint32_t ap[4];
            ldsm4(ap, pB + (uint32_t)((pRow * APLD + kt * 8 + pCol) * 4));
            #pragma unroll
            for (int nt = 0; nt < 8; nt++) {
                const uint32_t* pv = Vst + (kt * 8 + lc) * AVLD + nt * 8 + lr;
                mma_tf32(accO[nt], ap, pv[0], pv[4 * AVLD]);
            }
        }
        __syncthreads();
    }

    if (!isg) {
        const float inv0 = 1.0f / l0, inv1 = 1.0f / l1;
        float* ob = o + (size_t)(b * Sseq + n * BSb + w * 16 + lr) * Dmod + h * DHd;
        #pragma unroll
        for (int nt = 0; nt < 8; nt++) {
            *(float2*)&ob[nt * 8 + 2 * lc] =
                make_float2(rf(accO[nt][0] * inv0), rf(accO[nt][1] * inv0));
            *(float2*)&ob[(size_t)8 * Dmod + nt * 8 + 2 * lc] =
                make_float2(rf(accO[nt][2] * inv1), rf(accO[nt][3] * inv1));
        }
    } else {
        const int g = n ? 1 : 0;
        const int pslot = ((b * 2 + g) * Hh + h) * 8 + split;
        if (lc == 0) {
            pm[pslot * 64 + w * 16 + lr]     = m0;
            pl[pslot * 64 + w * 16 + lr]     = l0;
            pm[pslot * 64 + w * 16 + 8 + lr] = m1;
            pl[pslot * 64 + w * 16 + 8 + lr] = l1;
        }
        float* pb = po + ((size_t)pslot * 64 + w * 16 + lr) * 64;
        #pragma unroll
        for (int nt = 0; nt < 8; nt++) {
            *(float2*)&pb[nt * 8 + 2 * lc]          = make_float2(accO[nt][0], accO[nt][1]);
            *(float2*)&pb[8 * 64 + nt * 8 + 2 * lc] = make_float2(accO[nt][2], accO[nt][3]);
        }
    }
}

// ---------------- combine global-split partials ----------------
__global__ void __launch_bounds__(256)
combine_kernel(const float* __restrict__ po, const float* __restrict__ pm,
               const float* __restrict__ pl, float* __restrict__ o) {
    const int group = blockIdx.x;
    const int b = group >> 4, g = (group >> 3) & 1, h = group & 7;
    const int row = threadIdx.x >> 2;
    const int cseg = (threadIdx.x & 3) * 16;

    float mv[8], lv[8];
    float M = -1e30f;
    #pragma unroll
    for (int s = 0; s < 8; s++) {
        mv[s] = pm[(group * 8 + s) * 64 + row];
        lv[s] = pl[(group * 8 + s) * 64 + row];
        M = fmaxf(M, mv[s]);
    }
    float L = 0.0f, wgt[8];
    #pragma unroll
    for (int s = 0; s < 8; s++) {
        wgt[s] = __expf(mv[s] - M);
        L += lv[s] * wgt[s];
    }
    float acc[16];
    #pragma unroll
    for (int c = 0; c < 16; c++) acc[c] = 0.0f;
    #pragma unroll
    for (int s = 0; s < 8; s++) {
        const float* pr = po + ((size_t)(group * 8 + s) * 64 + row) * 64 + cseg;
        #pragma unroll
        for (int c4 = 0; c4 < 4; c4++) {
            float4 vv = *(const float4*)&pr[c4 * 4];
            acc[c4 * 4 + 0] += wgt[s] * vv.x;
            acc[c4 * 4 + 1] += wgt[s] * vv.y;
            acc[c4 * 4 + 2] += wgt[s] * vv.z;
            acc[c4 * 4 + 3] += wgt[s] * vv.w;
        }
    }
    const float inv = 1.0f / L;
    const int nblk = g ? (NBb - 1) : 0;
    float* ob = o + (size_t)(b * Sseq + nblk * BSb + row) * Dmod + h * DHd + cseg;
    #pragma unroll
    for (int c4 = 0; c4 < 4; c4++) {
        float4 ov;
        ov.x = rf(acc[c4 * 4 + 0] * inv);
        ov.y = rf(acc[c4 * 4 + 1] * inv);
        ov.z = rf(acc[c4 * 4 + 2] * inv);
        ov.w = rf(acc[c4 * 4 + 3] * inv);
        *(float4*)&ob[c4 * 4] = ov;
    }
}

// ---------------- launcher ----------------
extern "C" void kernel_launch(void* const* d_in, const int* in_sizes, int n_in,
                              void* d_out, int out_size) {
    const float* inputs = (const float*)d_in[0];
    const float* ln1_s  = (const float*)d_in[1];
    const float* ln1_b  = (const float*)d_in[2];
    const float* wq     = (const float*)d_in[3];
    const float* wk     = (const float*)d_in[4];
    const float* wv     = (const float*)d_in[5];
    const float* wo     = (const float*)d_in[6];
    const float* ln2_s  = (const float*)d_in[7];
    const float* ln2_b  = (const float*)d_in[8];
    const float* w1     = (const float*)d_in[9];
    const float* b1     = (const float*)d_in[10];
    const float* w2     = (const float*)d_in[11];
    const float* b2     = (const float*)d_in[12];
    float* out = (float*)d_out;

    float *xn, *qkv, *o, *yn, *hb, *wqkv, *wor, *w1r, *w2r, *po, *pmv, *plv;
    int *idx, *cnt;
    cudaGetSymbolAddress((void**)&xn,   g_xn);
    cudaGetSymbolAddress((void**)&qkv,  g_qkv);
    cudaGetSymbolAddress((void**)&o,    g_o);
    cudaGetSymbolAddress((void**)&yn,   g_yn);
    cudaGetSymbolAddress((void**)&hb,   g_hb);
    cudaGetSymbolAddress((void**)&wqkv, g_wqkv);
    cudaGetSymbolAddress((void**)&wor,  g_wor);
    cudaGetSymbolAddress((void**)&w1r,  g_w1r);
    cudaGetSymbolAddress((void**)&w2r,  g_w2r);
    cudaGetSymbolAddress((void**)&po,   g_po);
    cudaGetSymbolAddress((void**)&pmv,  g_pm);
    cudaGetSymbolAddress((void**)&plv,  g_pl);
    cudaGetSymbolAddress((void**)&idx,  g_idx);
    cudaGetSymbolAddress((void**)&cnt,  g_cnt);

    cudaFuncSetAttribute(sgemm_tc<0, true>,  cudaFuncAttributeMaxDynamicSharedMemorySize, GEMM_SMEM);
    cudaFuncSetAttribute(sgemm_tc<1, true>,  cudaFuncAttributeMaxDynamicSharedMemorySize, GEMM_SMEM);
    cudaFuncSetAttribute(sgemm_tc<2, false>, cudaFuncAttributeMaxDynamicSharedMemorySize, GEMM_SMEM);
    cudaFuncSetAttribute(sgemm_tc<3, false>, cudaFuncAttributeMaxDynamicSharedMemorySize, GEMM_SMEM);

    // 0. BigBird index table (host, input-independent)
    static int h_idx[NROWS * 8];
    static int h_cnt[NROWS];
    h_make_table(h_idx, h_cnt);
    cudaMemcpyAsync(idx, h_idx, sizeof(h_idx), cudaMemcpyHostToDevice, 0);
    cudaMemcpyAsync(cnt, h_cnt, sizeof(h_cnt), cudaMemcpyHostToDevice, 0);

    // 1. transpose + round ALL weights in one launch
    transpose_round_all<<<3072, 256>>>(wq, wk, wv, wo, w1, w2, wqkv, wor, w1r, w2r);

    // 2. LN1 (rounded)
    ln_kernel<true><<<NTOK, 128>>>(inputs, ln1_s, ln1_b, xn);

    // 3. QKV: single GEMM, N=1536 packed; alpha=0.125 on q columns
    dim3 gqkv(QKV_LD / 128, NTOK / 128);
    sgemm_tc<0, true><<<gqkv, 256, GEMM_SMEM>>>(xn, wqkv, qkv, QKV_LD, Dmod, 0.125f, nullptr, nullptr);

    // 4. attention: interiors + split-KV globals, then combine
    attn_tc<<<dim3(78, Hh, Bsz), 128, ATT_SMEM>>>(qkv, o, po, pmv, plv, idx, cnt);
    combine_kernel<<<64, 256>>>(po, pmv, plv, o);

    // 5. WO + residual (exact fp32)
    dim3 g512(Dmod / 128, NTOK / 128);
    sgemm_tc<2, false><<<g512, 256, GEMM_SMEM>>>(o, wor, out, Dmod, Dmod, 1.0f, nullptr, inputs);

    // 6. LN2 (rounded)
    ln_kernel<true><<<NTOK, 128>>>(out, ln2_s, ln2_b, yn);

    // 7. FFN1: gelu(yn @ w1 + b1), rounded
    dim3 g2048(Mff / 128, NTOK / 128);
    sgemm_tc<1, true><<<g2048, 256, GEMM_SMEM>>>(yn, w1r, hb, Mff, Dmod, 1.0f, b1, nullptr);

    // 8. FFN2 + bias + residual (exact fp32)
    sgemm_tc<3, false><<<g512, 256, GEMM_SMEM>>>(hb, w2r, out, Dmod, Mff, 1.0f, b2, out);
}

// round 7
// speedup vs baseline: 11.9555x; 1.4488x over previous
#include <cuda_runtime.h>
#include <cuda_fp16.h>
#include <math.h>
#include <stdint.h>

// ---------------- problem constants ----------------
#define Bsz   4
#define Sseq  4096
#define Dmod  512
#define Hh    8
#define DHd   64
#define Mff   2048
#define BSb   64
#define NBb   64
#define NROWS (NBb - 2)
#define NTOK  (Bsz * Sseq)        // 16384
#define QKV_LD 1536

// ---------------- scratch (device globals; no allocation) ----------------
__device__ __half g_xn  [(size_t)NTOK * Dmod];
__device__ __half g_qkv [(size_t)NTOK * QKV_LD];
__device__ __half g_o   [(size_t)NTOK * Dmod];
__device__ __half g_yn  [(size_t)NTOK * Dmod];
__device__ __half g_hb  [(size_t)NTOK * Mff];
__device__ __half g_wqkv[(size_t)QKV_LD * Dmod];   // transposed [n][k], fp16
__device__ __half g_wor [(size_t)Dmod * Dmod];
__device__ __half g_w1r [(size_t)Mff * Dmod];
__device__ __half g_w2r [(size_t)Dmod * Mff];
__device__ float  g_po  [(size_t)512 * 64 * 64];   // global-split partials (fp32)
__device__ float  g_pm  [512 * 64];
__device__ float  g_pl  [512 * 64];
__device__ int    g_idx[NROWS * 8];
__device__ int    g_cnt[NROWS];

// ---------------- host-side numpy-legacy MT19937 ----------------
struct HostMT { unsigned int k[624]; int pos; };
static void h_mt_seed(HostMT& st, unsigned int seed) {
    for (int p = 0; p < 624; p++) {
        st.k[p] = seed;
        seed = 1812433253u * (seed ^ (seed >> 30)) + (unsigned)p + 1u;
    }
    st.pos = 624;
}
static unsigned int h_mt_next(HostMT& st) {
    if (st.pos == 624) {
        for (int i = 0; i < 624; i++) {
            unsigned int y = (st.k[i] & 0x80000000u) | (st.k[(i + 1) % 624] & 0x7fffffffu);
            st.k[i] = st.k[(i + 397) % 624] ^ (y >> 1) ^ ((y & 1u) ? 0x9908b0dfu : 0u);
        }
        st.pos = 0;
    }
    unsigned int y = st.k[st.pos++];
    y ^= y >> 11;
    y ^= (y << 7)  & 0x9d2c5680u;
    y ^= (y << 15) & 0xefc60000u;
    y ^= y >> 18;
    return y;
}
static unsigned int h_mt_interval(HostMT& st, unsigned int mx) {
    if (mx == 0u) return 0u;
    unsigned int mask = mx;
    mask |= mask >> 1; mask |= mask >> 2; mask |= mask >> 4;
    mask |= mask >> 8; mask |= mask >> 16;
    unsigned int v;
    do { v = h_mt_next(st) & mask; } while (v > mx);
    return v;
}
static void h_make_table(int* h_idx, int* h_cnt) {
    HostMT st;
    h_mt_seed(st, 0u);
    for (int i = 1; i <= NBb - 2; i++) {
        bool fx[NBb];
        for (int z = 0; z < NBb; z++) fx[z] = false;
        fx[0] = true; fx[NBb - 1] = true;
        fx[i - 1] = true; fx[i] = true; fx[i + 1] = true;
        int fixed[8], nf = 0;
        int allowed[NBb], na = 0;
        for (int bb = 0; bb < NBb; bb++) {
            if (fx[bb]) fixed[nf++] = bb;
            else        allowed[na++] = bb;
        }
        int perm[NBb];
        for (int t = 0; t < na; t++) perm[t] = t;
        for (int t = na - 1; t >= 1; t--) {
            int j = (int)h_mt_interval(st, (unsigned)t);
            int tmp = perm[t]; perm[t] = perm[j]; perm[j] = tmp;
        }
        int row = i - 1;
        int cnt = 0;
        for (int s = 0; s < nf; s++) h_idx[row * 8 + cnt++] = fixed[s];
        for (int r3 = 0; r3 < 3; r3++) h_idx[row * 8 + cnt++] = allowed[perm[r3]];
        h_cnt[row] = cnt;
        for (; cnt < 8; cnt++) h_idx[row * 8 + cnt] = 0;
    }
}

// ---------------- helpers ----------------
__device__ __forceinline__ float gelu_tanh(float x) {
    const float c = 0.7978845608028654f;
    float x3 = x * x * x;
    return 0.5f * x * (1.0f + tanhf(c * (x + 0.044715f * x3)));
}
__device__ __forceinline__ void cpasync16(uint32_t saddr, const void* gaddr) {
    asm volatile("cp.async.cg.shared.global [%0], [%1], 16;" :: "r"(saddr), "l"(gaddr) : "memory");
}
__device__ __forceinline__ void mma_f16(float* c, const uint32_t* a, uint32_t b0, uint32_t b1) {
    asm volatile(
        "mma.sync.aligned.m16n8k16.row.col.f32.f16.f16.f32 "
        "{%0,%1,%2,%3}, {%4,%5,%6,%7}, {%8,%9}, {%0,%1,%2,%3};"
        : "+f"(c[0]), "+f"(c[1]), "+f"(c[2]), "+f"(c[3])
        : "r"(a[0]), "r"(a[1]), "r"(a[2]), "r"(a[3]), "r"(b0), "r"(b1));
}
__device__ __forceinline__ void ldsm4(uint32_t* r, uint32_t saddr) {
    asm volatile("ldmatrix.sync.aligned.m8n8.x4.shared.b16 {%0,%1,%2,%3}, [%4];"
                 : "=r"(r[0]), "=r"(r[1]), "=r"(r[2]), "=r"(r[3]) : "r"(saddr));
}
__device__ __forceinline__ void ldsm4t(uint32_t* r, uint32_t saddr) {
    asm volatile("ldmatrix.sync.aligned.m8n8.x4.trans.shared.b16 {%0,%1,%2,%3}, [%4];"
                 : "=r"(r[0]), "=r"(r[1]), "=r"(r[2]), "=r"(r[3]) : "r"(saddr));
}

// ---------------- merged transpose + fp16 convert of all 6 weight matrices ----------------
__global__ void __launch_bounds__(256)
transpose_cvt_all(const float* __restrict__ wq, const float* __restrict__ wk,
                  const float* __restrict__ wv, const float* __restrict__ wo,
                  const float* __restrict__ w1, const float* __restrict__ w2,
                  __half* __restrict__ dqkv, __half* __restrict__ dwo,
                  __half* __restrict__ dw1, __half* __restrict__ dw2) {
    __shared__ float t[32][33];
    const int bid = blockIdx.x;
    const float* src;
    __half* dst;
    int R, C, ti;
    if (bid < 1024) {
        const int m = bid >> 8;
        ti = bid & 255;
        R = 512; C = 512;
        if (m == 0)      { src = wq; dst = dqkv; }
        else if (m == 1) { src = wk; dst = dqkv + 512 * 512; }
        else if (m == 2) { src = wv; dst = dqkv + 1024 * 512; }
        else             { src = wo; dst = dwo; }
    } else if (bid < 2048) {
        ti = bid - 1024; R = 512; C = 2048; src = w1; dst = dw1;
    } else {
        ti = bid - 2048; R = 2048; C = 512; src = w2; dst = dw2;
    }
    const int Ct = C >> 5;
    const int r0 = (ti / Ct) * 32, c0 = (ti % Ct) * 32;
    const int tx = threadIdx.x & 31, ty = threadIdx.x >> 5;
    #pragma unroll
    for (int j = 0; j < 4; j++)
        t[ty + j * 8][tx] = src[(size_t)(r0 + ty + j * 8) * C + c0 + tx];
    __syncthreads();
    #pragma unroll
    for (int j = 0; j < 4; j++)
        dst[(size_t)(c0 + ty + j * 8) * R + r0 + tx] = __float2half_rn(t[tx][ty + j * 8]);
}

// ---------------- LayerNorm (fp32 in, fp16 out for GEMM A) ----------------
__global__ void ln_kernel(const float* __restrict__ x, const float* __restrict__ g,
                          const float* __restrict__ bta, __half* __restrict__ y) {
    __shared__ float red[2][4];
    const int row = blockIdx.x;
    const int t = threadIdx.x;
    const float* xr = x + (size_t)row * Dmod;
    float4 xv = ((const float4*)xr)[t];
    float s  = xv.x + xv.y + xv.z + xv.w;
    float q2 = xv.x * xv.x + xv.y * xv.y + xv.z * xv.z + xv.w * xv.w;
    #pragma unroll
    for (int o = 16; o; o >>= 1) {
        s  += __shfl_xor_sync(0xffffffffu, s,  o);
        q2 += __shfl_xor_sync(0xffffffffu, q2, o);
    }
    if ((t & 31) == 0) { red[0][t >> 5] = s; red[1][t >> 5] = q2; }
    __syncthreads();
    s  = red[0][0] + red[0][1] + red[0][2] + red[0][3];
    q2 = red[1][0] + red[1][1] + red[1][2] + red[1][3];
    const float mu   = s * (1.0f / Dmod);
    const float var  = q2 * (1.0f / Dmod) - mu * mu;
    const float rstd = rsqrtf(var + 1e-6f);
    float4 gv = ((const float4*)g)[t];
    float4 bv = ((const float4*)bta)[t];
    __half2 h0 = __floats2half2_rn((xv.x - mu) * rstd * gv.x + bv.x,
                                   (xv.y - mu) * rstd * gv.y + bv.y);
    __half2 h1 = __floats2half2_rn((xv.z - mu) * rstd * gv.z + bv.z,
                                   (xv.w - mu) * rstd * gv.w + bv.w);
    __half2* yo = (__half2*)(y + (size_t)row * Dmod + t * 4);
    yo[0] = h0; yo[1] = h1;
}

// ---------------- FP16 TC GEMM: A[m][k], Bt[n][k]; m16n8k16; 3-stage cp.async ----------------
#define GH_LD      40                          // halves per row (80B, odd 16B mult)
#define GH_STAGE_B (128 * GH_LD * 2)           // 10240 bytes per operand stage
#define GEMM_SMEM  (6 * GH_STAGE_B)            // 61440 B

__device__ __forceinline__ void hgemm_prefetch(uint32_t sA, uint32_t sB,
                                               const __half* __restrict__ A,
                                               const __half* __restrict__ Bt,
                                               int bm, int bn, int K,
                                               int tid, int t, int stage) {
    #pragma unroll
    for (int i = 0; i < 2; i++) {
        int cc = tid + 256 * i;
        int row = cc >> 2, ch = (cc & 3) * 8;
        const uint32_t so = (uint32_t)(stage * GH_STAGE_B + (row * GH_LD + ch) * 2);
        cpasync16(sA + so, A  + (size_t)(bm + row) * K + t * 32 + ch);
        cpasync16(sB + so, Bt + (size_t)(bn + row) * K + t * 32 + ch);
    }
    asm volatile("cp.async.commit_group;" ::: "memory");
}

// EPI: 0 = qkv->half (alpha on cols<512) ; 1 = gelu(acc+bias)->half ;
//      2 = acc+res->float ; 3 = acc+bias+res->float
template <int EPI>
__global__ void __launch_bounds__(256, 2)
hgemm_tc(const __half* __restrict__ A, const __half* __restrict__ Bt,
         void* __restrict__ Cv, int N, int K, float alpha,
         const float* __restrict__ bias, const float* __restrict__ res) {
    extern __shared__ char smc[];
    const int tid  = threadIdx.x;
    const int bm   = blockIdx.y * 128;
    const int bn   = blockIdx.x * 128;
    const int lane = tid & 31;
    const int wid  = tid >> 5;
    const int wm   = wid & 1;
    const int wn   = wid >> 1;
    const int lr   = lane >> 2;
    const int lc   = lane & 3;
    const int fRow = (lane & 7) + ((lane >> 3) & 1) * 8;  // ldmatrix row-in-16
    const int fCg  = (lane >> 4) * 8;                     // ldmatrix col group

    uint32_t sbase = (uint32_t)__cvta_generic_to_shared(smc);
    uint32_t sA = sbase;
    uint32_t sB = sbase + 3 * GH_STAGE_B;

    float acc[4][4][4];
    #pragma unroll
    for (int mt = 0; mt < 4; mt++)
        #pragma unroll
        for (int nt = 0; nt < 4; nt++)
            #pragma unroll
            for (int r = 0; r < 4; r++) acc[mt][nt][r] = 0.0f;

    const int nk = K >> 5;

    hgemm_prefetch(sA, sB, A, Bt, bm, bn, K, tid, 0, 0);
    hgemm_prefetch(sA, sB, A, Bt, bm, bn, K, tid, 1, 1);

    int cs = 0, ps = 2;
    for (int t = 0; t < nk; t++) {
        if (t + 1 < nk) {
            asm volatile("cp.async.wait_group 1;" ::: "memory");
        } else {
            asm volatile("cp.async.wait_group 0;" ::: "memory");
        }
        __syncthreads();

        if (t + 2 < nk)
            hgemm_prefetch(sA, sB, A, Bt, bm, bn, K, tid, t + 2, ps);

        const uint32_t sAc = sA + (uint32_t)(cs * GH_STAGE_B);
        const uint32_t sBc = sB + (uint32_t)(cs * GH_STAGE_B);

        #pragma unroll
        for (int kst = 0; kst < 2; kst++) {
            const int k0 = kst * 16;
            uint32_t af[4][4], bf[2][4];
            #pragma unroll
            for (int mt = 0; mt < 4; mt++)
                ldsm4(af[mt], sAc + (uint32_t)(((wm * 64 + mt * 16 + fRow) * GH_LD + k0 + fCg) * 2));
            #pragma unroll
            for (int np = 0; np < 2; np++)
                ldsm4(bf[np], sBc + (uint32_t)(((wn * 32 + np * 16 + fRow) * GH_LD + k0 + fCg) * 2));
            #pragma unroll
            for (int mt = 0; mt < 4; mt++) {
                mma_f16(acc[mt][0], af[mt], bf[0][0], bf[0][2]);
                mma_f16(acc[mt][1], af[mt], bf[0][1], bf[0][3]);
                mma_f16(acc[mt][2], af[mt], bf[1][0], bf[1][2]);
                mma_f16(acc[mt][3], af[mt], bf[1][1], bf[1][3]);
            }
        }

        cs = (cs == 2) ? 0 : cs + 1;
        ps = (ps == 2) ? 0 : ps + 1;
    }

    const float a_eff = (EPI == 0) ? ((bn < 512) ? alpha : 1.0f) : alpha;
    __half* Ch = (__half*)Cv;
    float*  Cf = (float*)Cv;

    #pragma unroll
    for (int mt = 0; mt < 4; mt++) {
        const int row0 = bm + wm * 64 + mt * 16 + lr;
        #pragma unroll
        for (int half_ = 0; half_ < 2; half_++) {
            const int row = row0 + half_ * 8;
            #pragma unroll
            for (int nt = 0; nt < 4; nt++) {
                const int col = bn + wn * 32 + nt * 8 + lc * 2;
                float v0 = acc[mt][nt][half_ * 2 + 0];
                float v1 = acc[mt][nt][half_ * 2 + 1];
                const size_t off = (size_t)row * N + col;
                if (EPI == 0) {
                    *(__half2*)&Ch[off] = __floats2half2_rn(v0 * a_eff, v1 * a_eff);
                } else if (EPI == 1) {
                    *(__half2*)&Ch[off] = __floats2half2_rn(gelu_tanh(v0 + bias[col]),
                                                            gelu_tanh(v1 + bias[col + 1]));
                } else if (EPI == 2) {
                    *(float2*)&Cf[off] = make_float2(v0 + res[off], v1 + res[off + 1]);
                } else {
                    *(float2*)&Cf[off] = make_float2(v0 + bias[col] + res[off],
                                                     v1 + bias[col + 1] + res[off + 1]);
                }
            }
        }
    }
}

// ---------------- fp16 flash BigBird attention ----------------
// smem (halves): K [2][32][72], V [2][32][72], P [64][40]
#define AKLD 72
#define APLD 40
#define A_KOFF 0
#define A_VOFF (2 * 32 * AKLD)                  // 4608 halves
#define A_POFF (A_VOFF + 2 * 32 * AKLD)         // 9216 halves
#define ATT_SMEM ((A_POFF + 64 * APLD) * 2)     // 23552 B

__device__ __forceinline__ void att_load_sub(uint32_t sbase, int tid, int stage,
                                             const __half* kb_g, const __half* vb_g) {
    #pragma unroll
    for (int i = 0; i < 2; i++) {
        int cc = tid + 128 * i;
        int row = cc >> 3, ch = (cc & 7) * 8;
        cpasync16(sbase + (uint32_t)((A_KOFF + stage * 32 * AKLD + row * AKLD + ch) * 2),
                  kb_g + (size_t)row * QKV_LD + ch);
        cpasync16(sbase + (uint32_t)((A_VOFF + stage * 32 * AKLD + row * AKLD + ch) * 2),
                  vb_g + (size_t)row * QKV_LD + ch);
    }
    asm volatile("cp.async.commit_group;" ::: "memory");
}

__global__ void __launch_bounds__(128)
attn_tc(const __half* __restrict__ qkv, __half* __restrict__ o,
        float* __restrict__ po, float* __restrict__ pm, float* __restrict__ pl,
        const int* __restrict__ idxTab, const int* __restrict__ cntTab) {
    extern __shared__ char smc[];
    __half* smh = (__half*)smc;
    const int bx = blockIdx.x, h = blockIdx.y, b = blockIdx.z;
    const int tid = threadIdx.x;
    const int lane = tid & 31, w = tid >> 5;
    const int lr = lane >> 2, lc = lane & 3;
    const int fRow = (lane & 7) + ((lane >> 3) & 1) * 8;
    const int fCg  = (lane >> 4) * 8;

    const bool isg = (bx < 16);
    int n, split = 0, nsub;
    if (isg) { split = bx & 7; n = (bx >> 3) ? (NBb - 1) : 0; nsub = 16; }
    else     { n = bx - 15; nsub = 2 * cntTab[n - 1]; }

    uint32_t sbase = (uint32_t)__cvta_generic_to_shared(smc);

    // ---- Q tile -> smem (K region) -> A fragments (4 ksteps of 16) ----
    const __half* qbase = qkv + (size_t)(b * Sseq + n * BSb) * QKV_LD + h * DHd;
    #pragma unroll
    for (int i = 0; i < 4; i++) {
        int cc = tid + 128 * i;
        int row = cc >> 3, ch = (cc & 7) * 8;
        *(uint4*)&smh[row * AKLD + ch] = *(const uint4*)&qbase[(size_t)row * QKV_LD + ch];
    }
    __syncthreads();
    uint32_t aq[4][4];
    #pragma unroll
    for (int kt = 0; kt < 4; kt++)
        ldsm4(aq[kt], sbase + (uint32_t)(((w * 16 + fRow) * AKLD + kt * 16 + fCg) * 2));
    __syncthreads();

    float accO[8][4];
    #pragma unroll
    for (int nt = 0; nt < 8; nt++)
        #pragma unroll
        for (int r = 0; r < 4; r++) accO[nt][r] = 0.0f;
    float m0 = -1e30f, m1 = -1e30f, l0 = 0.0f, l1 = 0.0f;

    {
        const int blk = isg ? split * 8 : idxTab[(n - 1) * 8];
        const __half* base = qkv + (size_t)(b * Sseq + blk * BSb) * QKV_LD + h * DHd;
        att_load_sub(sbase, tid, 0, base + 512, base + 1024);
    }

    for (int it = 0; it < nsub; it++) {
        const int st = it & 1;
        if (it + 1 < nsub) {
            const int i2 = it + 1;
            const int blk = isg ? (split * 8 + (i2 >> 1)) : idxTab[(n - 1) * 8 + (i2 >> 1)];
            const __half* base = qkv + (size_t)(b * Sseq + blk * BSb + (i2 & 1) * 32) * QKV_LD + h * DHd;
            att_load_sub(sbase, tid, st ^ 1, base + 512, base + 1024);
            asm volatile("cp.async.wait_group 1;" ::: "memory");
        } else {
            asm volatile("cp.async.wait_group 0;" ::: "memory");
        }
        __syncthreads();

        // ---- S = Q K^T (16 q x 32 j per warp); B frags from Ks[j][d] rows ----
        float s[4][4];
        #pragma unroll
        for (int nt = 0; nt < 4; nt++)
            #pragma unroll
            for (int r = 0; r < 4; r++) s[nt][r] = 0.0f;

        const uint32_t kB = sbase + (uint32_t)((A_KOFF + st * 32 * AKLD) * 2);
        #pragma unroll
        for (int kt = 0; kt < 4; kt++) {
            const int k0 = kt * 16;
            uint32_t bf[2][4];
            #pragma unroll
            for (int jp = 0; jp < 2; jp++)
                ldsm4(bf[jp], kB + (uint32_t)(((jp * 16 + fRow) * AKLD + k0 + fCg) * 2));
            mma_f16(s[0], aq[kt], bf[0][0], bf[0][2]);
            mma_f16(s[1], aq[kt], bf[0][1], bf[0][3]);
            mma_f16(s[2], aq[kt], bf[1][0], bf[1][2]);
            mma_f16(s[3], aq[kt], bf[1][1], bf[1][3]);
        }

        // ---- streaming softmax (rows lr / lr+8) ----
        float mx0 = fmaxf(fmaxf(s[0][0], s[0][1]), fmaxf(s[1][0], s[1][1]));
        float mx1 = fmaxf(fmaxf(s[0][2], s[0][3]), fmaxf(s[1][2], s[1][3]));
        mx0 = fmaxf(mx0, fmaxf(fmaxf(s[2][0], s[2][1]), fmaxf(s[3][0], s[3][1])));
        mx1 = fmaxf(mx1, fmaxf(fmaxf(s[2][2], s[2][3]), fmaxf(s[3][2], s[3][3])));
        mx0 = fmaxf(mx0, __shfl_xor_sync(0xffffffffu, mx0, 1));
        mx0 = fmaxf(mx0, __shfl_xor_sync(0xffffffffu, mx0, 2));
        mx1 = fmaxf(mx1, __shfl_xor_sync(0xffffffffu, mx1, 1));
        mx1 = fmaxf(mx1, __shfl_xor_sync(0xffffffffu, mx1, 2));
        const float mn0 = fmaxf(m0, mx0), mn1 = fmaxf(m1, mx1);
        const float cor0 = __expf(m0 - mn0), cor1 = __expf(m1 - mn1);
        float ps0 = 0.0f, ps1 = 0.0f;
        #pragma unroll
        for (int nt = 0; nt < 4; nt++) {
            s[nt][0] = __expf(s[nt][0] - mn0);
            s[nt][1] = __expf(s[nt][1] - mn0);
            s[nt][2] = __expf(s[nt][2] - mn1);
            s[nt][3] = __expf(s[nt][3] - mn1);
            ps0 += s[nt][0] + s[nt][1];
            ps1 += s[nt][2] + s[nt][3];
        }
        ps0 += __shfl_xor_sync(0xffffffffu, ps0, 1);
        ps0 += __shfl_xor_sync(0xffffffffu, ps0, 2);
        ps1 += __shfl_xor_sync(0xffffffffu, ps1, 1);
        ps1 += __shfl_xor_sync(0xffffffffu, ps1, 2);
        l0 = l0 * cor0 + ps0;
        l1 = l1 * cor1 + ps1;
        m0 = mn0; m1 = mn1;
        #pragma unroll
        for (int nt = 0; nt < 8; nt++) {
            accO[nt][0] *= cor0; accO[nt][1] *= cor0;
            accO[nt][2] *= cor1; accO[nt][3] *= cor1;
        }

        // ---- P -> per-warp smem as fp16 ----
        __half* pw = smh + A_POFF + (w * 16 + lr) * APLD;
        #pragma unroll
        for (int nt = 0; nt < 4; nt++) {
            *(__half2*)&pw[nt * 8 + 2 * lc]            = __floats2half2_rn(s[nt][0], s[nt][1]);
            *(__half2*)&pw[8 * APLD + nt * 8 + 2 * lc] = __floats2half2_rn(s[nt][2], s[nt][3]);
        }
        __syncwarp();

        // ---- O += P V: A=P via ldsm4, B=V via ldsm4.trans ----
        const uint32_t pB = sbase + (uint32_t)((A_POFF + w * 16 * APLD) * 2);
        const uint32_t vB = sbase + (uint32_t)((A_VOFF + st * 32 * AKLD) * 2);
        #pragma unroll
        for (int kst = 0; kst < 2; kst++) {
            const int k0 = kst * 16;   // j offset
            uint32_t ap[4];
            ldsm4(ap, pB + (uint32_t)((fRow * APLD + k0 + fCg) * 2));
            #pragma unroll
            for (int dg = 0; dg < 4; dg++) {
                uint32_t bv[4];
                ldsm4t(bv, vB + (uint32_t)(((k0 + fRow) * AKLD + dg * 16 + fCg) * 2));
                mma_f16(accO[2 * dg],     ap, bv[0], bv[1]);
                mma_f16(accO[2 * dg + 1], ap, bv[2], bv[3]);
            }
        }
        __syncthreads();
    }

    if (!isg) {
        const float inv0 = 1.0f / l0, inv1 = 1.0f / l1;
        __half* ob = o + (size_t)(b * Sseq + n * BSb + w * 16 + lr) * Dmod + h * DHd;
        #pragma unroll
        for (int nt = 0; nt < 8; nt++) {
            *(__half2*)&ob[nt * 8 + 2 * lc] =
                __floats2half2_rn(accO[nt][0] * inv0, accO[nt][1] * inv0);
            *(__half2*)&ob[(size_t)8 * Dmod + nt * 8 + 2 * lc] =
                __floats2half2_rn(accO[nt][2] * inv1, accO[nt][3] * inv1);
        }
    } else {
        const int g = n ? 1 : 0;
        const int pslot = ((b * 2 + g) * Hh + h) * 8 + split;
        if (lc == 0) {
            pm[pslot * 64 + w * 16 + lr]     = m0;
            pl[pslot * 64 + w * 16 + lr]     = l0;
            pm[pslot * 64 + w * 16 + 8 + lr] = m1;
            pl[pslot * 64 + w * 16 + 8 + lr] = l1;
        }
        float* pb = po + ((size_t)pslot * 64 + w * 16 + lr) * 64;
        #pragma unroll
        for (int nt = 0; nt < 8; nt++) {
            *(float2*)&pb[nt * 8 + 2 * lc]          = make_float2(accO[nt][0], accO[nt][1]);
            *(float2*)&pb[8 * 64 + nt * 8 + 2 * lc] = make_float2(accO[nt][2], accO[nt][3]);
        }
    }
}

// ---------------- combine global-split partials (fp32 in, fp16 out) ----------------
__global__ void __launch_bounds__(256)
combine_kernel(const float* __restrict__ po, const float* __restrict__ pm,
               const float* __restrict__ pl, __half* __restrict__ o) {
    const int group = blockIdx.x;
    const int b = group >> 4, g = (group >> 3) & 1, h = group & 7;
    const int row = threadIdx.x >> 2;
    const int cseg = (threadIdx.x & 3) * 16;

    float mv[8], lv[8];
    float M = -1e30f;
    #pragma unroll
    for (int s = 0; s < 8; s++) {
        mv[s] = pm[(group * 8 + s) * 64 + row];
        lv[s] = pl[(group * 8 + s) * 64 + row];
        M = fmaxf(M, mv[s]);
    }
    float L = 0.0f, wgt[8];
    #pragma unroll
    for (int s = 0; s < 8; s++) {
        wgt[s] = __expf(mv[s] - M);
        L += lv[s] * wgt[s];
    }
    float acc[16];
    #pragma unroll
    for (int c = 0; c < 16; c++) acc[c] = 0.0f;
    #pragma unroll
    for (int s = 0; s < 8; s++) {
        const float* pr = po + ((size_t)(group * 8 + s) * 64 + row) * 64 + cseg;
        #pragma unroll
        for (int c4 = 0; c4 < 4; c4++) {
            float4 vv = *(const float4*)&pr[c4 * 4];
            acc[c4 * 4 + 0] += wgt[s] * vv.x;
            acc[c4 * 4 + 1] += wgt[s] * vv.y;
            acc[c4 * 4 + 2] += wgt[s] * vv.z;
            acc[c4 * 4 + 3] += wgt[s] * vv.w;
        }
    }
    const float inv = 1.0f / L;
    const int nblk = g ? (NBb - 1) : 0;
    __half* ob = o + (size_t)(b * Sseq + nblk * BSb + row) * Dmod + h * DHd + cseg;
    #pragma unroll
    for (int c4 = 0; c4 < 4; c4++) {
        *(__half2*)&ob[c4 * 4]     = __floats2half2_rn(acc[c4 * 4 + 0] * inv, acc[c4 * 4 + 1] * inv);
        *(__half2*)&ob[c4 * 4 + 2] = __floats2half2_rn(acc[c4 * 4 + 2] * inv, acc[c4 * 4 + 3] * inv);
    }
}

// ---------------- launcher ----------------
extern "C" void kernel_launch(void* const* d_in, const int* in_sizes, int n_in,
                              void* d_out, int out_size) {
    const float* inputs = (const float*)d_in[0];
    const float* ln1_s  = (const float*)d_in[1];
    const float* ln1_b  = (const float*)d_in[2];
    const float* wq     = (const float*)d_in[3];
    const float* wk     = (const float*)d_in[4];
    const float* wv     = (const float*)d_in[5];
    const float* wo     = (const float*)d_in[6];
    const float* ln2_s  = (const float*)d_in[7];
    const float* ln2_b  = (const float*)d_in[8];
    const float* w1     = (const float*)d_in[9];
    const float* b1     = (const float*)d_in[10];
    const float* w2     = (const float*)d_in[11];
    const float* b2     = (const float*)d_in[12];
    float* out = (float*)d_out;

    __half *xn, *qkv, *o, *yn, *hb, *wqkv, *wor, *w1r, *w2r;
    float *po, *pmv, *plv;
    int *idx, *cnt;
    cudaGetSymbolAddress((void**)&xn,   g_xn);
    cudaGetSymbolAddress((void**)&qkv,  g_qkv);
    cudaGetSymbolAddress((void**)&o,    g_o);
    cudaGetSymbolAddress((void**)&yn,   g_yn);
    cudaGetSymbolAddress((void**)&hb,   g_hb);
    cudaGetSymbolAddress((void**)&wqkv, g_wqkv);
    cudaGetSymbolAddress((void**)&wor,  g_wor);
    cudaGetSymbolAddress((void**)&w1r,  g_w1r);
    cudaGetSymbolAddress((void**)&w2r,  g_w2r);
    cudaGetSymbolAddress((void**)&po,   g_po);
    cudaGetSymbolAddress((void**)&pmv,  g_pm);
    cudaGetSymbolAddress((void**)&plv,  g_pl);
    cudaGetSymbolAddress((void**)&idx,  g_idx);
    cudaGetSymbolAddress((void**)&cnt,  g_cnt);

    cudaFuncSetAttribute(hgemm_tc<0>, cudaFuncAttributeMaxDynamicSharedMemorySize, GEMM_SMEM);
    cudaFuncSetAttribute(hgemm_tc<1>, cudaFuncAttributeMaxDynamicSharedMemorySize, GEMM_SMEM);
    cudaFuncSetAttribute(hgemm_tc<2>, cudaFuncAttributeMaxDynamicSharedMemorySize, GEMM_SMEM);
    cudaFuncSetAttribute(hgemm_tc<3>, cudaFuncAttributeMaxDynamicSharedMemorySize, GEMM_SMEM);

    // 0. BigBird index table (host, input-independent)
    static int h_idx[NROWS * 8];
    static int h_cnt[NROWS];
    h_make_table(h_idx, h_cnt);
    cudaMemcpyAsync(idx, h_idx, sizeof(h_idx), cudaMemcpyHostToDevice, 0);
    cudaMemcpyAsync(cnt, h_cnt, sizeof(h_cnt), cudaMemcpyHostToDevice, 0);

    // 1. transpose + fp16-convert all weights (one launch)
    transpose_cvt_all<<<3072, 256>>>(wq, wk, wv, wo, w1, w2, wqkv, wor, w1r, w2r);

    // 2. LN1 -> fp16
    ln_kernel<<<NTOK, 128>>>(inputs, ln1_s, ln1_b, xn);

    // 3. QKV: single fp16 GEMM, N=1536; alpha=0.125 on q columns
    dim3 gqkv(QKV_LD / 128, NTOK / 128);
    hgemm_tc<0><<<gqkv, 256, GEMM_SMEM>>>(xn, wqkv, qkv, QKV_LD, Dmod, 0.125f, nullptr, nullptr);

    // 4. attention (fp16 mma) + combine
    attn_tc<<<dim3(78, Hh, Bsz), 128, ATT_SMEM>>>(qkv, o, po, pmv, plv, idx, cnt);
    combine_kernel<<<64, 256>>>(po, pmv, plv, o);

    // 5. WO + residual (fp32 out)
    dim3 g512(Dmod / 128, NTOK / 128);
    hgemm_tc<2><<<g512, 256, GEMM_SMEM>>>(o, wor, out, Dmod, Dmod, 1.0f, nullptr, inputs);

    // 6. LN2 -> fp16
    ln_kernel<<<NTOK, 128>>>(out, ln2_s, ln2_b, yn);

    // 7. FFN1: gelu(yn @ w1 + b1) -> fp16
    dim3 g2048(Mff / 128, NTOK / 128);
    hgemm_tc<1><<<g2048, 256, GEMM_SMEM>>>(yn, w1r, hb, Mff, Dmod, 1.0f, b1, nullptr);

    // 8. FFN2 + bias + residual (fp32 out)
    hgemm_tc<3><<<g512, 256, GEMM_SMEM>>>(hb, w2r, out, Dmod, Mff, 1.0f, b2, out);
}

// round 8
// speedup vs baseline: 12.0243x; 1.0058x over previous
#include <cuda_runtime.h>
#include <cuda_fp16.h>
#include <math.h>
#include <stdint.h>

// ---------------- problem constants ----------------
#define Bsz   4
#define Sseq  4096
#define Dmod  512
#define Hh    8
#define DHd   64
#define Mff   2048
#define BSb   64
#define NBb   64
#define NROWS (NBb - 2)
#define NTOK  (Bsz * Sseq)        // 16384
#define QKV_LD 1536

// ---------------- scratch (device globals; no allocation) ----------------
__device__ __half g_xn  [(size_t)NTOK * Dmod];
__device__ __half g_qkv [(size_t)NTOK * QKV_LD];
__device__ __half g_o   [(size_t)NTOK * Dmod];
__device__ __half g_yn  [(size_t)NTOK * Dmod];
__device__ __half g_hb  [(size_t)NTOK * Mff];
__device__ __half g_wqkv[(size_t)QKV_LD * Dmod];
__device__ __half g_wor [(size_t)Dmod * Dmod];
__device__ __half g_w1r [(size_t)Mff * Dmod];
__device__ __half g_w2r [(size_t)Dmod * Mff];
__device__ float  g_po  [(size_t)512 * 64 * 64];
__device__ float  g_pm  [512 * 64];
__device__ float  g_pl  [512 * 64];
__device__ int    g_idx[NROWS * 8];
__device__ int    g_cnt[NROWS];

// ---------------- host-side numpy-legacy MT19937 ----------------
struct HostMT { unsigned int k[624]; int pos; };
static void h_mt_seed(HostMT& st, unsigned int seed) {
    for (int p = 0; p < 624; p++) {
        st.k[p] = seed;
        seed = 1812433253u * (seed ^ (seed >> 30)) + (unsigned)p + 1u;
    }
    st.pos = 624;
}
static unsigned int h_mt_next(HostMT& st) {
    if (st.pos == 624) {
        for (int i = 0; i < 624; i++) {
            unsigned int y = (st.k[i] & 0x80000000u) | (st.k[(i + 1) % 624] & 0x7fffffffu);
            st.k[i] = st.k[(i + 397) % 624] ^ (y >> 1) ^ ((y & 1u) ? 0x9908b0dfu : 0u);
        }
        st.pos = 0;
    }
    unsigned int y = st.k[st.pos++];
    y ^= y >> 11;
    y ^= (y << 7)  & 0x9d2c5680u;
    y ^= (y << 15) & 0xefc60000u;
    y ^= y >> 18;
    return y;
}
static unsigned int h_mt_interval(HostMT& st, unsigned int mx) {
    if (mx == 0u) return 0u;
    unsigned int mask = mx;
    mask |= mask >> 1; mask |= mask >> 2; mask |= mask >> 4;
    mask |= mask >> 8; mask |= mask >> 16;
    unsigned int v;
    do { v = h_mt_next(st) & mask; } while (v > mx);
    return v;
}
static void h_make_table(int* h_idx, int* h_cnt) {
    HostMT st;
    h_mt_seed(st, 0u);
    for (int i = 1; i <= NBb - 2; i++) {
        bool fx[NBb];
        for (int z = 0; z < NBb; z++) fx[z] = false;
        fx[0] = true; fx[NBb - 1] = true;
        fx[i - 1] = true; fx[i] = true; fx[i + 1] = true;
        int fixed[8], nf = 0;
        int allowed[NBb], na = 0;
        for (int bb = 0; bb < NBb; bb++) {
            if (fx[bb]) fixed[nf++] = bb;
            else        allowed[na++] = bb;
        }
        int perm[NBb];
        for (int t = 0; t < na; t++) perm[t] = t;
        for (int t = na - 1; t >= 1; t--) {
            int j = (int)h_mt_interval(st, (unsigned)t);
            int tmp = perm[t]; perm[t] = perm[j]; perm[j] = tmp;
        }
        int row = i - 1;
        int cnt = 0;
        for (int s = 0; s < nf; s++) h_idx[row * 8 + cnt++] = fixed[s];
        for (int r3 = 0; r3 < 3; r3++) h_idx[row * 8 + cnt++] = allowed[perm[r3]];
        h_cnt[row] = cnt;
        for (; cnt < 8; cnt++) h_idx[row * 8 + cnt] = 0;
    }
}

// ---------------- helpers ----------------
__device__ __forceinline__ float gelu_tanh(float x) {
    const float c = 0.7978845608028654f;
    float x3 = x * x * x;
    return 0.5f * x * (1.0f + tanhf(c * (x + 0.044715f * x3)));
}
__device__ __forceinline__ void cpasync16(uint32_t saddr, const void* gaddr) {
    asm volatile("cp.async.cg.shared.global [%0], [%1], 16;" :: "r"(saddr), "l"(gaddr) : "memory");
}
__device__ __forceinline__ void mma_f16(float* c, const uint32_t* a, uint32_t b0, uint32_t b1) {
    asm volatile(
        "mma.sync.aligned.m16n8k16.row.col.f32.f16.f16.f32 "
        "{%0,%1,%2,%3}, {%4,%5,%6,%7}, {%8,%9}, {%0,%1,%2,%3};"
        : "+f"(c[0]), "+f"(c[1]), "+f"(c[2]), "+f"(c[3])
        : "r"(a[0]), "r"(a[1]), "r"(a[2]), "r"(a[3]), "r"(b0), "r"(b1));
}
__device__ __forceinline__ void ldsm4(uint32_t* r, uint32_t saddr) {
    asm volatile("ldmatrix.sync.aligned.m8n8.x4.shared.b16 {%0,%1,%2,%3}, [%4];"
                 : "=r"(r[0]), "=r"(r[1]), "=r"(r[2]), "=r"(r[3]) : "r"(saddr));
}
__device__ __forceinline__ void ldsm4t(uint32_t* r, uint32_t saddr) {
    asm volatile("ldmatrix.sync.aligned.m8n8.x4.trans.shared.b16 {%0,%1,%2,%3}, [%4];"
                 : "=r"(r[0]), "=r"(r[1]), "=r"(r[2]), "=r"(r[3]) : "r"(saddr));
}

// ---------------- merged transpose + fp16 convert of all 6 weight matrices ----------------
__global__ void __launch_bounds__(256)
transpose_cvt_all(const float* __restrict__ wq, const float* __restrict__ wk,
                  const float* __restrict__ wv, const float* __restrict__ wo,
                  const float* __restrict__ w1, const float* __restrict__ w2,
                  __half* __restrict__ dqkv, __half* __restrict__ dwo,
                  __half* __restrict__ dw1, __half* __restrict__ dw2) {
    __shared__ float t[32][33];
    const int bid = blockIdx.x;
    const float* src;
    __half* dst;
    int R, C, ti;
    if (bid < 1024) {
        const int m = bid >> 8;
        ti = bid & 255;
        R = 512; C = 512;
        if (m == 0)      { src = wq; dst = dqkv; }
        else if (m == 1) { src = wk; dst = dqkv + 512 * 512; }
        else if (m == 2) { src = wv; dst = dqkv + 1024 * 512; }
        else             { src = wo; dst = dwo; }
    } else if (bid < 2048) {
        ti = bid - 1024; R = 512; C = 2048; src = w1; dst = dw1;
    } else {
        ti = bid - 2048; R = 2048; C = 512; src = w2; dst = dw2;
    }
    const int Ct = C >> 5;
    const int r0 = (ti / Ct) * 32, c0 = (ti % Ct) * 32;
    const int tx = threadIdx.x & 31, ty = threadIdx.x >> 5;
    #pragma unroll
    for (int j = 0; j < 4; j++)
        t[ty + j * 8][tx] = src[(size_t)(r0 + ty + j * 8) * C + c0 + tx];
    __syncthreads();
    #pragma unroll
    for (int j = 0; j < 4; j++)
        dst[(size_t)(c0 + ty + j * 8) * R + r0 + tx] = __float2half_rn(t[tx][ty + j * 8]);
}

// ---------------- LayerNorm (fp32 in, fp16 out) ----------------
__global__ void ln_kernel(const float* __restrict__ x, const float* __restrict__ g,
                          const float* __restrict__ bta, __half* __restrict__ y) {
    __shared__ float red[2][4];
    const int row = blockIdx.x;
    const int t = threadIdx.x;
    const float* xr = x + (size_t)row * Dmod;
    float4 xv = ((const float4*)xr)[t];
    float s  = xv.x + xv.y + xv.z + xv.w;
    float q2 = xv.x * xv.x + xv.y * xv.y + xv.z * xv.z + xv.w * xv.w;
    #pragma unroll
    for (int o = 16; o; o >>= 1) {
        s  += __shfl_xor_sync(0xffffffffu, s,  o);
        q2 += __shfl_xor_sync(0xffffffffu, q2, o);
    }
    if ((t & 31) == 0) { red[0][t >> 5] = s; red[1][t >> 5] = q2; }
    __syncthreads();
    s  = red[0][0] + red[0][1] + red[0][2] + red[0][3];
    q2 = red[1][0] + red[1][1] + red[1][2] + red[1][3];
    const float mu   = s * (1.0f / Dmod);
    const float var  = q2 * (1.0f / Dmod) - mu * mu;
    const float rstd = rsqrtf(var + 1e-6f);
    float4 gv = ((const float4*)g)[t];
    float4 bv = ((const float4*)bta)[t];
    __half2 h0 = __floats2half2_rn((xv.x - mu) * rstd * gv.x + bv.x,
                                   (xv.y - mu) * rstd * gv.y + bv.y);
    __half2 h1 = __floats2half2_rn((xv.z - mu) * rstd * gv.z + bv.z,
                                   (xv.w - mu) * rstd * gv.w + bv.w);
    __half2* yo = (__half2*)(y + (size_t)row * Dmod + t * 4);
    yo[0] = h0; yo[1] = h1;
}

// ---------------- FP16 TC GEMM: 128x128 tile, 4 warps, warp tile 64x64 ----------------
#define GH_LD      40
#define GH_STAGE_B (128 * GH_LD * 2)           // 10240 B per operand stage
#define GEMM_SMEM  (6 * GH_STAGE_B)            // 61440 B (3 stages x A,B)

__device__ __forceinline__ void hgemm_prefetch(uint32_t sA, uint32_t sB,
                                               const __half* __restrict__ A,
                                               const __half* __restrict__ Bt,
                                               int bm, int bn, int K,
                                               int tid, int t, int stage) {
    #pragma unroll
    for (int i = 0; i < 4; i++) {
        int cc = tid + 128 * i;
        int row = cc >> 2, ch = (cc & 3) * 8;
        const uint32_t so = (uint32_t)(stage * GH_STAGE_B + (row * GH_LD + ch) * 2);
        cpasync16(sA + so, A  + (size_t)(bm + row) * K + t * 32 + ch);
        cpasync16(sB + so, Bt + (size_t)(bn + row) * K + t * 32 + ch);
    }
    asm volatile("cp.async.commit_group;" ::: "memory");
}

// EPI: 0 = qkv->half (alpha on cols<512) ; 1 = gelu(acc+bias)->half ;
//      2 = acc+res->float ; 3 = acc+bias+res->float
template <int EPI>
__global__ void __launch_bounds__(128, 2)
hgemm_tc(const __half* __restrict__ A, const __half* __restrict__ Bt,
         void* __restrict__ Cv, int N, int K, float alpha,
         const float* __restrict__ bias, const float* __restrict__ res) {
    extern __shared__ char smc[];
    const int tid  = threadIdx.x;
    const int bm   = blockIdx.y * 128;
    const int bn   = blockIdx.x * 128;
    const int lane = tid & 31;
    const int wid  = tid >> 5;          // 0..3
    const int wm   = wid & 1;           // 64-row half
    const int wn   = wid >> 1;          // 64-col half
    const int lr   = lane >> 2;
    const int lc   = lane & 3;
    const int fRow = (lane & 7) + ((lane >> 3) & 1) * 8;
    const int fCg  = (lane >> 4) * 8;

    uint32_t sbase = (uint32_t)__cvta_generic_to_shared(smc);
    uint32_t sA = sbase;
    uint32_t sB = sbase + 3 * GH_STAGE_B;

    float acc[4][8][4];
    #pragma unroll
    for (int mt = 0; mt < 4; mt++)
        #pragma unroll
        for (int nt = 0; nt < 8; nt++)
            #pragma unroll
            for (int r = 0; r < 4; r++) acc[mt][nt][r] = 0.0f;

    const int nk = K >> 5;

    hgemm_prefetch(sA, sB, A, Bt, bm, bn, K, tid, 0, 0);
    hgemm_prefetch(sA, sB, A, Bt, bm, bn, K, tid, 1, 1);

    int cs = 0, ps = 2;
    for (int t = 0; t < nk; t++) {
        if (t + 1 < nk) {
            asm volatile("cp.async.wait_group 1;" ::: "memory");
        } else {
            asm volatile("cp.async.wait_group 0;" ::: "memory");
        }
        __syncthreads();

        if (t + 2 < nk)
            hgemm_prefetch(sA, sB, A, Bt, bm, bn, K, tid, t + 2, ps);

        const uint32_t sAc = sA + (uint32_t)(cs * GH_STAGE_B);
        const uint32_t sBc = sB + (uint32_t)(cs * GH_STAGE_B);

        #pragma unroll
        for (int kst = 0; kst < 2; kst++) {
            const int k0 = kst * 16;
            uint32_t af[4][4], bf[4][4];
            #pragma unroll
            for (int mt = 0; mt < 4; mt++)
                ldsm4(af[mt], sAc + (uint32_t)(((wm * 64 + mt * 16 + fRow) * GH_LD + k0 + fCg) * 2));
            #pragma unroll
            for (int np = 0; np < 4; np++)
                ldsm4(bf[np], sBc + (uint32_t)(((wn * 64 + np * 16 + fRow) * GH_LD + k0 + fCg) * 2));
            #pragma unroll
            for (int mt = 0; mt < 4; mt++)
                #pragma unroll
                for (int np = 0; np < 4; np++) {
                    mma_f16(acc[mt][2 * np],     af[mt], bf[np][0], bf[np][2]);
                    mma_f16(acc[mt][2 * np + 1], af[mt], bf[np][1], bf[np][3]);
                }
        }

        cs = (cs == 2) ? 0 : cs + 1;
        ps = (ps == 2) ? 0 : ps + 1;
    }

    const float a_eff = (EPI == 0) ? ((bn < 512) ? alpha : 1.0f) : alpha;
    __half* Ch = (__half*)Cv;
    float*  Cf = (float*)Cv;

    #pragma unroll
    for (int mt = 0; mt < 4; mt++) {
        #pragma unroll
        for (int half_ = 0; half_ < 2; half_++) {
            const int row = bm + wm * 64 + mt * 16 + half_ * 8 + lr;
            #pragma unroll
            for (int nt = 0; nt < 8; nt++) {
                const int col = bn + wn * 64 + nt * 8 + lc * 2;
                float v0 = acc[mt][nt][half_ * 2 + 0];
                float v1 = acc[mt][nt][half_ * 2 + 1];
                const size_t off = (size_t)row * N + col;
                if (EPI == 0) {
                    *(__half2*)&Ch[off] = __floats2half2_rn(v0 * a_eff, v1 * a_eff);
                } else if (EPI == 1) {
                    *(__half2*)&Ch[off] = __floats2half2_rn(gelu_tanh(v0 + bias[col]),
                                                            gelu_tanh(v1 + bias[col + 1]));
                } else if (EPI == 2) {
                    *(float2*)&Cf[off] = make_float2(v0 + res[off], v1 + res[off + 1]);
                } else {
                    *(float2*)&Cf[off] = make_float2(v0 + bias[col] + res[off],
                                                     v1 + bias[col + 1] + res[off + 1]);
                }
            }
        }
    }
}

// ---------------- fp16 flash BigBird attention: 64-key subtiles ----------------
// smem (halves): K [2][64][72], V [2][64][72], P [64][72]
#define AKLD 72
#define APLD 72
#define A_KOFF 0
#define A_VOFF (2 * 64 * AKLD)                  // 9216 halves
#define A_POFF (A_VOFF + 2 * 64 * AKLD)         // 18432 halves
#define ATT_SMEM ((A_POFF + 64 * APLD) * 2)     // 46080 B

__device__ __forceinline__ void att_load_sub(uint32_t sbase, int tid, int stage,
                                             const __half* kb_g, const __half* vb_g) {
    #pragma unroll
    for (int i = 0; i < 4; i++) {
        int cc = tid + 128 * i;
        int row = cc >> 3, ch = (cc & 7) * 8;
        cpasync16(sbase + (uint32_t)((A_KOFF + stage * 64 * AKLD + row * AKLD + ch) * 2),
                  kb_g + (size_t)row * QKV_LD + ch);
        cpasync16(sbase + (uint32_t)((A_VOFF + stage * 64 * AKLD + row * AKLD + ch) * 2),
                  vb_g + (size_t)row * QKV_LD + ch);
    }
    asm volatile("cp.async.commit_group;" ::: "memory");
}

__global__ void __launch_bounds__(128)
attn_tc(const __half* __restrict__ qkv, __half* __restrict__ o,
        float* __restrict__ po, float* __restrict__ pm, float* __restrict__ pl,
        const int* __restrict__ idxTab, const int* __restrict__ cntTab) {
    extern __shared__ char smc[];
    __half* smh = (__half*)smc;
    const int bx = blockIdx.x, h = blockIdx.y, b = blockIdx.z;
    const int tid = threadIdx.x;
    const int lane = tid & 31, w = tid >> 5;
    const int lr = lane >> 2, lc = lane & 3;
    const int fRow = (lane & 7) + ((lane >> 3) & 1) * 8;
    const int fCg  = (lane >> 4) * 8;

    const bool isg = (bx < 16);
    int n, split = 0, nsub;
    if (isg) { split = bx & 7; n = (bx >> 3) ? (NBb - 1) : 0; nsub = 8; }
    else     { n = bx - 15; nsub = cntTab[n - 1]; }

    uint32_t sbase = (uint32_t)__cvta_generic_to_shared(smc);

    // ---- Q tile -> smem (K region) -> A fragments ----
    const __half* qbase = qkv + (size_t)(b * Sseq + n * BSb) * QKV_LD + h * DHd;
    #pragma unroll
    for (int i = 0; i < 4; i++) {
        int cc = tid + 128 * i;
        int row = cc >> 3, ch = (cc & 7) * 8;
        *(uint4*)&smh[row * AKLD + ch] = *(const uint4*)&qbase[(size_t)row * QKV_LD + ch];
    }
    __syncthreads();
    uint32_t aq[4][4];
    #pragma unroll
    for (int kt = 0; kt < 4; kt++)
        ldsm4(aq[kt], sbase + (uint32_t)(((w * 16 + fRow) * AKLD + kt * 16 + fCg) * 2));
    __syncthreads();

    float accO[8][4];
    #pragma unroll
    for (int nt = 0; nt < 8; nt++)
        #pragma unroll
        for (int r = 0; r < 4; r++) accO[nt][r] = 0.0f;
    float m0 = -1e30f, m1 = -1e30f, l0 = 0.0f, l1 = 0.0f;

    {
        const int blk = isg ? split * 8 : idxTab[(n - 1) * 8];
        const __half* base = qkv + (size_t)(b * Sseq + blk * BSb) * QKV_LD + h * DHd;
        att_load_sub(sbase, tid, 0, base + 512, base + 1024);
    }

    for (int it = 0; it < nsub; it++) {
        const int st = it & 1;
        if (it + 1 < nsub) {
            const int blk = isg ? (split * 8 + it + 1) : idxTab[(n - 1) * 8 + it + 1];
            const __half* base = qkv + (size_t)(b * Sseq + blk * BSb) * QKV_LD + h * DHd;
            att_load_sub(sbase, tid, st ^ 1, base + 512, base + 1024);
            asm volatile("cp.async.wait_group 1;" ::: "memory");
        } else {
            asm volatile("cp.async.wait_group 0;" ::: "memory");
        }
        __syncthreads();

        // ---- S = Q K^T (16 q x 64 j per warp) ----
        float s[8][4];
        #pragma unroll
        for (int nt = 0; nt < 8; nt++)
            #pragma unroll
            for (int r = 0; r < 4; r++) s[nt][r] = 0.0f;

        const uint32_t kB = sbase + (uint32_t)((A_KOFF + st * 64 * AKLD) * 2);
        #pragma unroll
        for (int kt = 0; kt < 4; kt++) {
            const int k0 = kt * 16;
            uint32_t bf[4][4];
            #pragma unroll
            for (int jp = 0; jp < 4; jp++)
                ldsm4(bf[jp], kB + (uint32_t)(((jp * 16 + fRow) * AKLD + k0 + fCg) * 2));
            #pragma unroll
            for (int jp = 0; jp < 4; jp++) {
                mma_f16(s[2 * jp],     aq[kt], bf[jp][0], bf[jp][2]);
                mma_f16(s[2 * jp + 1], aq[kt], bf[jp][1], bf[jp][3]);
            }
        }

        // ---- streaming softmax (rows lr / lr+8) ----
        float mx0 = -1e30f, mx1 = -1e30f;
        #pragma unroll
        for (int nt = 0; nt < 8; nt++) {
            mx0 = fmaxf(mx0, fmaxf(s[nt][0], s[nt][1]));
            mx1 = fmaxf(mx1, fmaxf(s[nt][2], s[nt][3]));
        }
        mx0 = fmaxf(mx0, __shfl_xor_sync(0xffffffffu, mx0, 1));
        mx0 = fmaxf(mx0, __shfl_xor_sync(0xffffffffu, mx0, 2));
        mx1 = fmaxf(mx1, __shfl_xor_sync(0xffffffffu, mx1, 1));
        mx1 = fmaxf(mx1, __shfl_xor_sync(0xffffffffu, mx1, 2));
        const float mn0 = fmaxf(m0, mx0), mn1 = fmaxf(m1, mx1);
        const float cor0 = __expf(m0 - mn0), cor1 = __expf(m1 - mn1);
        float ps0 = 0.0f, ps1 = 0.0f;
        #pragma unroll
        for (int nt = 0; nt < 8; nt++) {
            s[nt][0] = __expf(s[nt][0] - mn0);
            s[nt][1] = __expf(s[nt][1] - mn0);
            s[nt][2] = __expf(s[nt][2] - mn1);
            s[nt][3] = __expf(s[nt][3] - mn1);
            ps0 += s[nt][0] + s[nt][1];
            ps1 += s[nt][2] + s[nt][3];
        }
        ps0 += __shfl_xor_sync(0xffffffffu, ps0, 1);
        ps0 += __shfl_xor_sync(0xffffffffu, ps0, 2);
        ps1 += __shfl_xor_sync(0xffffffffu, ps1, 1);
        ps1 += __shfl_xor_sync(0xffffffffu, ps1, 2);
        l0 = l0 * cor0 + ps0;
        l1 = l1 * cor1 + ps1;
        m0 = mn0; m1 = mn1;
        #pragma unroll
        for (int nt = 0; nt < 8; nt++) {
            accO[nt][0] *= cor0; accO[nt][1] *= cor0;
            accO[nt][2] *= cor1; accO[nt][3] *= cor1;
        }

        // ---- P -> per-warp smem as fp16 ----
        __half* pw = smh + A_POFF + (w * 16 + lr) * APLD;
        #pragma unroll
        for (int nt = 0; nt < 8; nt++) {
            *(__half2*)&pw[nt * 8 + 2 * lc]            = __floats2half2_rn(s[nt][0], s[nt][1]);
            *(__half2*)&pw[8 * APLD + nt * 8 + 2 * lc] = __floats2half2_rn(s[nt][2], s[nt][3]);
        }
        __syncwarp();

        // ---- O += P V: A=P via ldsm4, B=V via ldsm4.trans ----
        const uint32_t pB = sbase + (uint32_t)((A_POFF + w * 16 * APLD) * 2);
        const uint32_t vB = sbase + (uint32_t)((A_VOFF + st * 64 * AKLD) * 2);
        #pragma unroll
        for (int kst = 0; kst < 4; kst++) {
            const int k0 = kst * 16;   // j offset
            uint32_t ap[4];
            ldsm4(ap, pB + (uint32_t)((fRow * APLD + k0 + fCg) * 2));
            #pragma unroll
            for (int dg = 0; dg < 4; dg++) {
                uint32_t bv[4];
                ldsm4t(bv, vB + (uint32_t)(((k0 + fRow) * AKLD + dg * 16 + fCg) * 2));
                mma_f16(accO[2 * dg],     ap, bv[0], bv[1]);
                mma_f16(accO[2 * dg + 1], ap, bv[2], bv[3]);
            }
        }
        __syncthreads();
    }

    if (!isg) {
        const float inv0 = 1.0f / l0, inv1 = 1.0f / l1;
        __half* ob = o + (size_t)(b * Sseq + n * BSb + w * 16 + lr) * Dmod + h * DHd;
        #pragma unroll
        for (int nt = 0; nt < 8; nt++) {
            *(__half2*)&ob[nt * 8 + 2 * lc] =
                __floats2half2_rn(accO[nt][0] * inv0, accO[nt][1] * inv0);
            *(__half2*)&ob[(size_t)8 * Dmod + nt * 8 + 2 * lc] =
                __floats2half2_rn(accO[nt][2] * inv1, accO[nt][3] * inv1);
        }
    } else {
        const int g = n ? 1 : 0;
        const int pslot = ((b * 2 + g) * Hh + h) * 8 + split;
        if (lc == 0) {
            pm[pslot * 64 + w * 16 + lr]     = m0;
            pl[pslot * 64 + w * 16 + lr]     = l0;
            pm[pslot * 64 + w * 16 + 8 + lr] = m1;
            pl[pslot * 64 + w * 16 + 8 + lr] = l1;
        }
        float* pb = po + ((size_t)pslot * 64 + w * 16 + lr) * 64;
        #pragma unroll
        for (int nt = 0; nt < 8; nt++) {
            *(float2*)&pb[nt * 8 + 2 * lc]          = make_float2(accO[nt][0], accO[nt][1]);
            *(float2*)&pb[8 * 64 + nt * 8 + 2 * lc] = make_float2(accO[nt][2], accO[nt][3]);
        }
    }
}

// ---------------- combine global-split partials ----------------
__global__ void __launch_bounds__(256)
combine_kernel(const float* __restrict__ po, const float* __restrict__ pm,
               const float* __restrict__ pl, __half* __restrict__ o) {
    const int group = blockIdx.x;
    const int b = group >> 4, g = (group >> 3) & 1, h = group & 7;
    const int row = threadIdx.x >> 2;
    const int cseg = (threadIdx.x & 3) * 16;

    float mv[8], lv[8];
    float M = -1e30f;
    #pragma unroll
    for (int s = 0; s < 8; s++) {
        mv[s] = pm[(group * 8 + s) * 64 + row];
        lv[s] = pl[(group * 8 + s) * 64 + row];
        M = fmaxf(M, mv[s]);
    }
    float L = 0.0f, wgt[8];
    #pragma unroll
    for (int s = 0; s < 8; s++) {
        wgt[s] = __expf(mv[s] - M);
        L += lv[s] * wgt[s];
    }
    float acc[16];
    #pragma unroll
    for (int c = 0; c < 16; c++) acc[c] = 0.0f;
    #pragma unroll
    for (int s = 0; s < 8; s++) {
        const float* pr = po + ((size_t)(group * 8 + s) * 64 + row) * 64 + cseg;
        #pragma unroll
        for (int c4 = 0; c4 < 4; c4++) {
            float4 vv = *(const float4*)&pr[c4 * 4];
            acc[c4 * 4 + 0] += wgt[s] * vv.x;
            acc[c4 * 4 + 1] += wgt[s] * vv.y;
            acc[c4 * 4 + 2] += wgt[s] * vv.z;
            acc[c4 * 4 + 3] += wgt[s] * vv.w;
        }
    }
    const float inv = 1.0f / L;
    const int nblk = g ? (NBb - 1) : 0;
    __half* ob = o + (size_t)(b * Sseq + nblk * BSb + row) * Dmod + h * DHd + cseg;
    #pragma unroll
    for (int c4 = 0; c4 < 4; c4++) {
        *(__half2*)&ob[c4 * 4]     = __floats2half2_rn(acc[c4 * 4 + 0] * inv, acc[c4 * 4 + 1] * inv);
        *(__half2*)&ob[c4 * 4 + 2] = __floats2half2_rn(acc[c4 * 4 + 2] * inv, acc[c4 * 4 + 3] * inv);
    }
}

// ---------------- launcher ----------------
extern "C" void kernel_launch(void* const* d_in, const int* in_sizes, int n_in,
                              void* d_out, int out_size) {
    const float* inputs = (const float*)d_in[0];
    const float* ln1_s  = (const float*)d_in[1];
    const float* ln1_b  = (const float*)d_in[2];
    const float* wq     = (const float*)d_in[3];
    const float* wk     = (const float*)d_in[4];
    const float* wv     = (const float*)d_in[5];
    const float* wo     = (const float*)d_in[6];
    const float* ln2_s  = (const float*)d_in[7];
    const float* ln2_b  = (const float*)d_in[8];
    const float* w1     = (const float*)d_in[9];
    const float* b1     = (const float*)d_in[10];
    const float* w2     = (const float*)d_in[11];
    const float* b2     = (const float*)d_in[12];
    float* out = (float*)d_out;

    __half *xn, *qkv, *o, *yn, *hb, *wqkv, *wor, *w1r, *w2r;
    float *po, *pmv, *plv;
    int *idx, *cnt;
    cudaGetSymbolAddress((void**)&xn,   g_xn);
    cudaGetSymbolAddress((void**)&qkv,  g_qkv);
    cudaGetSymbolAddress((void**)&o,    g_o);
    cudaGetSymbolAddress((void**)&yn,   g_yn);
    cudaGetSymbolAddress((void**)&hb,   g_hb);
    cudaGetSymbolAddress((void**)&wqkv, g_wqkv);
    cudaGetSymbolAddress((void**)&wor,  g_wor);
    cudaGetSymbolAddress((void**)&w1r,  g_w1r);
    cudaGetSymbolAddress((void**)&w2r,  g_w2r);
    cudaGetSymbolAddress((void**)&po,   g_po);
    cudaGetSymbolAddress((void**)&pmv,  g_pm);
    cudaGetSymbolAddress((void**)&plv,  g_pl);
    cudaGetSymbolAddress((void**)&idx,  g_idx);
    cudaGetSymbolAddress((void**)&cnt,  g_cnt);

    cudaFuncSetAttribute(hgemm_tc<0>, cudaFuncAttributeMaxDynamicSharedMemorySize, GEMM_SMEM);
    cudaFuncSetAttribute(hgemm_tc<1>, cudaFuncAttributeMaxDynamicSharedMemorySize, GEMM_SMEM);
    cudaFuncSetAttribute(hgemm_tc<2>, cudaFuncAttributeMaxDynamicSharedMemorySize, GEMM_SMEM);
    cudaFuncSetAttribute(hgemm_tc<3>, cudaFuncAttributeMaxDynamicSharedMemorySize, GEMM_SMEM);
    cudaFuncSetAttribute(attn_tc, cudaFuncAttributeMaxDynamicSharedMemorySize, ATT_SMEM);

    // 0. BigBird index table (host, input-independent)
    static int h_idx[NROWS * 8];
    static int h_cnt[NROWS];
    h_make_table(h_idx, h_cnt);
    cudaMemcpyAsync(idx, h_idx, sizeof(h_idx), cudaMemcpyHostToDevice, 0);
    cudaMemcpyAsync(cnt, h_cnt, sizeof(h_cnt), cudaMemcpyHostToDevice, 0);

    // 1. transpose + fp16-convert all weights (one launch)
    transpose_cvt_all<<<3072, 256>>>(wq, wk, wv, wo, w1, w2, wqkv, wor, w1r, w2r);

    // 2. LN1 -> fp16
    ln_kernel<<<NTOK, 128>>>(inputs, ln1_s, ln1_b, xn);

    // 3. QKV: single fp16 GEMM, N=1536; alpha=0.125 on q columns
    dim3 gqkv(QKV_LD / 128, NTOK / 128);
    hgemm_tc<0><<<gqkv, 128, GEMM_SMEM>>>(xn, wqkv, qkv, QKV_LD, Dmod, 0.125f, nullptr, nullptr);

    // 4. attention (64-key subtiles) + combine
    attn_tc<<<dim3(78, Hh, Bsz), 128, ATT_SMEM>>>(qkv, o, po, pmv, plv, idx, cnt);
    combine_kernel<<<64, 256>>>(po, pmv, plv, o);

    // 5. WO + residual (fp32 out)
    dim3 g512(Dmod / 128, NTOK / 128);
    hgemm_tc<2><<<g512, 128, GEMM_SMEM>>>(o, wor, out, Dmod, Dmod, 1.0f, nullptr, inputs);

    // 6. LN2 -> fp16
    ln_kernel<<<NTOK, 128>>>(out, ln2_s, ln2_b, yn);

    // 7. FFN1: gelu(yn @ w1 + b1) -> fp16
    dim3 g2048(Mff / 128, NTOK / 128);
    hgemm_tc<1><<<g2048, 128, GEMM_SMEM>>>(yn, w1r, hb, Mff, Dmod, 1.0f, b1, nullptr);

    // 8. FFN2 + bias + residual (fp32 out)
    hgemm_tc<3><<<g512, 128, GEMM_SMEM>>>(hb, w2r, out, Dmod, Mff, 1.0f, b2, out);
}